// round 1
// baseline (speedup 1.0000x reference)
#include <cuda_runtime.h>
#include <math.h>

// Problem constants
#define BB 4
#define SS 2048
#define DD 1024
#define HH 16
#define DK 64
#define MM (BB * SS)   // 8192 rows

// Scratch (static device globals: allocation-free per harness rules)
__device__ float g_q[MM * DD];
__device__ float g_k[MM * DD];
__device__ float g_v[MM * DD];
__device__ float g_ctx[MM * DD];

// ---------------------------------------------------------------------------
// SGEMM (NT): C[m,n] = sum_k A[m,k] * W[n,k] + bias[n]
// BM=BN=128, BK=16, 256 threads, 8x8 per-thread micro-tile.
// ---------------------------------------------------------------------------
__global__ __launch_bounds__(256) void sgemm_nt_bias(
    const float* __restrict__ A, const float* __restrict__ W,
    const float* __restrict__ bias, float* __restrict__ C,
    int M, int N, int K)
{
    const int BM = 128, BN = 128, BK = 16;
    __shared__ float As[BK][BM + 4];   // [k][m]
    __shared__ float Bs[BK][BN + 4];   // [k][n]

    int tid = threadIdx.x;
    int ty = tid >> 4;        // 0..15  (M direction)
    int tx = tid & 15;        // 0..15  (N direction)
    int m0 = blockIdx.y * BM;
    int n0 = blockIdx.x * BN;

    float acc[8][8];
    #pragma unroll
    for (int i = 0; i < 8; i++)
        #pragma unroll
        for (int j = 0; j < 8; j++) acc[i][j] = 0.f;

    for (int k0 = 0; k0 < K; k0 += BK) {
        // Stage tiles (transposed into [k][row]) : 512 float4 per matrix
        #pragma unroll
        for (int r = 0; r < 2; r++) {
            int idx = tid + r * 256;          // 0..511
            int row = idx >> 2;               // 0..127
            int c4  = (idx & 3) << 2;         // 0,4,8,12
            float4 av = *reinterpret_cast<const float4*>(
                &A[(size_t)(m0 + row) * K + k0 + c4]);
            As[c4 + 0][row] = av.x; As[c4 + 1][row] = av.y;
            As[c4 + 2][row] = av.z; As[c4 + 3][row] = av.w;
            float4 bv = *reinterpret_cast<const float4*>(
                &W[(size_t)(n0 + row) * K + k0 + c4]);
            Bs[c4 + 0][row] = bv.x; Bs[c4 + 1][row] = bv.y;
            Bs[c4 + 2][row] = bv.z; Bs[c4 + 3][row] = bv.w;
        }
        __syncthreads();

        #pragma unroll
        for (int kk = 0; kk < BK; kk++) {
            float a[8], b[8];
            *reinterpret_cast<float4*>(&a[0]) =
                *reinterpret_cast<float4*>(&As[kk][ty * 8]);
            *reinterpret_cast<float4*>(&a[4]) =
                *reinterpret_cast<float4*>(&As[kk][ty * 8 + 4]);
            *reinterpret_cast<float4*>(&b[0]) =
                *reinterpret_cast<float4*>(&Bs[kk][tx * 8]);
            *reinterpret_cast<float4*>(&b[4]) =
                *reinterpret_cast<float4*>(&Bs[kk][tx * 8 + 4]);
            #pragma unroll
            for (int i = 0; i < 8; i++)
                #pragma unroll
                for (int j = 0; j < 8; j++)
                    acc[i][j] += a[i] * b[j];
        }
        __syncthreads();
    }

    // Epilogue: add bias, store
    float bia[8];
    #pragma unroll
    for (int j = 0; j < 8; j++) bia[j] = bias[n0 + tx * 8 + j];

    #pragma unroll
    for (int i = 0; i < 8; i++) {
        size_t row = (size_t)(m0 + ty * 8 + i);
        float* crow = &C[row * N + n0 + tx * 8];
        float4 r0, r1;
        r0.x = acc[i][0] + bia[0]; r0.y = acc[i][1] + bia[1];
        r0.z = acc[i][2] + bia[2]; r0.w = acc[i][3] + bia[3];
        r1.x = acc[i][4] + bia[4]; r1.y = acc[i][5] + bia[5];
        r1.z = acc[i][6] + bia[6]; r1.w = acc[i][7] + bia[7];
        *reinterpret_cast<float4*>(&crow[0]) = r0;
        *reinterpret_cast<float4*>(&crow[4]) = r1;
    }
}

// ---------------------------------------------------------------------------
// Flash attention (fp32 SIMT). One block = 64 query rows of one (b,h).
// BM=BN=DK=64, 256 threads, 4x4 micro-tiles, online softmax.
// ---------------------------------------------------------------------------
__global__ __launch_bounds__(256) void flash_attn_kernel(
    const float* __restrict__ Q, const float* __restrict__ Kg,
    const float* __restrict__ Vg, float* __restrict__ Octx)
{
    const int ST = 68;                 // padded row stride (floats)
    extern __shared__ float sm[];
    float* QsT = sm;                   // [d][i]  64 x ST
    float* KsT = QsT + 64 * ST;        // [d][j]
    float* Vs  = KsT + 64 * ST;        // [j][d]
    float* PsT = Vs  + 64 * ST;        // [j][i]

    int tid = threadIdx.x;
    int ty = tid >> 4;                 // row group  (i = ty*4 + ii)
    int tx = tid & 15;                 // col group  (j/d = tx*4 + xx)
    int q0 = blockIdx.x * 64;
    int h  = blockIdx.y;
    int b  = blockIdx.z;

    const size_t base = (size_t)b * SS * DD + (size_t)h * DK;  // + s*DD + d

    // Load Q tile (scaled by 1/sqrt(DK) = 0.125)
    #pragma unroll
    for (int r = 0; r < 4; r++) {
        int idx = tid + r * 256;       // 0..1023 (float4 index)
        int row = idx >> 4;            // 0..63
        int d4  = (idx & 15) << 2;     // 0..60
        float4 v = *reinterpret_cast<const float4*>(
            &Q[base + (size_t)(q0 + row) * DD + d4]);
        QsT[(d4 + 0) * ST + row] = v.x * 0.125f;
        QsT[(d4 + 1) * ST + row] = v.y * 0.125f;
        QsT[(d4 + 2) * ST + row] = v.z * 0.125f;
        QsT[(d4 + 3) * ST + row] = v.w * 0.125f;
    }

    const float NEG_INF = __int_as_float(0xff800000);
    float m[4], l[4], o[4][4];
    #pragma unroll
    for (int ii = 0; ii < 4; ii++) {
        m[ii] = NEG_INF; l[ii] = 0.f;
        #pragma unroll
        for (int dd = 0; dd < 4; dd++) o[ii][dd] = 0.f;
    }

    for (int t = 0; t < SS / 64; t++) {
        __syncthreads();   // protect K/V/P smem from previous iteration's readers
        int k0 = t * 64;
        #pragma unroll
        for (int r = 0; r < 4; r++) {
            int idx = tid + r * 256;
            int row = idx >> 4;
            int d4  = (idx & 15) << 2;
            float4 kv = *reinterpret_cast<const float4*>(
                &Kg[base + (size_t)(k0 + row) * DD + d4]);
            KsT[(d4 + 0) * ST + row] = kv.x;
            KsT[(d4 + 1) * ST + row] = kv.y;
            KsT[(d4 + 2) * ST + row] = kv.z;
            KsT[(d4 + 3) * ST + row] = kv.w;
            float4 vv = *reinterpret_cast<const float4*>(
                &Vg[base + (size_t)(k0 + row) * DD + d4]);
            *reinterpret_cast<float4*>(&Vs[row * ST + d4]) = vv;
        }
        __syncthreads();

        // S = Q K^T  (64-deep)
        float s[4][4];
        #pragma unroll
        for (int ii = 0; ii < 4; ii++)
            #pragma unroll
            for (int jj = 0; jj < 4; jj++) s[ii][jj] = 0.f;

        #pragma unroll
        for (int d = 0; d < 64; d++) {
            float4 qv = *reinterpret_cast<float4*>(&QsT[d * ST + ty * 4]);
            float4 kv = *reinterpret_cast<float4*>(&KsT[d * ST + tx * 4]);
            float qa[4] = {qv.x, qv.y, qv.z, qv.w};
            float ka[4] = {kv.x, kv.y, kv.z, kv.w};
            #pragma unroll
            for (int ii = 0; ii < 4; ii++)
                #pragma unroll
                for (int jj = 0; jj < 4; jj++)
                    s[ii][jj] += qa[ii] * ka[jj];
        }

        // Online softmax update (16-lane reductions; a row's 16 threads are
        // contiguous lanes within one warp half)
        #pragma unroll
        for (int ii = 0; ii < 4; ii++) {
            float tmax = fmaxf(fmaxf(s[ii][0], s[ii][1]),
                               fmaxf(s[ii][2], s[ii][3]));
            #pragma unroll
            for (int off = 8; off >= 1; off >>= 1)
                tmax = fmaxf(tmax, __shfl_xor_sync(0xffffffffu, tmax, off));
            float mn = fmaxf(m[ii], tmax);
            float scale = __expf(m[ii] - mn);
            float rsum = 0.f;
            #pragma unroll
            for (int jj = 0; jj < 4; jj++) {
                s[ii][jj] = __expf(s[ii][jj] - mn);
                rsum += s[ii][jj];
            }
            #pragma unroll
            for (int off = 8; off >= 1; off >>= 1)
                rsum += __shfl_xor_sync(0xffffffffu, rsum, off);
            l[ii] = l[ii] * scale + rsum;
            m[ii] = mn;
            #pragma unroll
            for (int dd = 0; dd < 4; dd++) o[ii][dd] *= scale;
            #pragma unroll
            for (int jj = 0; jj < 4; jj++)
                PsT[(tx * 4 + jj) * ST + ty * 4 + ii] = s[ii][jj];
        }
        __syncthreads();

        // O += P V  (64-deep over j)
        #pragma unroll
        for (int j = 0; j < 64; j++) {
            float4 pv = *reinterpret_cast<float4*>(&PsT[j * ST + ty * 4]);
            float4 vv = *reinterpret_cast<float4*>(&Vs[j * ST + tx * 4]);
            float pa[4] = {pv.x, pv.y, pv.z, pv.w};
            float va[4] = {vv.x, vv.y, vv.z, vv.w};
            #pragma unroll
            for (int ii = 0; ii < 4; ii++)
                #pragma unroll
                for (int dd = 0; dd < 4; dd++)
                    o[ii][dd] += pa[ii] * va[dd];
        }
    }

    // Epilogue: normalize, write ctx
    #pragma unroll
    for (int ii = 0; ii < 4; ii++) {
        float inv = 1.f / l[ii];
        size_t row = (size_t)(q0 + ty * 4 + ii);
        float4 r;
        r.x = o[ii][0] * inv; r.y = o[ii][1] * inv;
        r.z = o[ii][2] * inv; r.w = o[ii][3] * inv;
        *reinterpret_cast<float4*>(&Octx[base + row * DD + tx * 4]) = r;
    }
}

// ---------------------------------------------------------------------------
// Launch
// ---------------------------------------------------------------------------
extern "C" void kernel_launch(void* const* d_in, const int* in_sizes, int n_in,
                              void* d_out, int out_size)
{
    const float* x  = (const float*)d_in[0];
    const float* Wq = (const float*)d_in[1];
    const float* bq = (const float*)d_in[2];
    const float* Wk = (const float*)d_in[3];
    const float* bk = (const float*)d_in[4];
    const float* Wv = (const float*)d_in[5];
    const float* bv = (const float*)d_in[6];
    const float* Wo = (const float*)d_in[7];
    const float* bo = (const float*)d_in[8];
    float* out = (float*)d_out;

    float *q, *k, *v, *ctx;
    cudaGetSymbolAddress((void**)&q,   g_q);
    cudaGetSymbolAddress((void**)&k,   g_k);
    cudaGetSymbolAddress((void**)&v,   g_v);
    cudaGetSymbolAddress((void**)&ctx, g_ctx);

    const int smem_attn = 4 * 64 * 68 * (int)sizeof(float);  // 69632 B
    cudaFuncSetAttribute(flash_attn_kernel,
                         cudaFuncAttributeMaxDynamicSharedMemorySize, smem_attn);

    dim3 gemm_grid(DD / 128, MM / 128);   // (8, 64)

    sgemm_nt_bias<<<gemm_grid, 256>>>(x, Wq, bq, q, MM, DD, DD);
    sgemm_nt_bias<<<gemm_grid, 256>>>(x, Wk, bk, k, MM, DD, DD);
    sgemm_nt_bias<<<gemm_grid, 256>>>(x, Wv, bv, v, MM, DD, DD);

    dim3 attn_grid(SS / 64, HH, BB);      // (32, 16, 4)
    flash_attn_kernel<<<attn_grid, 256, smem_attn>>>(q, k, v, ctx);

    sgemm_nt_bias<<<gemm_grid, 256>>>(ctx, Wo, bo, out, MM, DD, DD);
}

// round 3
// speedup vs baseline: 2.9396x; 2.9396x over previous
#include <cuda_runtime.h>
#include <cuda_bf16.h>
#include <math.h>
#include <stdint.h>

// Problem constants
#define BB 4
#define SS 2048
#define DD 1024
#define HH 16
#define DK 64
#define MM (BB * SS)   // 8192 rows

// ---------------------------------------------------------------------------
// Scratch (static device globals: allocation-free per harness rules)
// ---------------------------------------------------------------------------
__device__ __align__(16) __nv_bfloat16 g_xh[MM * DD];
__device__ __align__(16) __nv_bfloat16 g_xl[MM * DD];
__device__ __align__(16) __nv_bfloat16 g_qh[MM * DD];
__device__ __align__(16) __nv_bfloat16 g_ql[MM * DD];
__device__ __align__(16) __nv_bfloat16 g_kh[MM * DD];
__device__ __align__(16) __nv_bfloat16 g_kl[MM * DD];
__device__ __align__(16) __nv_bfloat16 g_vh[MM * DD];
__device__ __align__(16) __nv_bfloat16 g_vl[MM * DD];
__device__ __align__(16) __nv_bfloat16 g_ch[MM * DD];
__device__ __align__(16) __nv_bfloat16 g_cl[MM * DD];
__device__ __align__(16) __nv_bfloat16 g_wh[4 * DD * DD];
__device__ __align__(16) __nv_bfloat16 g_wl[4 * DD * DD];

// ---------------------------------------------------------------------------
// Low-level helpers (base ISA only: ldmatrix + mma.sync + cp.async)
// ---------------------------------------------------------------------------
__device__ __forceinline__ uint32_t smem_u32(const void* p) {
    uint32_t a;
    asm("{ .reg .u64 t; cvta.to.shared.u64 t, %1; cvt.u32.u64 %0, t; }"
        : "=r"(a) : "l"(p));
    return a;
}

__device__ __forceinline__ uint32_t sw128(uint32_t off) {
    return off ^ ((off >> 3) & 0x70);
}

__device__ __forceinline__ void cp16(uint32_t dst, const void* src) {
    asm volatile("cp.async.cg.shared.global [%0], [%1], 16;"
                 :: "r"(dst), "l"(src) : "memory");
}

__device__ __forceinline__ void ldsm_x4(uint32_t* r, uint32_t addr) {
    asm volatile("ldmatrix.sync.aligned.m8n8.x4.shared.b16 {%0,%1,%2,%3}, [%4];"
                 : "=r"(r[0]), "=r"(r[1]), "=r"(r[2]), "=r"(r[3]) : "r"(addr));
}

__device__ __forceinline__ void ldsm_x4t(uint32_t* r, uint32_t addr) {
    asm volatile("ldmatrix.sync.aligned.m8n8.x4.trans.shared.b16 {%0,%1,%2,%3}, [%4];"
                 : "=r"(r[0]), "=r"(r[1]), "=r"(r[2]), "=r"(r[3]) : "r"(addr));
}

__device__ __forceinline__ void mma16816(float* c, const uint32_t* a,
                                         const uint32_t* b) {
    asm volatile(
        "mma.sync.aligned.m16n8k16.row.col.f32.bf16.bf16.f32 "
        "{%0,%1,%2,%3}, {%4,%5,%6,%7}, {%8,%9}, {%0,%1,%2,%3};"
        : "+f"(c[0]), "+f"(c[1]), "+f"(c[2]), "+f"(c[3])
        : "r"(a[0]), "r"(a[1]), "r"(a[2]), "r"(a[3]), "r"(b[0]), "r"(b[1]));
}

// pack two floats into bf16x2 hi + bf16x2 lo (hi/lo split)
__device__ __forceinline__ void split2(float x, float y,
                                       uint32_t& hi, uint32_t& lo) {
    __nv_bfloat16 hx = __float2bfloat16(x);
    __nv_bfloat16 hy = __float2bfloat16(y);
    float rx = x - __bfloat162float(hx);
    float ry = y - __bfloat162float(hy);
    __nv_bfloat162 H = __halves2bfloat162(hx, hy);
    __nv_bfloat162 L = __halves2bfloat162(__float2bfloat16(rx),
                                          __float2bfloat16(ry));
    hi = *reinterpret_cast<uint32_t*>(&H);
    lo = *reinterpret_cast<uint32_t*>(&L);
}

// ---------------------------------------------------------------------------
// fp32 -> bf16 hi/lo split pass (x and the 4 weight matrices only)
// ---------------------------------------------------------------------------
__global__ __launch_bounds__(256) void split_hi_lo(
    const float* __restrict__ src,
    __nv_bfloat16* __restrict__ hi, __nv_bfloat16* __restrict__ lo, int n4)
{
    int i = blockIdx.x * 256 + threadIdx.x;
    if (i >= n4) return;
    float4 v = reinterpret_cast<const float4*>(src)[i];
    uint32_t h0, l0, h1, l1;
    split2(v.x, v.y, h0, l0);
    split2(v.z, v.w, h1, l1);
    reinterpret_cast<uint32_t*>(hi)[2 * i]     = h0;
    reinterpret_cast<uint32_t*>(hi)[2 * i + 1] = h1;
    reinterpret_cast<uint32_t*>(lo)[2 * i]     = l0;
    reinterpret_cast<uint32_t*>(lo)[2 * i + 1] = l1;
}

// ---------------------------------------------------------------------------
// bf16x3 GEMM (NT): C[m,n] = (Ah+Al)[m,:] . (Bh+Bl)[n,:] + bias[n]
// CTA 128x128, BK=64, 8 warps (2x4), warp tile 64x32, double-buffered cp.async.
// Output either fp32 (Cf) or bf16 hi/lo (Ch/Cl).
// ---------------------------------------------------------------------------
#define G_STAGE 65536   // Ah 16K | Al 16K | Bh 16K | Bl 16K
#define G_SMEM  (2 * G_STAGE)

__global__ __launch_bounds__(256, 1) void hgemm_bf16x3(
    const __nv_bfloat16* __restrict__ Ah, const __nv_bfloat16* __restrict__ Al,
    const __nv_bfloat16* __restrict__ Bh, const __nv_bfloat16* __restrict__ Bl,
    const float* __restrict__ bias,
    float* __restrict__ Cf,
    __nv_bfloat16* __restrict__ Ch, __nv_bfloat16* __restrict__ Cl)
{
    extern __shared__ __align__(1024) char smem[];
    uint32_t sb = smem_u32(smem);
    const int tid = threadIdx.x;
    const int w = tid >> 5, lane = tid & 31;
    const int wr = w >> 2, wc = w & 3;      // warp tile: m = wr*64, n = wc*32
    const int m0 = blockIdx.y * 128, n0 = blockIdx.x * 128;

    const char* gp[4] = {(const char*)Ah, (const char*)Al,
                         (const char*)Bh, (const char*)Bl};
    const int rb[4] = {m0, m0, n0, n0};

    float acc[4][4][4];
    #pragma unroll
    for (int mt = 0; mt < 4; mt++)
        #pragma unroll
        for (int nt = 0; nt < 4; nt++)
            #pragma unroll
            for (int i = 0; i < 4; i++) acc[mt][nt][i] = 0.f;

    auto load_stage = [&](int t, int s) {
        uint32_t base = sb + s * G_STAGE;
        #pragma unroll
        for (int mtx = 0; mtx < 4; mtx++) {
            const char* g = gp[mtx] + (size_t)rb[mtx] * 2048 + t * 128;
            uint32_t sm = base + mtx * 16384;
            #pragma unroll
            for (int i = 0; i < 4; i++) {
                int idx = tid + i * 256;       // 0..1023 (row*8 + chunk)
                int row = idx >> 3, c = idx & 7;
                cp16(sm + sw128((uint32_t)idx * 16),
                     g + (size_t)row * 2048 + c * 16);
            }
        }
        asm volatile("cp.async.commit_group;" ::: "memory");
    };

    load_stage(0, 0);

    for (int t = 0; t < DD / 64; t++) {
        if (t + 1 < DD / 64) {
            load_stage(t + 1, (t + 1) & 1);
            asm volatile("cp.async.wait_group 1;" ::: "memory");
        } else {
            asm volatile("cp.async.wait_group 0;" ::: "memory");
        }
        __syncthreads();
        uint32_t base = sb + (t & 1) * G_STAGE;

        #pragma unroll
        for (int k16 = 0; k16 < 4; k16++) {
            uint32_t af_h[4][4], af_l[4][4];
            #pragma unroll
            for (int mt = 0; mt < 4; mt++) {
                int row = wr * 64 + mt * 16 + (lane & 15);
                uint32_t off = sw128((uint32_t)row * 128 +
                                     (k16 * 2 + (lane >> 4)) * 16);
                ldsm_x4(af_h[mt], base + off);
                ldsm_x4(af_l[mt], base + 16384u + off);
            }
            uint32_t bf_h[4][2], bf_l[4][2];
            #pragma unroll
            for (int nh = 0; nh < 2; nh++) {
                int row = wc * 32 + nh * 16 + (lane & 15);
                uint32_t off = sw128((uint32_t)row * 128 +
                                     (k16 * 2 + (lane >> 4)) * 16);
                uint32_t r[4];
                ldsm_x4(r, base + 32768u + off);
                bf_h[nh * 2][0] = r[0]; bf_h[nh * 2 + 1][0] = r[1];
                bf_h[nh * 2][1] = r[2]; bf_h[nh * 2 + 1][1] = r[3];
                ldsm_x4(r, base + 49152u + off);
                bf_l[nh * 2][0] = r[0]; bf_l[nh * 2 + 1][0] = r[1];
                bf_l[nh * 2][1] = r[2]; bf_l[nh * 2 + 1][1] = r[3];
            }
            #pragma unroll
            for (int mt = 0; mt < 4; mt++)
                #pragma unroll
                for (int nt = 0; nt < 4; nt++) {
                    mma16816(acc[mt][nt], af_h[mt], bf_h[nt]);
                    mma16816(acc[mt][nt], af_h[mt], bf_l[nt]);
                    mma16816(acc[mt][nt], af_l[mt], bf_h[nt]);
                }
        }
        __syncthreads();
    }

    // Epilogue
    const int r = lane >> 2, cp2 = (lane & 3) * 2;
    #pragma unroll
    for (int mt = 0; mt < 4; mt++) {
        #pragma unroll
        for (int nt = 0; nt < 4; nt++) {
            int row = m0 + wr * 64 + mt * 16 + r;
            int col = n0 + wc * 32 + nt * 8 + cp2;
            float b0 = bias[col], b1 = bias[col + 1];
            float v00 = acc[mt][nt][0] + b0, v01 = acc[mt][nt][1] + b1;
            float v10 = acc[mt][nt][2] + b0, v11 = acc[mt][nt][3] + b1;
            if (Cf) {
                *reinterpret_cast<float2*>(Cf + (size_t)row * DD + col) =
                    make_float2(v00, v01);
                *reinterpret_cast<float2*>(Cf + (size_t)(row + 8) * DD + col) =
                    make_float2(v10, v11);
            } else {
                uint32_t h, l;
                split2(v00, v01, h, l);
                *reinterpret_cast<uint32_t*>(Ch + (size_t)row * DD + col) = h;
                *reinterpret_cast<uint32_t*>(Cl + (size_t)row * DD + col) = l;
                split2(v10, v11, h, l);
                *reinterpret_cast<uint32_t*>(Ch + (size_t)(row + 8) * DD + col) = h;
                *reinterpret_cast<uint32_t*>(Cl + (size_t)(row + 8) * DD + col) = l;
            }
        }
    }
}

// ---------------------------------------------------------------------------
// Flash attention on mma.sync bf16x3.
// Block: 256 threads (8 warps), BM=128 q rows (16/warp), BN=64 kv per iter,
// DK=64. Q fragments held in registers; P converted in-register to A-frags.
// Writes ctx as bf16 hi/lo.
// ---------------------------------------------------------------------------
#define A_STAGE 32768   // Kh 8K | Kl 8K | Vh 8K | Vl 8K
#define A_SMEM  (2 * A_STAGE)

__global__ __launch_bounds__(256, 1) void attn_mma(
    const __nv_bfloat16* __restrict__ Qh, const __nv_bfloat16* __restrict__ Ql,
    const __nv_bfloat16* __restrict__ Kh, const __nv_bfloat16* __restrict__ Kl,
    const __nv_bfloat16* __restrict__ Vh, const __nv_bfloat16* __restrict__ Vl,
    __nv_bfloat16* __restrict__ Ch, __nv_bfloat16* __restrict__ Cl)
{
    extern __shared__ __align__(1024) char smem[];
    uint32_t sb = smem_u32(smem);
    const int tid = threadIdx.x;
    const int w = tid >> 5, lane = tid & 31;
    const int q0 = blockIdx.x * 128;
    const int hd = blockIdx.y;
    const int b  = blockIdx.z;

    const size_t qbase = ((size_t)b * SS + q0) * DD + hd * 64;   // elements
    const size_t kbase = (size_t)b * SS * DD + hd * 64;

    // ---- Stage Q (128 x 64 bf16, hi+lo) into smem, load frags, release ----
    {
        const char* gq_h = (const char*)Qh + qbase * 2;
        const char* gq_l = (const char*)Ql + qbase * 2;
        #pragma unroll
        for (int i = 0; i < 4; i++) {
            int idx = tid + i * 256;          // 0..1023
            int row = idx >> 3, c = idx & 7;
            cp16(sb + sw128((uint32_t)idx * 16),
                 gq_h + (size_t)row * 2048 + c * 16);
            cp16(sb + 16384u + sw128((uint32_t)idx * 16),
                 gq_l + (size_t)row * 2048 + c * 16);
        }
        asm volatile("cp.async.commit_group;" ::: "memory");
        asm volatile("cp.async.wait_group 0;" ::: "memory");
        __syncthreads();
    }
    uint32_t qf_h[4][4], qf_l[4][4];
    #pragma unroll
    for (int k16 = 0; k16 < 4; k16++) {
        int row = w * 16 + (lane & 15);
        uint32_t off = sw128((uint32_t)row * 128 +
                             (k16 * 2 + (lane >> 4)) * 16);
        ldsm_x4(qf_h[k16], sb + off);
        ldsm_x4(qf_l[k16], sb + 16384u + off);
    }
    __syncthreads();   // Q smem now reusable for KV stages

    float o[8][4];
    #pragma unroll
    for (int dt = 0; dt < 8; dt++)
        #pragma unroll
        for (int i = 0; i < 4; i++) o[dt][i] = 0.f;
    const float NEG_INF = __int_as_float(0xff800000);
    float mrow[2] = {NEG_INF, NEG_INF};
    float lrow[2] = {0.f, 0.f};

    auto load_kv = [&](int it, int s) {
        uint32_t base = sb + s * A_STAGE;
        const char* g[4] = {
            (const char*)Kh + (kbase + (size_t)it * 64 * DD) * 2,
            (const char*)Kl + (kbase + (size_t)it * 64 * DD) * 2,
            (const char*)Vh + (kbase + (size_t)it * 64 * DD) * 2,
            (const char*)Vl + (kbase + (size_t)it * 64 * DD) * 2};
        #pragma unroll
        for (int mtx = 0; mtx < 4; mtx++) {
            #pragma unroll
            for (int i = 0; i < 2; i++) {
                int idx = tid + i * 256;       // 0..511
                int row = idx >> 3, c = idx & 7;
                cp16(base + mtx * 8192u + sw128((uint32_t)idx * 16),
                     g[mtx] + (size_t)row * 2048 + c * 16);
            }
        }
        asm volatile("cp.async.commit_group;" ::: "memory");
    };

    load_kv(0, 0);

    for (int it = 0; it < SS / 64; it++) {
        if (it + 1 < SS / 64) {
            load_kv(it + 1, (it + 1) & 1);
            asm volatile("cp.async.wait_group 1;" ::: "memory");
        } else {
            asm volatile("cp.async.wait_group 0;" ::: "memory");
        }
        __syncthreads();
        uint32_t base = sb + (it & 1) * A_STAGE;

        // ---- S = Q K^T (bf16x3) ----
        float s[8][4];
        #pragma unroll
        for (int nt = 0; nt < 8; nt++)
            #pragma unroll
            for (int i = 0; i < 4; i++) s[nt][i] = 0.f;

        #pragma unroll
        for (int k16 = 0; k16 < 4; k16++) {
            uint32_t kf_h[8][2], kf_l[8][2];
            #pragma unroll
            for (int nh = 0; nh < 4; nh++) {
                int row = nh * 16 + (lane & 15);
                uint32_t off = sw128((uint32_t)row * 128 +
                                     (k16 * 2 + (lane >> 4)) * 16);
                uint32_t r[4];
                ldsm_x4(r, base + off);
                kf_h[nh * 2][0] = r[0]; kf_h[nh * 2 + 1][0] = r[1];
                kf_h[nh * 2][1] = r[2]; kf_h[nh * 2 + 1][1] = r[3];
                ldsm_x4(r, base + 8192u + off);
                kf_l[nh * 2][0] = r[0]; kf_l[nh * 2 + 1][0] = r[1];
                kf_l[nh * 2][1] = r[2]; kf_l[nh * 2 + 1][1] = r[3];
            }
            #pragma unroll
            for (int nt = 0; nt < 8; nt++) {
                mma16816(s[nt], qf_h[k16], kf_h[nt]);
                mma16816(s[nt], qf_h[k16], kf_l[nt]);
                mma16816(s[nt], qf_l[k16], kf_h[nt]);
            }
        }

        // ---- online softmax (rows r and r+8 per lane) ----
        #pragma unroll
        for (int nt = 0; nt < 8; nt++)
            #pragma unroll
            for (int i = 0; i < 4; i++) s[nt][i] *= 0.125f;

        #pragma unroll
        for (int hf = 0; hf < 2; hf++) {
            float mx = NEG_INF;
            #pragma unroll
            for (int nt = 0; nt < 8; nt++)
                mx = fmaxf(mx, fmaxf(s[nt][2 * hf], s[nt][2 * hf + 1]));
            mx = fmaxf(mx, __shfl_xor_sync(0xffffffffu, mx, 1));
            mx = fmaxf(mx, __shfl_xor_sync(0xffffffffu, mx, 2));
            float mn = fmaxf(mrow[hf], mx);
            float scale = __expf(mrow[hf] - mn);
            float rs = 0.f;
            #pragma unroll
            for (int nt = 0; nt < 8; nt++) {
                float p0 = __expf(s[nt][2 * hf] - mn);
                float p1 = __expf(s[nt][2 * hf + 1] - mn);
                s[nt][2 * hf] = p0; s[nt][2 * hf + 1] = p1;
                rs += p0 + p1;
            }
            rs += __shfl_xor_sync(0xffffffffu, rs, 1);
            rs += __shfl_xor_sync(0xffffffffu, rs, 2);
            lrow[hf] = lrow[hf] * scale + rs;
            mrow[hf] = mn;
            #pragma unroll
            for (int dt = 0; dt < 8; dt++) {
                o[dt][2 * hf]     *= scale;
                o[dt][2 * hf + 1] *= scale;
            }
        }

        // ---- O += P V (bf16x3, P a-frags built in-register) ----
        #pragma unroll
        for (int t = 0; t < 4; t++) {
            uint32_t pa_h[4], pa_l[4];
            split2(s[2 * t][0],     s[2 * t][1],     pa_h[0], pa_l[0]);
            split2(s[2 * t][2],     s[2 * t][3],     pa_h[1], pa_l[1]);
            split2(s[2 * t + 1][0], s[2 * t + 1][1], pa_h[2], pa_l[2]);
            split2(s[2 * t + 1][2], s[2 * t + 1][3], pa_h[3], pa_l[3]);

            uint32_t vf_h[8][2], vf_l[8][2];
            #pragma unroll
            for (int dp = 0; dp < 4; dp++) {
                int row = t * 16 + (lane & 15);
                uint32_t off = sw128((uint32_t)row * 128 +
                                     (dp * 2 + (lane >> 4)) * 16);
                uint32_t r[4];
                ldsm_x4t(r, base + 16384u + off);
                vf_h[dp * 2][0] = r[0]; vf_h[dp * 2][1] = r[1];
                vf_h[dp * 2 + 1][0] = r[2]; vf_h[dp * 2 + 1][1] = r[3];
                ldsm_x4t(r, base + 24576u + off);
                vf_l[dp * 2][0] = r[0]; vf_l[dp * 2][1] = r[1];
                vf_l[dp * 2 + 1][0] = r[2]; vf_l[dp * 2 + 1][1] = r[3];
            }
            #pragma unroll
            for (int dt = 0; dt < 8; dt++) {
                mma16816(o[dt], pa_h, vf_h[dt]);
                mma16816(o[dt], pa_h, vf_l[dt]);
                mma16816(o[dt], pa_l, vf_h[dt]);
            }
        }
        __syncthreads();
    }

    // ---- epilogue: ctx = O / l, written as bf16 hi/lo ----
    const int r = lane >> 2, cp2 = (lane & 3) * 2;
    #pragma unroll
    for (int hf = 0; hf < 2; hf++) {
        float inv = 1.f / lrow[hf];
        int row = q0 + w * 16 + r + hf * 8;
        size_t ob = ((size_t)b * SS + row) * DD + hd * 64;
        #pragma unroll
        for (int dt = 0; dt < 8; dt++) {
            float v0 = o[dt][2 * hf] * inv;
            float v1 = o[dt][2 * hf + 1] * inv;
            uint32_t h, l;
            split2(v0, v1, h, l);
            *reinterpret_cast<uint32_t*>(Ch + ob + dt * 8 + cp2) = h;
            *reinterpret_cast<uint32_t*>(Cl + ob + dt * 8 + cp2) = l;
        }
    }
}

// ---------------------------------------------------------------------------
// Launch
// ---------------------------------------------------------------------------
extern "C" void kernel_launch(void* const* d_in, const int* in_sizes, int n_in,
                              void* d_out, int out_size)
{
    const float* x  = (const float*)d_in[0];
    const float* Wq = (const float*)d_in[1];
    const float* bq = (const float*)d_in[2];
    const float* Wk = (const float*)d_in[3];
    const float* bk = (const float*)d_in[4];
    const float* Wv = (const float*)d_in[5];
    const float* bv = (const float*)d_in[6];
    const float* Wo = (const float*)d_in[7];
    const float* bo = (const float*)d_in[8];
    float* out = (float*)d_out;

    __nv_bfloat16 *xh, *xl, *qh, *ql, *kh, *kl, *vh, *vl, *ch, *cl, *wh, *wl;
    cudaGetSymbolAddress((void**)&xh, g_xh);
    cudaGetSymbolAddress((void**)&xl, g_xl);
    cudaGetSymbolAddress((void**)&qh, g_qh);
    cudaGetSymbolAddress((void**)&ql, g_ql);
    cudaGetSymbolAddress((void**)&kh, g_kh);
    cudaGetSymbolAddress((void**)&kl, g_kl);
    cudaGetSymbolAddress((void**)&vh, g_vh);
    cudaGetSymbolAddress((void**)&vl, g_vl);
    cudaGetSymbolAddress((void**)&ch, g_ch);
    cudaGetSymbolAddress((void**)&cl, g_cl);
    cudaGetSymbolAddress((void**)&wh, g_wh);
    cudaGetSymbolAddress((void**)&wl, g_wl);

    cudaFuncSetAttribute(hgemm_bf16x3,
                         cudaFuncAttributeMaxDynamicSharedMemorySize, G_SMEM);
    cudaFuncSetAttribute(attn_mma,
                         cudaFuncAttributeMaxDynamicSharedMemorySize, A_SMEM);

    // hi/lo splits for x and weights
    const int nx4 = MM * DD / 4;
    const int nw4 = DD * DD / 4;
    split_hi_lo<<<nx4 / 256, 256>>>(x, xh, xl, nx4);
    split_hi_lo<<<nw4 / 256, 256>>>(Wq, wh + 0 * DD * DD, wl + 0 * DD * DD, nw4);
    split_hi_lo<<<nw4 / 256, 256>>>(Wk, wh + 1 * DD * DD, wl + 1 * DD * DD, nw4);
    split_hi_lo<<<nw4 / 256, 256>>>(Wv, wh + 2 * DD * DD, wl + 2 * DD * DD, nw4);
    split_hi_lo<<<nw4 / 256, 256>>>(Wo, wh + 3 * DD * DD, wl + 3 * DD * DD, nw4);

    dim3 gg(DD / 128, MM / 128);  // (8, 64)
    hgemm_bf16x3<<<gg, 256, G_SMEM>>>(xh, xl, wh + 0 * DD * DD, wl + 0 * DD * DD,
                                      bq, nullptr, qh, ql);
    hgemm_bf16x3<<<gg, 256, G_SMEM>>>(xh, xl, wh + 1 * DD * DD, wl + 1 * DD * DD,
                                      bk, nullptr, kh, kl);
    hgemm_bf16x3<<<gg, 256, G_SMEM>>>(xh, xl, wh + 2 * DD * DD, wl + 2 * DD * DD,
                                      bv, nullptr, vh, vl);

    dim3 ag(SS / 128, HH, BB);    // (16, 16, 4)
    attn_mma<<<ag, 256, A_SMEM>>>(qh, ql, kh, kl, vh, vl, ch, cl);

    hgemm_bf16x3<<<gg, 256, G_SMEM>>>(ch, cl, wh + 3 * DD * DD, wl + 3 * DD * DD,
                                      bo, out, nullptr, nullptr);
}

// round 4
// speedup vs baseline: 3.0212x; 1.0278x over previous
#include <cuda_runtime.h>
#include <cuda_bf16.h>
#include <math.h>
#include <stdint.h>

// Problem constants
#define BB 4
#define SS 2048
#define DD 1024
#define HH 16
#define DK 64
#define MM (BB * SS)   // 8192 rows

// 0.125 (1/sqrt(DK)) * log2(e): folded into Q so softmax runs in log2 domain
#define SCALE_Q 0.1803368801111204f

// ---------------------------------------------------------------------------
// Scratch (static device globals: allocation-free per harness rules)
// ---------------------------------------------------------------------------
__device__ __align__(16) __nv_bfloat16 g_xh[MM * DD];
__device__ __align__(16) __nv_bfloat16 g_xl[MM * DD];
__device__ __align__(16) __nv_bfloat16 g_qh[MM * DD];
__device__ __align__(16) __nv_bfloat16 g_ql[MM * DD];
__device__ __align__(16) __nv_bfloat16 g_kh[MM * DD];
__device__ __align__(16) __nv_bfloat16 g_kl[MM * DD];
__device__ __align__(16) __nv_bfloat16 g_vh[MM * DD];
__device__ __align__(16) __nv_bfloat16 g_vl[MM * DD];
__device__ __align__(16) __nv_bfloat16 g_ch[MM * DD];
__device__ __align__(16) __nv_bfloat16 g_cl[MM * DD];
__device__ __align__(16) __nv_bfloat16 g_wh[4 * DD * DD];
__device__ __align__(16) __nv_bfloat16 g_wl[4 * DD * DD];

// ---------------------------------------------------------------------------
// Low-level helpers (base ISA only: ldmatrix + mma.sync + cp.async)
// ---------------------------------------------------------------------------
__device__ __forceinline__ uint32_t smem_u32(const void* p) {
    uint32_t a;
    asm("{ .reg .u64 t; cvta.to.shared.u64 t, %1; cvt.u32.u64 %0, t; }"
        : "=r"(a) : "l"(p));
    return a;
}

__device__ __forceinline__ uint32_t sw128(uint32_t off) {
    return off ^ ((off >> 3) & 0x70);
}

__device__ __forceinline__ void cp16(uint32_t dst, const void* src) {
    asm volatile("cp.async.cg.shared.global [%0], [%1], 16;"
                 :: "r"(dst), "l"(src) : "memory");
}

__device__ __forceinline__ void ldsm_x4(uint32_t* r, uint32_t addr) {
    asm volatile("ldmatrix.sync.aligned.m8n8.x4.shared.b16 {%0,%1,%2,%3}, [%4];"
                 : "=r"(r[0]), "=r"(r[1]), "=r"(r[2]), "=r"(r[3]) : "r"(addr));
}

__device__ __forceinline__ void ldsm_x4t(uint32_t* r, uint32_t addr) {
    asm volatile("ldmatrix.sync.aligned.m8n8.x4.trans.shared.b16 {%0,%1,%2,%3}, [%4];"
                 : "=r"(r[0]), "=r"(r[1]), "=r"(r[2]), "=r"(r[3]) : "r"(addr));
}

__device__ __forceinline__ void mma16816(float* c, const uint32_t* a,
                                         const uint32_t* b) {
    asm volatile(
        "mma.sync.aligned.m16n8k16.row.col.f32.bf16.bf16.f32 "
        "{%0,%1,%2,%3}, {%4,%5,%6,%7}, {%8,%9}, {%0,%1,%2,%3};"
        : "+f"(c[0]), "+f"(c[1]), "+f"(c[2]), "+f"(c[3])
        : "r"(a[0]), "r"(a[1]), "r"(a[2]), "r"(a[3]), "r"(b[0]), "r"(b[1]));
}

__device__ __forceinline__ float ex2f(float x) {
    float r;
    asm("ex2.approx.ftz.f32 %0, %1;" : "=f"(r) : "f"(x));
    return r;
}

// Fast hi/lo split: hi = bit-truncated bf16 (exact), lo = rn_bf16(x - hi).
// 6 instrs: 2 LOP, 2 FADD, 1 PRMT, 1 CVT.bf16x2. Residual error ~2^-17.
__device__ __forceinline__ void split2(float x, float y,
                                       uint32_t& hi, uint32_t& lo) {
    uint32_t xi = __float_as_uint(x), yi = __float_as_uint(y);
    float rx = x - __uint_as_float(xi & 0xFFFF0000u);
    float ry = y - __uint_as_float(yi & 0xFFFF0000u);
    hi = __byte_perm(xi, yi, 0x7632);   // {lo16: x.hi16, hi16: y.hi16}
    asm("cvt.rn.bf16x2.f32 %0, %1, %2;" : "=r"(lo) : "f"(ry), "f"(rx));
}

// ---------------------------------------------------------------------------
// fp32 -> bf16 hi/lo split pass (x and the 4 weight matrices)
// ---------------------------------------------------------------------------
__global__ __launch_bounds__(256) void split_hi_lo(
    const float* __restrict__ src,
    __nv_bfloat16* __restrict__ hi, __nv_bfloat16* __restrict__ lo, int n4)
{
    int i = blockIdx.x * 256 + threadIdx.x;
    if (i >= n4) return;
    float4 v = reinterpret_cast<const float4*>(src)[i];
    uint32_t h0, l0, h1, l1;
    split2(v.x, v.y, h0, l0);
    split2(v.z, v.w, h1, l1);
    reinterpret_cast<uint32_t*>(hi)[2 * i]     = h0;
    reinterpret_cast<uint32_t*>(hi)[2 * i + 1] = h1;
    reinterpret_cast<uint32_t*>(lo)[2 * i]     = l0;
    reinterpret_cast<uint32_t*>(lo)[2 * i + 1] = l1;
}

// ---------------------------------------------------------------------------
// bf16x3 GEMM (NT), fused over up to 3 weight matrices (mat = blockIdx.x>>3):
//   C[m,n] = ((Ah+Al)[m,:] . (Wh+Wl)[n,:] + bias[n]) * scale
// CTA 128x128, BK=64, 8 warps (2x4), warp tile 64x32, 3-stage cp.async.
// F32OUT=false: bf16 hi/lo outputs (QKV, Q scaled); true: fp32 (O proj).
// ---------------------------------------------------------------------------
#define G_STAGE 65536   // Ah 16K | Al 16K | Wh 16K | Wl 16K
#define G_SMEM  (3 * G_STAGE)

template<bool F32OUT>
__global__ __launch_bounds__(256, 1) void hgemm(
    const __nv_bfloat16* __restrict__ Ah, const __nv_bfloat16* __restrict__ Al,
    const __nv_bfloat16* __restrict__ Wh, const __nv_bfloat16* __restrict__ Wl,
    const float* __restrict__ B0, const float* __restrict__ B1,
    const float* __restrict__ B2,
    __nv_bfloat16* __restrict__ O0h, __nv_bfloat16* __restrict__ O0l,
    __nv_bfloat16* __restrict__ O1h, __nv_bfloat16* __restrict__ O1l,
    __nv_bfloat16* __restrict__ O2h, __nv_bfloat16* __restrict__ O2l,
    float* __restrict__ Cf)
{
    extern __shared__ __align__(1024) char smem[];
    uint32_t sb = smem_u32(smem);
    const int tid = threadIdx.x;
    const int w = tid >> 5, lane = tid & 31;
    const int wr = w >> 2, wc = w & 3;
    const int mat = blockIdx.x >> 3;
    const int n0  = (blockIdx.x & 7) * 128;
    const int m0  = blockIdx.y * 128;
    const __nv_bfloat16* Wmh = Wh + (size_t)mat * DD * DD;
    const __nv_bfloat16* Wml = Wl + (size_t)mat * DD * DD;

    float acc[4][4][4];
    #pragma unroll
    for (int mt = 0; mt < 4; mt++)
        #pragma unroll
        for (int nt = 0; nt < 4; nt++)
            #pragma unroll
            for (int i = 0; i < 4; i++) acc[mt][nt][i] = 0.f;

    auto load_stage = [&](int t, int s) {
        uint32_t base = sb + s * G_STAGE;
        const char* srcs[4] = {
            (const char*)Ah  + (size_t)m0 * 2048 + t * 128,
            (const char*)Al  + (size_t)m0 * 2048 + t * 128,
            (const char*)Wmh + (size_t)n0 * 2048 + t * 128,
            (const char*)Wml + (size_t)n0 * 2048 + t * 128};
        #pragma unroll
        for (int mtx = 0; mtx < 4; mtx++) {
            #pragma unroll
            for (int i = 0; i < 4; i++) {
                int idx = tid + i * 256;       // 0..1023 (row*8 + chunk)
                int row = idx >> 3, c = idx & 7;
                cp16(base + mtx * 16384u + sw128((uint32_t)idx * 16),
                     srcs[mtx] + (size_t)row * 2048 + c * 16);
            }
        }
        asm volatile("cp.async.commit_group;" ::: "memory");
    };

    const int NT = DD / 64;  // 16
    load_stage(0, 0);
    load_stage(1, 1);

    for (int t = 0; t < NT; t++) {
        if (t < NT - 1)
            asm volatile("cp.async.wait_group 1;" ::: "memory");
        else
            asm volatile("cp.async.wait_group 0;" ::: "memory");
        __syncthreads();
        if (t + 2 < NT) load_stage(t + 2, (t + 2) % 3);
        uint32_t base = sb + (t % 3) * G_STAGE;

        #pragma unroll
        for (int k16 = 0; k16 < 4; k16++) {
            uint32_t af_h[4][4], af_l[4][4];
            #pragma unroll
            for (int mt = 0; mt < 4; mt++) {
                int row = wr * 64 + mt * 16 + (lane & 15);
                uint32_t off = sw128((uint32_t)row * 128 +
                                     (k16 * 2 + (lane >> 4)) * 16);
                ldsm_x4(af_h[mt], base + off);
                ldsm_x4(af_l[mt], base + 16384u + off);
            }
            uint32_t bf_h[4][2], bf_l[4][2];
            #pragma unroll
            for (int nh = 0; nh < 2; nh++) {
                int row = wc * 32 + nh * 16 + (lane & 15);
                uint32_t off = sw128((uint32_t)row * 128 +
                                     (k16 * 2 + (lane >> 4)) * 16);
                uint32_t r[4];
                ldsm_x4(r, base + 32768u + off);
                bf_h[nh * 2][0] = r[0]; bf_h[nh * 2 + 1][0] = r[1];
                bf_h[nh * 2][1] = r[2]; bf_h[nh * 2 + 1][1] = r[3];
                ldsm_x4(r, base + 49152u + off);
                bf_l[nh * 2][0] = r[0]; bf_l[nh * 2 + 1][0] = r[1];
                bf_l[nh * 2][1] = r[2]; bf_l[nh * 2 + 1][1] = r[3];
            }
            #pragma unroll
            for (int mt = 0; mt < 4; mt++)
                #pragma unroll
                for (int nt = 0; nt < 4; nt++) {
                    mma16816(acc[mt][nt], af_h[mt], bf_h[nt]);
                    mma16816(acc[mt][nt], af_h[mt], bf_l[nt]);
                    mma16816(acc[mt][nt], af_l[mt], bf_h[nt]);
                }
        }
    }

    // Epilogue
    const float* bias = (mat == 0) ? B0 : (mat == 1 ? B1 : B2);
    __nv_bfloat16* Oh = (mat == 0) ? O0h : (mat == 1 ? O1h : O2h);
    __nv_bfloat16* Ol = (mat == 0) ? O0l : (mat == 1 ? O1l : O2l);
    const float scl = (!F32OUT && mat == 0) ? SCALE_Q : 1.0f;
    const int r = lane >> 2, cp2 = (lane & 3) * 2;
    #pragma unroll
    for (int mt = 0; mt < 4; mt++) {
        #pragma unroll
        for (int nt = 0; nt < 4; nt++) {
            int row = m0 + wr * 64 + mt * 16 + r;
            int col = n0 + wc * 32 + nt * 8 + cp2;
            float b0 = bias[col], b1 = bias[col + 1];
            float v00 = (acc[mt][nt][0] + b0) * scl;
            float v01 = (acc[mt][nt][1] + b1) * scl;
            float v10 = (acc[mt][nt][2] + b0) * scl;
            float v11 = (acc[mt][nt][3] + b1) * scl;
            if (F32OUT) {
                *reinterpret_cast<float2*>(Cf + (size_t)row * DD + col) =
                    make_float2(v00, v01);
                *reinterpret_cast<float2*>(Cf + (size_t)(row + 8) * DD + col) =
                    make_float2(v10, v11);
            } else {
                uint32_t h, l;
                split2(v00, v01, h, l);
                *reinterpret_cast<uint32_t*>(Oh + (size_t)row * DD + col) = h;
                *reinterpret_cast<uint32_t*>(Ol + (size_t)row * DD + col) = l;
                split2(v10, v11, h, l);
                *reinterpret_cast<uint32_t*>(Oh + (size_t)(row + 8) * DD + col) = h;
                *reinterpret_cast<uint32_t*>(Ol + (size_t)(row + 8) * DD + col) = l;
            }
        }
    }
}

// ---------------------------------------------------------------------------
// Flash attention on mma.sync bf16x3, log2-domain softmax (Q pre-scaled by
// 0.125*log2e). 256 threads, BM=128, BN=64, 3-stage KV pipeline.
// ---------------------------------------------------------------------------
#define A_STAGE 32768   // Kh 8K | Kl 8K | Vh 8K | Vl 8K
#define A_SMEM  (3 * A_STAGE)

__global__ __launch_bounds__(256, 1) void attn_mma(
    const __nv_bfloat16* __restrict__ Qh, const __nv_bfloat16* __restrict__ Ql,
    const __nv_bfloat16* __restrict__ Kh, const __nv_bfloat16* __restrict__ Kl,
    const __nv_bfloat16* __restrict__ Vh, const __nv_bfloat16* __restrict__ Vl,
    __nv_bfloat16* __restrict__ Ch, __nv_bfloat16* __restrict__ Cl)
{
    extern __shared__ __align__(1024) char smem[];
    uint32_t sb = smem_u32(smem);
    const int tid = threadIdx.x;
    const int w = tid >> 5, lane = tid & 31;
    const int q0 = blockIdx.x * 128;
    const int hd = blockIdx.y;
    const int b  = blockIdx.z;

    const size_t qbase = ((size_t)b * SS + q0) * DD + hd * 64;
    const size_t kbase = (size_t)b * SS * DD + hd * 64;

    auto load_kv = [&](int it, int s) {
        uint32_t base = sb + s * A_STAGE;
        const char* g[4] = {
            (const char*)Kh + (kbase + (size_t)it * 64 * DD) * 2,
            (const char*)Kl + (kbase + (size_t)it * 64 * DD) * 2,
            (const char*)Vh + (kbase + (size_t)it * 64 * DD) * 2,
            (const char*)Vl + (kbase + (size_t)it * 64 * DD) * 2};
        #pragma unroll
        for (int mtx = 0; mtx < 4; mtx++) {
            #pragma unroll
            for (int i = 0; i < 2; i++) {
                int idx = tid + i * 256;       // 0..511
                int row = idx >> 3, c = idx & 7;
                cp16(base + mtx * 8192u + sw128((uint32_t)idx * 16),
                     g[mtx] + (size_t)row * 2048 + c * 16);
            }
        }
        asm volatile("cp.async.commit_group;" ::: "memory");
    };

    // ---- Prologue: Q into stage-2 area; KV stages 0,1 in flight ----
    {
        const char* gq_h = (const char*)Qh + qbase * 2;
        const char* gq_l = (const char*)Ql + qbase * 2;
        uint32_t qb = sb + 2 * A_STAGE;
        #pragma unroll
        for (int i = 0; i < 4; i++) {
            int idx = tid + i * 256;
            int row = idx >> 3, c = idx & 7;
            cp16(qb + sw128((uint32_t)idx * 16),
                 gq_h + (size_t)row * 2048 + c * 16);
            cp16(qb + 16384u + sw128((uint32_t)idx * 16),
                 gq_l + (size_t)row * 2048 + c * 16);
        }
        asm volatile("cp.async.commit_group;" ::: "memory");
    }
    load_kv(0, 0);
    load_kv(1, 1);
    asm volatile("cp.async.wait_group 2;" ::: "memory");  // Q landed
    __syncthreads();

    uint32_t qf_h[4][4], qf_l[4][4];
    {
        uint32_t qb = sb + 2 * A_STAGE;
        #pragma unroll
        for (int k16 = 0; k16 < 4; k16++) {
            int row = w * 16 + (lane & 15);
            uint32_t off = sw128((uint32_t)row * 128 +
                                 (k16 * 2 + (lane >> 4)) * 16);
            ldsm_x4(qf_h[k16], qb + off);
            ldsm_x4(qf_l[k16], qb + 16384u + off);
        }
    }
    __syncthreads();   // Q area may now be reused as KV stage 2

    float o[8][4];
    #pragma unroll
    for (int dt = 0; dt < 8; dt++)
        #pragma unroll
        for (int i = 0; i < 4; i++) o[dt][i] = 0.f;
    const float NEG_INF = __int_as_float(0xff800000);
    float mrow[2] = {NEG_INF, NEG_INF};
    float lrow[2] = {0.f, 0.f};

    const int NT = SS / 64;  // 32
    for (int it = 0; it < NT; it++) {
        if (it < NT - 1)
            asm volatile("cp.async.wait_group 1;" ::: "memory");
        else
            asm volatile("cp.async.wait_group 0;" ::: "memory");
        __syncthreads();
        if (it + 2 < NT) load_kv(it + 2, (it + 2) % 3);
        uint32_t base = sb + (it % 3) * A_STAGE;

        // ---- S = Q K^T (bf16x3, already in log2 units via Q scale) ----
        float s[8][4];
        #pragma unroll
        for (int nt = 0; nt < 8; nt++)
            #pragma unroll
            for (int i = 0; i < 4; i++) s[nt][i] = 0.f;

        #pragma unroll
        for (int k16 = 0; k16 < 4; k16++) {
            uint32_t kf_h[8][2], kf_l[8][2];
            #pragma unroll
            for (int nh = 0; nh < 4; nh++) {
                int row = nh * 16 + (lane & 15);
                uint32_t off = sw128((uint32_t)row * 128 +
                                     (k16 * 2 + (lane >> 4)) * 16);
                uint32_t r[4];
                ldsm_x4(r, base + off);
                kf_h[nh * 2][0] = r[0]; kf_h[nh * 2 + 1][0] = r[1];
                kf_h[nh * 2][1] = r[2]; kf_h[nh * 2 + 1][1] = r[3];
                ldsm_x4(r, base + 8192u + off);
                kf_l[nh * 2][0] = r[0]; kf_l[nh * 2 + 1][0] = r[1];
                kf_l[nh * 2][1] = r[2]; kf_l[nh * 2 + 1][1] = r[3];
            }
            #pragma unroll
            for (int nt = 0; nt < 8; nt++) {
                mma16816(s[nt], qf_h[k16], kf_h[nt]);
                mma16816(s[nt], qf_h[k16], kf_l[nt]);
                mma16816(s[nt], qf_l[k16], kf_h[nt]);
            }
        }

        // ---- online softmax in log2 domain ----
        #pragma unroll
        for (int hf = 0; hf < 2; hf++) {
            float mx = NEG_INF;
            #pragma unroll
            for (int nt = 0; nt < 8; nt++)
                mx = fmaxf(mx, fmaxf(s[nt][2 * hf], s[nt][2 * hf + 1]));
            mx = fmaxf(mx, __shfl_xor_sync(0xffffffffu, mx, 1));
            mx = fmaxf(mx, __shfl_xor_sync(0xffffffffu, mx, 2));
            float mn = fmaxf(mrow[hf], mx);
            uint32_t keep = __all_sync(0xffffffffu, mn == mrow[hf]);
            float rs = 0.f;
            #pragma unroll
            for (int nt = 0; nt < 8; nt++) {
                float p0 = ex2f(s[nt][2 * hf] - mn);
                float p1 = ex2f(s[nt][2 * hf + 1] - mn);
                s[nt][2 * hf] = p0; s[nt][2 * hf + 1] = p1;
                rs += p0 + p1;
            }
            rs += __shfl_xor_sync(0xffffffffu, rs, 1);
            rs += __shfl_xor_sync(0xffffffffu, rs, 2);
            if (keep) {
                lrow[hf] += rs;
            } else {
                float scale = ex2f(mrow[hf] - mn);
                lrow[hf] = lrow[hf] * scale + rs;
                mrow[hf] = mn;
                #pragma unroll
                for (int dt = 0; dt < 8; dt++) {
                    o[dt][2 * hf]     *= scale;
                    o[dt][2 * hf + 1] *= scale;
                }
            }
        }

        // ---- O += P V (bf16x3, P a-frags built in-register) ----
        #pragma unroll
        for (int t = 0; t < 4; t++) {
            uint32_t pa_h[4], pa_l[4];
            split2(s[2 * t][0],     s[2 * t][1],     pa_h[0], pa_l[0]);
            split2(s[2 * t][2],     s[2 * t][3],     pa_h[1], pa_l[1]);
            split2(s[2 * t + 1][0], s[2 * t + 1][1], pa_h[2], pa_l[2]);
            split2(s[2 * t + 1][2], s[2 * t + 1][3], pa_h[3], pa_l[3]);

            uint32_t vf_h[8][2], vf_l[8][2];
            #pragma unroll
            for (int dp = 0; dp < 4; dp++) {
                int row = t * 16 + (lane & 15);
                uint32_t off = sw128((uint32_t)row * 128 +
                                     (dp * 2 + (lane >> 4)) * 16);
                uint32_t r[4];
                ldsm_x4t(r, base + 16384u + off);
                vf_h[dp * 2][0] = r[0]; vf_h[dp * 2][1] = r[1];
                vf_h[dp * 2 + 1][0] = r[2]; vf_h[dp * 2 + 1][1] = r[3];
                ldsm_x4t(r, base + 24576u + off);
                vf_l[dp * 2][0] = r[0]; vf_l[dp * 2][1] = r[1];
                vf_l[dp * 2 + 1][0] = r[2]; vf_l[dp * 2 + 1][1] = r[3];
            }
            #pragma unroll
            for (int dt = 0; dt < 8; dt++) {
                mma16816(o[dt], pa_h, vf_h[dt]);
                mma16816(o[dt], pa_h, vf_l[dt]);
                mma16816(o[dt], pa_l, vf_h[dt]);
            }
        }
    }

    // ---- epilogue: ctx = O / l, written as bf16 hi/lo ----
    const int r = lane >> 2, cp2 = (lane & 3) * 2;
    #pragma unroll
    for (int hf = 0; hf < 2; hf++) {
        float inv = 1.f / lrow[hf];
        int row = q0 + w * 16 + r + hf * 8;
        size_t ob = ((size_t)b * SS + row) * DD + hd * 64;
        #pragma unroll
        for (int dt = 0; dt < 8; dt++) {
            float v0 = o[dt][2 * hf] * inv;
            float v1 = o[dt][2 * hf + 1] * inv;
            uint32_t h, l;
            split2(v0, v1, h, l);
            *reinterpret_cast<uint32_t*>(Ch + ob + dt * 8 + cp2) = h;
            *reinterpret_cast<uint32_t*>(Cl + ob + dt * 8 + cp2) = l;
        }
    }
}

// ---------------------------------------------------------------------------
// Launch
// ---------------------------------------------------------------------------
extern "C" void kernel_launch(void* const* d_in, const int* in_sizes, int n_in,
                              void* d_out, int out_size)
{
    const float* x  = (const float*)d_in[0];
    const float* Wq = (const float*)d_in[1];
    const float* bq = (const float*)d_in[2];
    const float* Wk = (const float*)d_in[3];
    const float* bk = (const float*)d_in[4];
    const float* Wv = (const float*)d_in[5];
    const float* bv = (const float*)d_in[6];
    const float* Wo = (const float*)d_in[7];
    const float* bo = (const float*)d_in[8];
    float* out = (float*)d_out;

    __nv_bfloat16 *xh, *xl, *qh, *ql, *kh, *kl, *vh, *vl, *ch, *cl, *wh, *wl;
    cudaGetSymbolAddress((void**)&xh, g_xh);
    cudaGetSymbolAddress((void**)&xl, g_xl);
    cudaGetSymbolAddress((void**)&qh, g_qh);
    cudaGetSymbolAddress((void**)&ql, g_ql);
    cudaGetSymbolAddress((void**)&kh, g_kh);
    cudaGetSymbolAddress((void**)&kl, g_kl);
    cudaGetSymbolAddress((void**)&vh, g_vh);
    cudaGetSymbolAddress((void**)&vl, g_vl);
    cudaGetSymbolAddress((void**)&ch, g_ch);
    cudaGetSymbolAddress((void**)&cl, g_cl);
    cudaGetSymbolAddress((void**)&wh, g_wh);
    cudaGetSymbolAddress((void**)&wl, g_wl);

    cudaFuncSetAttribute(hgemm<false>,
                         cudaFuncAttributeMaxDynamicSharedMemorySize, G_SMEM);
    cudaFuncSetAttribute(hgemm<true>,
                         cudaFuncAttributeMaxDynamicSharedMemorySize, G_SMEM);
    cudaFuncSetAttribute(attn_mma,
                         cudaFuncAttributeMaxDynamicSharedMemorySize, A_SMEM);

    // hi/lo splits for x and weights (Wq,Wk,Wv,Wo packed into wh/wl)
    const int nx4 = MM * DD / 4;
    const int nw4 = DD * DD / 4;
    split_hi_lo<<<nx4 / 256, 256>>>(x, xh, xl, nx4);
    split_hi_lo<<<nw4 / 256, 256>>>(Wq, wh + 0 * DD * DD, wl + 0 * DD * DD, nw4);
    split_hi_lo<<<nw4 / 256, 256>>>(Wk, wh + 1 * DD * DD, wl + 1 * DD * DD, nw4);
    split_hi_lo<<<nw4 / 256, 256>>>(Wv, wh + 2 * DD * DD, wl + 2 * DD * DD, nw4);
    split_hi_lo<<<nw4 / 256, 256>>>(Wo, wh + 3 * DD * DD, wl + 3 * DD * DD, nw4);

    // Fused QKV projection (mat 0 = Q gets softmax scale folded in)
    dim3 gqkv(24, 64);
    hgemm<false><<<gqkv, 256, G_SMEM>>>(
        xh, xl, wh, wl, bq, bk, bv,
        qh, ql, kh, kl, vh, vl, nullptr);

    dim3 ag(SS / 128, HH, BB);    // (16, 16, 4)
    attn_mma<<<ag, 256, A_SMEM>>>(qh, ql, kh, kl, vh, vl, ch, cl);

    // Output projection (fp32 out)
    dim3 go(8, 64);
    hgemm<true><<<go, 256, G_SMEM>>>(
        ch, cl, wh + 3 * DD * DD, wl + 3 * DD * DD, bo, nullptr, nullptr,
        nullptr, nullptr, nullptr, nullptr, nullptr, nullptr, out);
}

// round 5
// speedup vs baseline: 3.5439x; 1.1730x over previous
#include <cuda_runtime.h>
#include <cuda_fp16.h>
#include <math.h>
#include <stdint.h>

// Problem constants
#define BB 4
#define SS 2048
#define DD 1024
#define HH 16
#define DK 64
#define MM (BB * SS)   // 8192 rows

// 0.125 (1/sqrt(DK)) * log2(e): folded into Q so softmax runs in log2 domain
#define SCALE_Q 0.1803368801111204f

// ---------------------------------------------------------------------------
// Scratch (static device globals: allocation-free per harness rules)
// ---------------------------------------------------------------------------
__device__ __align__(16) __half g_xh[MM * DD];
__device__ __align__(16) __half g_xl[MM * DD];
__device__ __align__(16) __half g_qh[MM * DD];
__device__ __align__(16) __half g_ql[MM * DD];
__device__ __align__(16) __half g_kh[MM * DD];
__device__ __align__(16) __half g_kl[MM * DD];
__device__ __align__(16) __half g_vh[MM * DD];
__device__ __align__(16) __half g_vl[MM * DD];
__device__ __align__(16) __half g_ch[MM * DD];
__device__ __align__(16) __half g_cl[MM * DD];
__device__ __align__(16) __half g_wh[4 * DD * DD];   // weights: fp16 hi only

// ---------------------------------------------------------------------------
// Low-level helpers (base ISA only: ldmatrix + mma.sync + cp.async)
// ---------------------------------------------------------------------------
__device__ __forceinline__ uint32_t smem_u32(const void* p) {
    uint32_t a;
    asm("{ .reg .u64 t; cvta.to.shared.u64 t, %1; cvt.u32.u64 %0, t; }"
        : "=r"(a) : "l"(p));
    return a;
}

__device__ __forceinline__ uint32_t sw128(uint32_t off) {
    return off ^ ((off >> 3) & 0x70);
}

__device__ __forceinline__ void cp16(uint32_t dst, const void* src) {
    asm volatile("cp.async.cg.shared.global [%0], [%1], 16;"
                 :: "r"(dst), "l"(src) : "memory");
}

__device__ __forceinline__ void ldsm_x4(uint32_t* r, uint32_t addr) {
    asm volatile("ldmatrix.sync.aligned.m8n8.x4.shared.b16 {%0,%1,%2,%3}, [%4];"
                 : "=r"(r[0]), "=r"(r[1]), "=r"(r[2]), "=r"(r[3]) : "r"(addr));
}

__device__ __forceinline__ void ldsm_x4t(uint32_t* r, uint32_t addr) {
    asm volatile("ldmatrix.sync.aligned.m8n8.x4.trans.shared.b16 {%0,%1,%2,%3}, [%4];"
                 : "=r"(r[0]), "=r"(r[1]), "=r"(r[2]), "=r"(r[3]) : "r"(addr));
}

// fp16 inputs, fp32 accumulate
__device__ __forceinline__ void mma16816(float* c, const uint32_t* a,
                                         const uint32_t* b) {
    asm volatile(
        "mma.sync.aligned.m16n8k16.row.col.f32.f16.f16.f32 "
        "{%0,%1,%2,%3}, {%4,%5,%6,%7}, {%8,%9}, {%0,%1,%2,%3};"
        : "+f"(c[0]), "+f"(c[1]), "+f"(c[2]), "+f"(c[3])
        : "r"(a[0]), "r"(a[1]), "r"(a[2]), "r"(a[3]), "r"(b[0]), "r"(b[1]));
}

__device__ __forceinline__ float ex2f(float x) {
    float r;
    asm("ex2.approx.ftz.f32 %0, %1;" : "=f"(r) : "f"(x));
    return r;
}

// fp16 hi/lo split: hi = rn_fp16(x) (error 2^-12), lo = rn_fp16(x - hi)
// -> pair represents x to ~2^-23.
__device__ __forceinline__ void split2h(float x, float y,
                                        uint32_t& hi, uint32_t& lo) {
    asm("cvt.rn.f16x2.f32 %0, %1, %2;" : "=r"(hi) : "f"(y), "f"(x));
    __half2 h2 = *reinterpret_cast<__half2*>(&hi);
    float rx = x - __half2float(__low2half(h2));
    float ry = y - __half2float(__high2half(h2));
    asm("cvt.rn.f16x2.f32 %0, %1, %2;" : "=r"(lo) : "f"(ry), "f"(rx));
}

__device__ __forceinline__ uint32_t pack_h2(float x, float y) {
    uint32_t h;
    asm("cvt.rn.f16x2.f32 %0, %1, %2;" : "=r"(h) : "f"(y), "f"(x));
    return h;
}

// ---------------------------------------------------------------------------
// Split kernels. Launch order matters for ncu capture (launch #3 = attn).
// ---------------------------------------------------------------------------
// All 4 weight matrices -> fp16 hi only, one launch. grid 4096, n4/mat=262144
__global__ __launch_bounds__(256) void split_w(
    const float* __restrict__ W0, const float* __restrict__ W1,
    const float* __restrict__ W2, const float* __restrict__ W3,
    __half* __restrict__ out)
{
    int mat = blockIdx.x >> 10;
    int i = (blockIdx.x & 1023) * 256 + threadIdx.x;
    const float* src = (mat == 0) ? W0 : (mat == 1) ? W1 : (mat == 2) ? W2 : W3;
    float4 v = reinterpret_cast<const float4*>(src)[i];
    uint32_t* dst = reinterpret_cast<uint32_t*>(out + (size_t)mat * DD * DD);
    dst[2 * i]     = pack_h2(v.x, v.y);
    dst[2 * i + 1] = pack_h2(v.z, v.w);
}

// x -> fp16 hi/lo. grid 8192.
__global__ __launch_bounds__(256) void split_x(
    const float* __restrict__ src,
    __half* __restrict__ hi, __half* __restrict__ lo)
{
    int i = blockIdx.x * 256 + threadIdx.x;
    float4 v = reinterpret_cast<const float4*>(src)[i];
    uint32_t h0, l0, h1, l1;
    split2h(v.x, v.y, h0, l0);
    split2h(v.z, v.w, h1, l1);
    reinterpret_cast<uint32_t*>(hi)[2 * i]     = h0;
    reinterpret_cast<uint32_t*>(hi)[2 * i + 1] = h1;
    reinterpret_cast<uint32_t*>(lo)[2 * i]     = l0;
    reinterpret_cast<uint32_t*>(lo)[2 * i + 1] = l1;
}

// ---------------------------------------------------------------------------
// fp16 2-chain GEMM (NT), fused over up to 3 weight matrices:
//   C[m,n] = ((Ah+Al)[m,:] . Wh[n,:] + bias[n]) * scale
// CTA 128x128, BK=64, 512 threads (16 warps, 4x4), warp tile 32x32,
// 3-stage cp.async. Error ~2^-12 (W fp16 rounding only).
// ---------------------------------------------------------------------------
#define G_STAGE 49152   // Ah 16K | Al 16K | Wh 16K
#define G_SMEM  (3 * G_STAGE)

template<bool F32OUT>
__global__ __launch_bounds__(512, 1) void hgemm(
    const __half* __restrict__ Ah, const __half* __restrict__ Al,
    const __half* __restrict__ Wh,
    const float* __restrict__ B0, const float* __restrict__ B1,
    const float* __restrict__ B2,
    __half* __restrict__ O0h, __half* __restrict__ O0l,
    __half* __restrict__ O1h, __half* __restrict__ O1l,
    __half* __restrict__ O2h, __half* __restrict__ O2l,
    float* __restrict__ Cf)
{
    extern __shared__ __align__(1024) char smem[];
    uint32_t sb = smem_u32(smem);
    const int tid = threadIdx.x;
    const int w = tid >> 5, lane = tid & 31;
    const int wr = w >> 2, wc = w & 3;          // 4x4 warp grid, 32x32 tiles
    const int mat = blockIdx.x >> 3;
    const int n0  = (blockIdx.x & 7) * 128;
    const int m0  = blockIdx.y * 128;
    const __half* Wmh = Wh + (size_t)mat * DD * DD;

    float acc[2][4][4];
    #pragma unroll
    for (int mt = 0; mt < 2; mt++)
        #pragma unroll
        for (int nt = 0; nt < 4; nt++)
            #pragma unroll
            for (int i = 0; i < 4; i++) acc[mt][nt][i] = 0.f;

    auto load_stage = [&](int t, int s) {
        uint32_t base = sb + s * G_STAGE;
        const char* srcs[3] = {
            (const char*)Ah  + (size_t)m0 * 2048 + t * 128,
            (const char*)Al  + (size_t)m0 * 2048 + t * 128,
            (const char*)Wmh + (size_t)n0 * 2048 + t * 128};
        #pragma unroll
        for (int mtx = 0; mtx < 3; mtx++) {
            #pragma unroll
            for (int i = 0; i < 2; i++) {
                int idx = tid + i * 512;       // 0..1023 (row*8 + chunk)
                int row = idx >> 3, c = idx & 7;
                cp16(base + mtx * 16384u + sw128((uint32_t)idx * 16),
                     srcs[mtx] + (size_t)row * 2048 + c * 16);
            }
        }
        asm volatile("cp.async.commit_group;" ::: "memory");
    };

    const int NT = DD / 64;  // 16
    load_stage(0, 0);
    load_stage(1, 1);

    for (int t = 0; t < NT; t++) {
        if (t < NT - 1)
            asm volatile("cp.async.wait_group 1;" ::: "memory");
        else
            asm volatile("cp.async.wait_group 0;" ::: "memory");
        __syncthreads();
        if (t + 2 < NT) load_stage(t + 2, (t + 2) % 3);
        uint32_t base = sb + (t % 3) * G_STAGE;

        #pragma unroll
        for (int k16 = 0; k16 < 4; k16++) {
            uint32_t af_h[2][4], af_l[2][4];
            #pragma unroll
            for (int mt = 0; mt < 2; mt++) {
                int row = wr * 32 + mt * 16 + (lane & 15);
                uint32_t off = sw128((uint32_t)row * 128 +
                                     (k16 * 2 + (lane >> 4)) * 16);
                ldsm_x4(af_h[mt], base + off);
                ldsm_x4(af_l[mt], base + 16384u + off);
            }
            uint32_t bf[4][2];
            #pragma unroll
            for (int nh = 0; nh < 2; nh++) {
                int row = wc * 32 + nh * 16 + (lane & 15);
                uint32_t off = sw128((uint32_t)row * 128 +
                                     (k16 * 2 + (lane >> 4)) * 16);
                uint32_t r[4];
                ldsm_x4(r, base + 32768u + off);
                bf[nh * 2][0] = r[0]; bf[nh * 2 + 1][0] = r[1];
                bf[nh * 2][1] = r[2]; bf[nh * 2 + 1][1] = r[3];
            }
            #pragma unroll
            for (int mt = 0; mt < 2; mt++)
                #pragma unroll
                for (int nt = 0; nt < 4; nt++) {
                    mma16816(acc[mt][nt], af_h[mt], bf[nt]);
                    mma16816(acc[mt][nt], af_l[mt], bf[nt]);
                }
        }
    }

    // Epilogue
    const float* bias = (mat == 0) ? B0 : (mat == 1 ? B1 : B2);
    __half* Oh = (mat == 0) ? O0h : (mat == 1 ? O1h : O2h);
    __half* Ol = (mat == 0) ? O0l : (mat == 1 ? O1l : O2l);
    const float scl = (!F32OUT && mat == 0) ? SCALE_Q : 1.0f;
    const int r = lane >> 2, cp2 = (lane & 3) * 2;
    #pragma unroll
    for (int mt = 0; mt < 2; mt++) {
        #pragma unroll
        for (int nt = 0; nt < 4; nt++) {
            int row = m0 + wr * 32 + mt * 16 + r;
            int col = n0 + wc * 32 + nt * 8 + cp2;
            float b0 = bias[col], b1 = bias[col + 1];
            float v00 = (acc[mt][nt][0] + b0) * scl;
            float v01 = (acc[mt][nt][1] + b1) * scl;
            float v10 = (acc[mt][nt][2] + b0) * scl;
            float v11 = (acc[mt][nt][3] + b1) * scl;
            if (F32OUT) {
                *reinterpret_cast<float2*>(Cf + (size_t)row * DD + col) =
                    make_float2(v00, v01);
                *reinterpret_cast<float2*>(Cf + (size_t)(row + 8) * DD + col) =
                    make_float2(v10, v11);
            } else {
                uint32_t h, l;
                split2h(v00, v01, h, l);
                *reinterpret_cast<uint32_t*>(Oh + (size_t)row * DD + col) = h;
                *reinterpret_cast<uint32_t*>(Ol + (size_t)row * DD + col) = l;
                split2h(v10, v11, h, l);
                *reinterpret_cast<uint32_t*>(Oh + (size_t)(row + 8) * DD + col) = h;
                *reinterpret_cast<uint32_t*>(Ol + (size_t)(row + 8) * DD + col) = l;
            }
        }
    }
}

// ---------------------------------------------------------------------------
// Flash attention on mma.sync fp16x3, log2-domain softmax (Q pre-scaled).
// 256 threads, BM=128, BN=64, 3-stage KV pipeline.
// ---------------------------------------------------------------------------
#define A_STAGE 32768   // Kh 8K | Kl 8K | Vh 8K | Vl 8K
#define A_SMEM  (3 * A_STAGE)

__global__ __launch_bounds__(256, 1) void attn_mma(
    const __half* __restrict__ Qh, const __half* __restrict__ Ql,
    const __half* __restrict__ Kh, const __half* __restrict__ Kl,
    const __half* __restrict__ Vh, const __half* __restrict__ Vl,
    __half* __restrict__ Ch, __half* __restrict__ Cl)
{
    extern __shared__ __align__(1024) char smem[];
    uint32_t sb = smem_u32(smem);
    const int tid = threadIdx.x;
    const int w = tid >> 5, lane = tid & 31;
    const int q0 = blockIdx.x * 128;
    const int hd = blockIdx.y;
    const int b  = blockIdx.z;

    const size_t qbase = ((size_t)b * SS + q0) * DD + hd * 64;
    const size_t kbase = (size_t)b * SS * DD + hd * 64;

    auto load_kv = [&](int it, int s) {
        uint32_t base = sb + s * A_STAGE;
        const char* g[4] = {
            (const char*)Kh + (kbase + (size_t)it * 64 * DD) * 2,
            (const char*)Kl + (kbase + (size_t)it * 64 * DD) * 2,
            (const char*)Vh + (kbase + (size_t)it * 64 * DD) * 2,
            (const char*)Vl + (kbase + (size_t)it * 64 * DD) * 2};
        #pragma unroll
        for (int mtx = 0; mtx < 4; mtx++) {
            #pragma unroll
            for (int i = 0; i < 2; i++) {
                int idx = tid + i * 256;       // 0..511
                int row = idx >> 3, c = idx & 7;
                cp16(base + mtx * 8192u + sw128((uint32_t)idx * 16),
                     g[mtx] + (size_t)row * 2048 + c * 16);
            }
        }
        asm volatile("cp.async.commit_group;" ::: "memory");
    };

    // ---- Prologue: Q into stage-2 area; KV stages 0,1 in flight ----
    {
        const char* gq_h = (const char*)Qh + qbase * 2;
        const char* gq_l = (const char*)Ql + qbase * 2;
        uint32_t qb = sb + 2 * A_STAGE;
        #pragma unroll
        for (int i = 0; i < 4; i++) {
            int idx = tid + i * 256;
            int row = idx >> 3, c = idx & 7;
            cp16(qb + sw128((uint32_t)idx * 16),
                 gq_h + (size_t)row * 2048 + c * 16);
            cp16(qb + 16384u + sw128((uint32_t)idx * 16),
                 gq_l + (size_t)row * 2048 + c * 16);
        }
        asm volatile("cp.async.commit_group;" ::: "memory");
    }
    load_kv(0, 0);
    load_kv(1, 1);
    asm volatile("cp.async.wait_group 2;" ::: "memory");  // Q landed
    __syncthreads();

    uint32_t qf_h[4][4], qf_l[4][4];
    {
        uint32_t qb = sb + 2 * A_STAGE;
        #pragma unroll
        for (int k16 = 0; k16 < 4; k16++) {
            int row = w * 16 + (lane & 15);
            uint32_t off = sw128((uint32_t)row * 128 +
                                 (k16 * 2 + (lane >> 4)) * 16);
            ldsm_x4(qf_h[k16], qb + off);
            ldsm_x4(qf_l[k16], qb + 16384u + off);
        }
    }
    __syncthreads();   // Q area may now be reused as KV stage 2

    float o[8][4];
    #pragma unroll
    for (int dt = 0; dt < 8; dt++)
        #pragma unroll
        for (int i = 0; i < 4; i++) o[dt][i] = 0.f;
    const float NEG_INF = __int_as_float(0xff800000);
    float mrow[2] = {NEG_INF, NEG_INF};
    float lrow[2] = {0.f, 0.f};

    const int NT = SS / 64;  // 32
    for (int it = 0; it < NT; it++) {
        if (it < NT - 1)
            asm volatile("cp.async.wait_group 1;" ::: "memory");
        else
            asm volatile("cp.async.wait_group 0;" ::: "memory");
        __syncthreads();
        if (it + 2 < NT) load_kv(it + 2, (it + 2) % 3);
        uint32_t base = sb + (it % 3) * A_STAGE;

        // ---- S = Q K^T (fp16x3, already in log2 units via Q scale) ----
        float s[8][4];
        #pragma unroll
        for (int nt = 0; nt < 8; nt++)
            #pragma unroll
            for (int i = 0; i < 4; i++) s[nt][i] = 0.f;

        #pragma unroll
        for (int k16 = 0; k16 < 4; k16++) {
            uint32_t kf_h[8][2], kf_l[8][2];
            #pragma unroll
            for (int nh = 0; nh < 4; nh++) {
                int row = nh * 16 + (lane & 15);
                uint32_t off = sw128((uint32_t)row * 128 +
                                     (k16 * 2 + (lane >> 4)) * 16);
                uint32_t r[4];
                ldsm_x4(r, base + off);
                kf_h[nh * 2][0] = r[0]; kf_h[nh * 2 + 1][0] = r[1];
                kf_h[nh * 2][1] = r[2]; kf_h[nh * 2 + 1][1] = r[3];
                ldsm_x4(r, base + 8192u + off);
                kf_l[nh * 2][0] = r[0]; kf_l[nh * 2 + 1][0] = r[1];
                kf_l[nh * 2][1] = r[2]; kf_l[nh * 2 + 1][1] = r[3];
            }
            #pragma unroll
            for (int nt = 0; nt < 8; nt++) {
                mma16816(s[nt], qf_h[k16], kf_h[nt]);
                mma16816(s[nt], qf_h[k16], kf_l[nt]);
                mma16816(s[nt], qf_l[k16], kf_h[nt]);
            }
        }

        // ---- online softmax in log2 domain ----
        #pragma unroll
        for (int hf = 0; hf < 2; hf++) {
            float mx = NEG_INF;
            #pragma unroll
            for (int nt = 0; nt < 8; nt++)
                mx = fmaxf(mx, fmaxf(s[nt][2 * hf], s[nt][2 * hf + 1]));
            mx = fmaxf(mx, __shfl_xor_sync(0xffffffffu, mx, 1));
            mx = fmaxf(mx, __shfl_xor_sync(0xffffffffu, mx, 2));
            float mn = fmaxf(mrow[hf], mx);
            uint32_t keep = __all_sync(0xffffffffu, mn == mrow[hf]);
            float rs = 0.f;
            #pragma unroll
            for (int nt = 0; nt < 8; nt++) {
                float p0 = ex2f(s[nt][2 * hf] - mn);
                float p1 = ex2f(s[nt][2 * hf + 1] - mn);
                s[nt][2 * hf] = p0; s[nt][2 * hf + 1] = p1;
                rs += p0 + p1;
            }
            rs += __shfl_xor_sync(0xffffffffu, rs, 1);
            rs += __shfl_xor_sync(0xffffffffu, rs, 2);
            if (keep) {
                lrow[hf] += rs;
            } else {
                float scale = ex2f(mrow[hf] - mn);
                lrow[hf] = lrow[hf] * scale + rs;
                mrow[hf] = mn;
                #pragma unroll
                for (int dt = 0; dt < 8; dt++) {
                    o[dt][2 * hf]     *= scale;
                    o[dt][2 * hf + 1] *= scale;
                }
            }
        }

        // ---- O += P V (fp16x3, P a-frags built in-register) ----
        #pragma unroll
        for (int t = 0; t < 4; t++) {
            uint32_t pa_h[4], pa_l[4];
            split2h(s[2 * t][0],     s[2 * t][1],     pa_h[0], pa_l[0]);
            split2h(s[2 * t][2],     s[2 * t][3],     pa_h[1], pa_l[1]);
            split2h(s[2 * t + 1][0], s[2 * t + 1][1], pa_h[2], pa_l[2]);
            split2h(s[2 * t + 1][2], s[2 * t + 1][3], pa_h[3], pa_l[3]);

            uint32_t vf_h[8][2], vf_l[8][2];
            #pragma unroll
            for (int dp = 0; dp < 4; dp++) {
                int row = t * 16 + (lane & 15);
                uint32_t off = sw128((uint32_t)row * 128 +
                                     (dp * 2 + (lane >> 4)) * 16);
                uint32_t r[4];
                ldsm_x4t(r, base + 16384u + off);
                vf_h[dp * 2][0] = r[0]; vf_h[dp * 2][1] = r[1];
                vf_h[dp * 2 + 1][0] = r[2]; vf_h[dp * 2 + 1][1] = r[3];
                ldsm_x4t(r, base + 24576u + off);
                vf_l[dp * 2][0] = r[0]; vf_l[dp * 2][1] = r[1];
                vf_l[dp * 2 + 1][0] = r[2]; vf_l[dp * 2 + 1][1] = r[3];
            }
            #pragma unroll
            for (int dt = 0; dt < 8; dt++) {
                mma16816(o[dt], pa_h, vf_h[dt]);
                mma16816(o[dt], pa_h, vf_l[dt]);
                mma16816(o[dt], pa_l, vf_h[dt]);
            }
        }
    }

    // ---- epilogue: ctx = O / l, written as fp16 hi/lo ----
    const int r = lane >> 2, cp2 = (lane & 3) * 2;
    #pragma unroll
    for (int hf = 0; hf < 2; hf++) {
        float inv = 1.f / lrow[hf];
        int row = q0 + w * 16 + r + hf * 8;
        size_t ob = ((size_t)b * SS + row) * DD + hd * 64;
        #pragma unroll
        for (int dt = 0; dt < 8; dt++) {
            float v0 = o[dt][2 * hf] * inv;
            float v1 = o[dt][2 * hf + 1] * inv;
            uint32_t h, l;
            split2h(v0, v1, h, l);
            *reinterpret_cast<uint32_t*>(Ch + ob + dt * 8 + cp2) = h;
            *reinterpret_cast<uint32_t*>(Cl + ob + dt * 8 + cp2) = l;
        }
    }
}

// ---------------------------------------------------------------------------
// Launch (order chosen so ncu's captured launch #3 = attn_mma)
// ---------------------------------------------------------------------------
extern "C" void kernel_launch(void* const* d_in, const int* in_sizes, int n_in,
                              void* d_out, int out_size)
{
    const float* x  = (const float*)d_in[0];
    const float* Wq = (const float*)d_in[1];
    const float* bq = (const float*)d_in[2];
    const float* Wk = (const float*)d_in[3];
    const float* bk = (const float*)d_in[4];
    const float* Wv = (const float*)d_in[5];
    const float* bv = (const float*)d_in[6];
    const float* Wo = (const float*)d_in[7];
    const float* bo = (const float*)d_in[8];
    float* out = (float*)d_out;

    __half *xh, *xl, *qh, *ql, *kh, *kl, *vh, *vl, *ch, *cl, *wh;
    cudaGetSymbolAddress((void**)&xh, g_xh);
    cudaGetSymbolAddress((void**)&xl, g_xl);
    cudaGetSymbolAddress((void**)&qh, g_qh);
    cudaGetSymbolAddress((void**)&ql, g_ql);
    cudaGetSymbolAddress((void**)&kh, g_kh);
    cudaGetSymbolAddress((void**)&kl, g_kl);
    cudaGetSymbolAddress((void**)&vh, g_vh);
    cudaGetSymbolAddress((void**)&vl, g_vl);
    cudaGetSymbolAddress((void**)&ch, g_ch);
    cudaGetSymbolAddress((void**)&cl, g_cl);
    cudaGetSymbolAddress((void**)&wh, g_wh);

    cudaFuncSetAttribute(hgemm<false>,
                         cudaFuncAttributeMaxDynamicSharedMemorySize, G_SMEM);
    cudaFuncSetAttribute(hgemm<true>,
                         cudaFuncAttributeMaxDynamicSharedMemorySize, G_SMEM);
    cudaFuncSetAttribute(attn_mma,
                         cudaFuncAttributeMaxDynamicSharedMemorySize, A_SMEM);

    // launch 0: all weights -> fp16 hi
    split_w<<<4096, 256>>>(Wq, Wk, Wv, Wo, wh);
    // launch 1: x -> fp16 hi/lo
    split_x<<<MM * DD / 1024, 256>>>(x, xh, xl);

    // launch 2: fused QKV projection (mat 0 = Q gets softmax scale folded in)
    dim3 gqkv(24, 64);
    hgemm<false><<<gqkv, 512, G_SMEM>>>(
        xh, xl, wh, bq, bk, bv,
        qh, ql, kh, kl, vh, vl, nullptr);

    // launch 3: attention  (ncu capture slot)
    dim3 ag(SS / 128, HH, BB);    // (16, 16, 4)
    attn_mma<<<ag, 256, A_SMEM>>>(qh, ql, kh, kl, vh, vl, ch, cl);

    // launch 4: output projection (fp32 out)
    dim3 go(8, 64);
    hgemm<true><<<go, 512, G_SMEM>>>(
        ch, cl, wh + 3 * (size_t)DD * DD, bo, nullptr, nullptr,
        nullptr, nullptr, nullptr, nullptr, nullptr, nullptr, out);
}

// round 6
// speedup vs baseline: 4.8740x; 1.3753x over previous
#include <cuda_runtime.h>
#include <cuda_fp16.h>
#include <math.h>
#include <stdint.h>

// Problem constants
#define BB 4
#define SS 2048
#define DD 1024
#define HH 16
#define DK 64
#define MM (BB * SS)   // 8192 rows

// 0.125 (1/sqrt(DK)) * log2(e): folded into Q so softmax runs in log2 domain
#define SCALE_Q 0.1803368801111204f

// ---------------------------------------------------------------------------
// Scratch (static device globals: allocation-free per harness rules)
// ---------------------------------------------------------------------------
__device__ __align__(16) __half g_xh[MM * DD];
__device__ __align__(16) __half g_xl[MM * DD];
__device__ __align__(16) __half g_qh[MM * DD];
__device__ __align__(16) __half g_kh[MM * DD];
__device__ __align__(16) __half g_vh[MM * DD];
__device__ __align__(16) __half g_ch[MM * DD];
__device__ __align__(16) __half g_cl[MM * DD];
__device__ __align__(16) __half g_wh[4 * DD * DD];   // weights: fp16 hi only

// ---------------------------------------------------------------------------
// Low-level helpers (base ISA only: ldmatrix + mma.sync + cp.async)
// ---------------------------------------------------------------------------
__device__ __forceinline__ uint32_t smem_u32(const void* p) {
    uint32_t a;
    asm("{ .reg .u64 t; cvta.to.shared.u64 t, %1; cvt.u32.u64 %0, t; }"
        : "=r"(a) : "l"(p));
    return a;
}

__device__ __forceinline__ uint32_t sw128(uint32_t off) {
    return off ^ ((off >> 3) & 0x70);
}

__device__ __forceinline__ void cp16(uint32_t dst, const void* src) {
    asm volatile("cp.async.cg.shared.global [%0], [%1], 16;"
                 :: "r"(dst), "l"(src) : "memory");
}

__device__ __forceinline__ void ldsm_x4(uint32_t* r, uint32_t addr) {
    asm volatile("ldmatrix.sync.aligned.m8n8.x4.shared.b16 {%0,%1,%2,%3}, [%4];"
                 : "=r"(r[0]), "=r"(r[1]), "=r"(r[2]), "=r"(r[3]) : "r"(addr));
}

__device__ __forceinline__ void ldsm_x4t(uint32_t* r, uint32_t addr) {
    asm volatile("ldmatrix.sync.aligned.m8n8.x4.trans.shared.b16 {%0,%1,%2,%3}, [%4];"
                 : "=r"(r[0]), "=r"(r[1]), "=r"(r[2]), "=r"(r[3]) : "r"(addr));
}

// fp16 inputs, fp32 accumulate
__device__ __forceinline__ void mma16816(float* c, const uint32_t* a,
                                         const uint32_t* b) {
    asm volatile(
        "mma.sync.aligned.m16n8k16.row.col.f32.f16.f16.f32 "
        "{%0,%1,%2,%3}, {%4,%5,%6,%7}, {%8,%9}, {%0,%1,%2,%3};"
        : "+f"(c[0]), "+f"(c[1]), "+f"(c[2]), "+f"(c[3])
        : "r"(a[0]), "r"(a[1]), "r"(a[2]), "r"(a[3]), "r"(b[0]), "r"(b[1]));
}

__device__ __forceinline__ float ex2f(float x) {
    float r;
    asm("ex2.approx.ftz.f32 %0, %1;" : "=f"(r) : "f"(x));
    return r;
}

// fp16 hi/lo split: hi = rn_fp16(x) (error 2^-12), lo = rn_fp16(x - hi)
__device__ __forceinline__ void split2h(float x, float y,
                                        uint32_t& hi, uint32_t& lo) {
    asm("cvt.rn.f16x2.f32 %0, %1, %2;" : "=r"(hi) : "f"(y), "f"(x));
    __half2 h2 = *reinterpret_cast<__half2*>(&hi);
    float rx = x - __half2float(__low2half(h2));
    float ry = y - __half2float(__high2half(h2));
    asm("cvt.rn.f16x2.f32 %0, %1, %2;" : "=r"(lo) : "f"(ry), "f"(rx));
}

__device__ __forceinline__ uint32_t pack_h2(float x, float y) {
    uint32_t h;
    asm("cvt.rn.f16x2.f32 %0, %1, %2;" : "=r"(h) : "f"(y), "f"(x));
    return h;
}

// ---------------------------------------------------------------------------
// Split kernels. Launch order matters for ncu capture (launch #3 = attn).
// ---------------------------------------------------------------------------
__global__ __launch_bounds__(256) void split_w(
    const float* __restrict__ W0, const float* __restrict__ W1,
    const float* __restrict__ W2, const float* __restrict__ W3,
    __half* __restrict__ out)
{
    int mat = blockIdx.x >> 10;
    int i = (blockIdx.x & 1023) * 256 + threadIdx.x;
    const float* src = (mat == 0) ? W0 : (mat == 1) ? W1 : (mat == 2) ? W2 : W3;
    float4 v = reinterpret_cast<const float4*>(src)[i];
    uint32_t* dst = reinterpret_cast<uint32_t*>(out + (size_t)mat * DD * DD);
    dst[2 * i]     = pack_h2(v.x, v.y);
    dst[2 * i + 1] = pack_h2(v.z, v.w);
}

__global__ __launch_bounds__(256) void split_x(
    const float* __restrict__ src,
    __half* __restrict__ hi, __half* __restrict__ lo)
{
    int i = blockIdx.x * 256 + threadIdx.x;
    float4 v = reinterpret_cast<const float4*>(src)[i];
    uint32_t h0, l0, h1, l1;
    split2h(v.x, v.y, h0, l0);
    split2h(v.z, v.w, h1, l1);
    reinterpret_cast<uint32_t*>(hi)[2 * i]     = h0;
    reinterpret_cast<uint32_t*>(hi)[2 * i + 1] = h1;
    reinterpret_cast<uint32_t*>(lo)[2 * i]     = l0;
    reinterpret_cast<uint32_t*>(lo)[2 * i + 1] = l1;
}

// ---------------------------------------------------------------------------
// fp16 2-chain GEMM (NT), fused over up to 3 weight matrices:
//   C[m,n] = ((Ah+Al)[m,:] . Wh[n,:] + bias[n]) * scale
// CTA 128x128, BK=64, 512 threads (16 warps, 4x4), warp tile 32x32,
// 3-stage cp.async. F32OUT=false: fp16 hi output only (QKV).
// ---------------------------------------------------------------------------
#define G_STAGE 49152   // Ah 16K | Al 16K | Wh 16K
#define G_SMEM  (3 * G_STAGE)

template<bool F32OUT>
__global__ __launch_bounds__(512, 1) void hgemm(
    const __half* __restrict__ Ah, const __half* __restrict__ Al,
    const __half* __restrict__ Wh,
    const float* __restrict__ B0, const float* __restrict__ B1,
    const float* __restrict__ B2,
    __half* __restrict__ O0h, __half* __restrict__ O1h,
    __half* __restrict__ O2h,
    float* __restrict__ Cf)
{
    extern __shared__ __align__(1024) char smem[];
    uint32_t sb = smem_u32(smem);
    const int tid = threadIdx.x;
    const int w = tid >> 5, lane = tid & 31;
    const int wr = w >> 2, wc = w & 3;          // 4x4 warp grid, 32x32 tiles
    const int mat = blockIdx.x >> 3;
    const int n0  = (blockIdx.x & 7) * 128;
    const int m0  = blockIdx.y * 128;
    const __half* Wmh = Wh + (size_t)mat * DD * DD;

    float acc[2][4][4];
    #pragma unroll
    for (int mt = 0; mt < 2; mt++)
        #pragma unroll
        for (int nt = 0; nt < 4; nt++)
            #pragma unroll
            for (int i = 0; i < 4; i++) acc[mt][nt][i] = 0.f;

    auto load_stage = [&](int t, int s) {
        uint32_t base = sb + s * G_STAGE;
        const char* srcs[3] = {
            (const char*)Ah  + (size_t)m0 * 2048 + t * 128,
            (const char*)Al  + (size_t)m0 * 2048 + t * 128,
            (const char*)Wmh + (size_t)n0 * 2048 + t * 128};
        #pragma unroll
        for (int mtx = 0; mtx < 3; mtx++) {
            #pragma unroll
            for (int i = 0; i < 2; i++) {
                int idx = tid + i * 512;       // 0..1023 (row*8 + chunk)
                int row = idx >> 3, c = idx & 7;
                cp16(base + mtx * 16384u + sw128((uint32_t)idx * 16),
                     srcs[mtx] + (size_t)row * 2048 + c * 16);
            }
        }
        asm volatile("cp.async.commit_group;" ::: "memory");
    };

    const int NT = DD / 64;  // 16
    load_stage(0, 0);
    load_stage(1, 1);

    for (int t = 0; t < NT; t++) {
        if (t < NT - 1)
            asm volatile("cp.async.wait_group 1;" ::: "memory");
        else
            asm volatile("cp.async.wait_group 0;" ::: "memory");
        __syncthreads();
        if (t + 2 < NT) load_stage(t + 2, (t + 2) % 3);
        uint32_t base = sb + (t % 3) * G_STAGE;

        #pragma unroll
        for (int k16 = 0; k16 < 4; k16++) {
            uint32_t af_h[2][4], af_l[2][4];
            #pragma unroll
            for (int mt = 0; mt < 2; mt++) {
                int row = wr * 32 + mt * 16 + (lane & 15);
                uint32_t off = sw128((uint32_t)row * 128 +
                                     (k16 * 2 + (lane >> 4)) * 16);
                ldsm_x4(af_h[mt], base + off);
                ldsm_x4(af_l[mt], base + 16384u + off);
            }
            uint32_t bf[4][2];
            #pragma unroll
            for (int nh = 0; nh < 2; nh++) {
                int row = wc * 32 + nh * 16 + (lane & 15);
                uint32_t off = sw128((uint32_t)row * 128 +
                                     (k16 * 2 + (lane >> 4)) * 16);
                uint32_t r[4];
                ldsm_x4(r, base + 32768u + off);
                bf[nh * 2][0] = r[0]; bf[nh * 2 + 1][0] = r[1];
                bf[nh * 2][1] = r[2]; bf[nh * 2 + 1][1] = r[3];
            }
            #pragma unroll
            for (int mt = 0; mt < 2; mt++)
                #pragma unroll
                for (int nt = 0; nt < 4; nt++) {
                    mma16816(acc[mt][nt], af_h[mt], bf[nt]);
                    mma16816(acc[mt][nt], af_l[mt], bf[nt]);
                }
        }
    }

    // Epilogue
    const float* bias = (mat == 0) ? B0 : (mat == 1 ? B1 : B2);
    __half* Oh = (mat == 0) ? O0h : (mat == 1 ? O1h : O2h);
    const float scl = (!F32OUT && mat == 0) ? SCALE_Q : 1.0f;
    const int r = lane >> 2, cp2 = (lane & 3) * 2;
    #pragma unroll
    for (int mt = 0; mt < 2; mt++) {
        #pragma unroll
        for (int nt = 0; nt < 4; nt++) {
            int row = m0 + wr * 32 + mt * 16 + r;
            int col = n0 + wc * 32 + nt * 8 + cp2;
            float b0 = bias[col], b1 = bias[col + 1];
            float v00 = (acc[mt][nt][0] + b0) * scl;
            float v01 = (acc[mt][nt][1] + b1) * scl;
            float v10 = (acc[mt][nt][2] + b0) * scl;
            float v11 = (acc[mt][nt][3] + b1) * scl;
            if (F32OUT) {
                *reinterpret_cast<float2*>(Cf + (size_t)row * DD + col) =
                    make_float2(v00, v01);
                *reinterpret_cast<float2*>(Cf + (size_t)(row + 8) * DD + col) =
                    make_float2(v10, v11);
            } else {
                *reinterpret_cast<uint32_t*>(Oh + (size_t)row * DD + col) =
                    pack_h2(v00, v01);
                *reinterpret_cast<uint32_t*>(Oh + (size_t)(row + 8) * DD + col) =
                    pack_h2(v10, v11);
            }
        }
    }
}

// ---------------------------------------------------------------------------
// Flash attention, single-chain fp16 (S = Qh Kh^T, O += Ph Vh).
// Attention dots are K=64 deep with 0.125 scale -> fp16 rounding adds only
// ~1e-4 relative error. 256 threads, BM=128, BN=64, 3-stage KV pipeline.
// ctx written as fp16 hi/lo (O-projection is K=1024 and needs the split).
// ---------------------------------------------------------------------------
#define A_STAGE 16384   // Kh 8K | Vh 8K
#define A_SMEM  (3 * A_STAGE)

__global__ __launch_bounds__(256, 1) void attn_mma(
    const __half* __restrict__ Qh,
    const __half* __restrict__ Kh,
    const __half* __restrict__ Vh,
    __half* __restrict__ Ch, __half* __restrict__ Cl)
{
    extern __shared__ __align__(1024) char smem[];
    uint32_t sb = smem_u32(smem);
    const int tid = threadIdx.x;
    const int w = tid >> 5, lane = tid & 31;
    const int q0 = blockIdx.x * 128;
    const int hd = blockIdx.y;
    const int b  = blockIdx.z;

    const size_t qbase = ((size_t)b * SS + q0) * DD + hd * 64;
    const size_t kbase = (size_t)b * SS * DD + hd * 64;

    auto load_kv = [&](int it, int s) {
        uint32_t base = sb + s * A_STAGE;
        const char* gk = (const char*)Kh + (kbase + (size_t)it * 64 * DD) * 2;
        const char* gv = (const char*)Vh + (kbase + (size_t)it * 64 * DD) * 2;
        #pragma unroll
        for (int i = 0; i < 2; i++) {
            int idx = tid + i * 256;       // 0..511
            int row = idx >> 3, c = idx & 7;
            cp16(base + sw128((uint32_t)idx * 16),
                 gk + (size_t)row * 2048 + c * 16);
            cp16(base + 8192u + sw128((uint32_t)idx * 16),
                 gv + (size_t)row * 2048 + c * 16);
        }
        asm volatile("cp.async.commit_group;" ::: "memory");
    };

    // ---- Prologue: Q (hi only, 16K) into stage-2 area; KV 0,1 in flight ----
    {
        const char* gq = (const char*)Qh + qbase * 2;
        uint32_t qb = sb + 2 * A_STAGE;
        #pragma unroll
        for (int i = 0; i < 4; i++) {
            int idx = tid + i * 256;       // 0..1023
            int row = idx >> 3, c = idx & 7;
            cp16(qb + sw128((uint32_t)idx * 16),
                 gq + (size_t)row * 2048 + c * 16);
        }
        asm volatile("cp.async.commit_group;" ::: "memory");
    }
    load_kv(0, 0);
    load_kv(1, 1);
    asm volatile("cp.async.wait_group 2;" ::: "memory");  // Q landed
    __syncthreads();

    uint32_t qf[4][4];
    {
        uint32_t qb = sb + 2 * A_STAGE;
        #pragma unroll
        for (int k16 = 0; k16 < 4; k16++) {
            int row = w * 16 + (lane & 15);
            uint32_t off = sw128((uint32_t)row * 128 +
                                 (k16 * 2 + (lane >> 4)) * 16);
            ldsm_x4(qf[k16], qb + off);
        }
    }
    __syncthreads();   // Q area may now be reused as KV stage 2

    float o[8][4];
    #pragma unroll
    for (int dt = 0; dt < 8; dt++)
        #pragma unroll
        for (int i = 0; i < 4; i++) o[dt][i] = 0.f;
    const float NEG_INF = __int_as_float(0xff800000);
    float mrow[2] = {NEG_INF, NEG_INF};
    float lrow[2] = {0.f, 0.f};

    const int NT = SS / 64;  // 32
    for (int it = 0; it < NT; it++) {
        if (it < NT - 1)
            asm volatile("cp.async.wait_group 1;" ::: "memory");
        else
            asm volatile("cp.async.wait_group 0;" ::: "memory");
        __syncthreads();
        if (it + 2 < NT) load_kv(it + 2, (it + 2) % 3);
        uint32_t base = sb + (it % 3) * A_STAGE;

        // ---- S = Q K^T (single chain; log2 units via folded Q scale) ----
        float s[8][4];
        #pragma unroll
        for (int nt = 0; nt < 8; nt++)
            #pragma unroll
            for (int i = 0; i < 4; i++) s[nt][i] = 0.f;

        #pragma unroll
        for (int k16 = 0; k16 < 4; k16++) {
            uint32_t kf[8][2];
            #pragma unroll
            for (int nh = 0; nh < 4; nh++) {
                int row = nh * 16 + (lane & 15);
                uint32_t off = sw128((uint32_t)row * 128 +
                                     (k16 * 2 + (lane >> 4)) * 16);
                uint32_t r[4];
                ldsm_x4(r, base + off);
                kf[nh * 2][0] = r[0]; kf[nh * 2 + 1][0] = r[1];
                kf[nh * 2][1] = r[2]; kf[nh * 2 + 1][1] = r[3];
            }
            #pragma unroll
            for (int nt = 0; nt < 8; nt++)
                mma16816(s[nt], qf[k16], kf[nt]);
        }

        // ---- online softmax in log2 domain ----
        #pragma unroll
        for (int hf = 0; hf < 2; hf++) {
            float mx = NEG_INF;
            #pragma unroll
            for (int nt = 0; nt < 8; nt++)
                mx = fmaxf(mx, fmaxf(s[nt][2 * hf], s[nt][2 * hf + 1]));
            mx = fmaxf(mx, __shfl_xor_sync(0xffffffffu, mx, 1));
            mx = fmaxf(mx, __shfl_xor_sync(0xffffffffu, mx, 2));
            float mn = fmaxf(mrow[hf], mx);
            uint32_t keep = __all_sync(0xffffffffu, mn == mrow[hf]);
            float rs = 0.f;
            #pragma unroll
            for (int nt = 0; nt < 8; nt++) {
                float p0 = ex2f(s[nt][2 * hf] - mn);
                float p1 = ex2f(s[nt][2 * hf + 1] - mn);
                s[nt][2 * hf] = p0; s[nt][2 * hf + 1] = p1;
                rs += p0 + p1;
            }
            rs += __shfl_xor_sync(0xffffffffu, rs, 1);
            rs += __shfl_xor_sync(0xffffffffu, rs, 2);
            if (keep) {
                lrow[hf] += rs;
            } else {
                float scale = ex2f(mrow[hf] - mn);
                lrow[hf] = lrow[hf] * scale + rs;
                mrow[hf] = mn;
                #pragma unroll
                for (int dt = 0; dt < 8; dt++) {
                    o[dt][2 * hf]     *= scale;
                    o[dt][2 * hf + 1] *= scale;
                }
            }
        }

        // ---- O += P V (single chain) ----
        #pragma unroll
        for (int t = 0; t < 4; t++) {
            uint32_t pa[4];
            pa[0] = pack_h2(s[2 * t][0],     s[2 * t][1]);
            pa[1] = pack_h2(s[2 * t][2],     s[2 * t][3]);
            pa[2] = pack_h2(s[2 * t + 1][0], s[2 * t + 1][1]);
            pa[3] = pack_h2(s[2 * t + 1][2], s[2 * t + 1][3]);

            uint32_t vf[8][2];
            #pragma unroll
            for (int dp = 0; dp < 4; dp++) {
                int row = t * 16 + (lane & 15);
                uint32_t off = sw128((uint32_t)row * 128 +
                                     (dp * 2 + (lane >> 4)) * 16);
                uint32_t r[4];
                ldsm_x4t(r, base + 8192u + off);
                vf[dp * 2][0] = r[0]; vf[dp * 2][1] = r[1];
                vf[dp * 2 + 1][0] = r[2]; vf[dp * 2 + 1][1] = r[3];
            }
            #pragma unroll
            for (int dt = 0; dt < 8; dt++)
                mma16816(o[dt], pa, vf[dt]);
        }
    }

    // ---- epilogue: ctx = O / l, written as fp16 hi/lo ----
    const int r = lane >> 2, cp2 = (lane & 3) * 2;
    #pragma unroll
    for (int hf = 0; hf < 2; hf++) {
        float inv = 1.f / lrow[hf];
        int row = q0 + w * 16 + r + hf * 8;
        size_t ob = ((size_t)b * SS + row) * DD + hd * 64;
        #pragma unroll
        for (int dt = 0; dt < 8; dt++) {
            float v0 = o[dt][2 * hf] * inv;
            float v1 = o[dt][2 * hf + 1] * inv;
            uint32_t h, l;
            split2h(v0, v1, h, l);
            *reinterpret_cast<uint32_t*>(Ch + ob + dt * 8 + cp2) = h;
            *reinterpret_cast<uint32_t*>(Cl + ob + dt * 8 + cp2) = l;
        }
    }
}

// ---------------------------------------------------------------------------
// Launch (order chosen so ncu's captured launch #3 = attn_mma)
// ---------------------------------------------------------------------------
extern "C" void kernel_launch(void* const* d_in, const int* in_sizes, int n_in,
                              void* d_out, int out_size)
{
    const float* x  = (const float*)d_in[0];
    const float* Wq = (const float*)d_in[1];
    const float* bq = (const float*)d_in[2];
    const float* Wk = (const float*)d_in[3];
    const float* bk = (const float*)d_in[4];
    const float* Wv = (const float*)d_in[5];
    const float* bv = (const float*)d_in[6];
    const float* Wo = (const float*)d_in[7];
    const float* bo = (const float*)d_in[8];
    float* out = (float*)d_out;

    __half *xh, *xl, *qh, *kh, *vh, *ch, *cl, *wh;
    cudaGetSymbolAddress((void**)&xh, g_xh);
    cudaGetSymbolAddress((void**)&xl, g_xl);
    cudaGetSymbolAddress((void**)&qh, g_qh);
    cudaGetSymbolAddress((void**)&kh, g_kh);
    cudaGetSymbolAddress((void**)&vh, g_vh);
    cudaGetSymbolAddress((void**)&ch, g_ch);
    cudaGetSymbolAddress((void**)&cl, g_cl);
    cudaGetSymbolAddress((void**)&wh, g_wh);

    cudaFuncSetAttribute(hgemm<false>,
                         cudaFuncAttributeMaxDynamicSharedMemorySize, G_SMEM);
    cudaFuncSetAttribute(hgemm<true>,
                         cudaFuncAttributeMaxDynamicSharedMemorySize, G_SMEM);
    cudaFuncSetAttribute(attn_mma,
                         cudaFuncAttributeMaxDynamicSharedMemorySize, A_SMEM);

    // launch 0: all weights -> fp16 hi
    split_w<<<4096, 256>>>(Wq, Wk, Wv, Wo, wh);
    // launch 1: x -> fp16 hi/lo
    split_x<<<MM * DD / 1024, 256>>>(x, xh, xl);

    // launch 2: fused QKV projection (mat 0 = Q gets softmax scale folded in)
    dim3 gqkv(24, 64);
    hgemm<false><<<gqkv, 512, G_SMEM>>>(
        xh, xl, wh, bq, bk, bv,
        qh, kh, vh, nullptr);

    // launch 3: attention  (ncu capture slot)
    dim3 ag(SS / 128, HH, BB);    // (16, 16, 4)
    attn_mma<<<ag, 256, A_SMEM>>>(qh, kh, vh, ch, cl);

    // launch 4: output projection (fp32 out)
    dim3 go(8, 64);
    hgemm<true><<<go, 512, G_SMEM>>>(
        ch, cl, wh + 3 * (size_t)DD * DD, bo, nullptr, nullptr,
        nullptr, nullptr, nullptr, out);
}

// round 7
// speedup vs baseline: 5.6045x; 1.1499x over previous
#include <cuda_runtime.h>
#include <cuda_fp16.h>
#include <math.h>
#include <stdint.h>

// Problem constants
#define BB 4
#define SS 2048
#define DD 1024
#define HH 16
#define DK 64
#define MM (BB * SS)   // 8192 rows

// 0.125 (1/sqrt(DK)) * log2(e): folded into Q so softmax runs in log2 domain
#define SCALE_Q 0.1803368801111204f

// ---------------------------------------------------------------------------
// Scratch (static device globals: allocation-free per harness rules)
// ---------------------------------------------------------------------------
__device__ __align__(16) __half g_xh[MM * DD];
__device__ __align__(16) __half g_xl[MM * DD];
__device__ __align__(16) __half g_qh[MM * DD];
__device__ __align__(16) __half g_kh[MM * DD];
__device__ __align__(16) __half g_vh[MM * DD];
__device__ __align__(16) __half g_ch[MM * DD];
__device__ __align__(16) __half g_cl[MM * DD];
__device__ __align__(16) __half g_wh[4 * DD * DD];   // weights: fp16 hi only

// ---------------------------------------------------------------------------
// Low-level helpers (base ISA only: ldmatrix + mma.sync + cp.async)
// ---------------------------------------------------------------------------
__device__ __forceinline__ uint32_t smem_u32(const void* p) {
    uint32_t a;
    asm("{ .reg .u64 t; cvta.to.shared.u64 t, %1; cvt.u32.u64 %0, t; }"
        : "=r"(a) : "l"(p));
    return a;
}

__device__ __forceinline__ uint32_t sw128(uint32_t off) {
    return off ^ ((off >> 3) & 0x70);
}

__device__ __forceinline__ void cp16(uint32_t dst, const void* src) {
    asm volatile("cp.async.cg.shared.global [%0], [%1], 16;"
                 :: "r"(dst), "l"(src) : "memory");
}

__device__ __forceinline__ void ldsm_x4(uint32_t* r, uint32_t addr) {
    asm volatile("ldmatrix.sync.aligned.m8n8.x4.shared.b16 {%0,%1,%2,%3}, [%4];"
                 : "=r"(r[0]), "=r"(r[1]), "=r"(r[2]), "=r"(r[3]) : "r"(addr));
}

__device__ __forceinline__ void ldsm_x4t(uint32_t* r, uint32_t addr) {
    asm volatile("ldmatrix.sync.aligned.m8n8.x4.trans.shared.b16 {%0,%1,%2,%3}, [%4];"
                 : "=r"(r[0]), "=r"(r[1]), "=r"(r[2]), "=r"(r[3]) : "r"(addr));
}

// fp16 inputs, fp32 accumulate
__device__ __forceinline__ void mma16816(float* c, const uint32_t* a,
                                         const uint32_t* b) {
    asm volatile(
        "mma.sync.aligned.m16n8k16.row.col.f32.f16.f16.f32 "
        "{%0,%1,%2,%3}, {%4,%5,%6,%7}, {%8,%9}, {%0,%1,%2,%3};"
        : "+f"(c[0]), "+f"(c[1]), "+f"(c[2]), "+f"(c[3])
        : "r"(a[0]), "r"(a[1]), "r"(a[2]), "r"(a[3]), "r"(b[0]), "r"(b[1]));
}

__device__ __forceinline__ float ex2f(float x) {
    float r;
    asm("ex2.approx.ftz.f32 %0, %1;" : "=f"(r) : "f"(x));
    return r;
}

// fp16 hi/lo split: hi = rn_fp16(x) (error 2^-12), lo = rn_fp16(x - hi)
__device__ __forceinline__ void split2h(float x, float y,
                                        uint32_t& hi, uint32_t& lo) {
    asm("cvt.rn.f16x2.f32 %0, %1, %2;" : "=r"(hi) : "f"(y), "f"(x));
    __half2 h2 = *reinterpret_cast<__half2*>(&hi);
    float rx = x - __half2float(__low2half(h2));
    float ry = y - __half2float(__high2half(h2));
    asm("cvt.rn.f16x2.f32 %0, %1, %2;" : "=r"(lo) : "f"(ry), "f"(rx));
}

__device__ __forceinline__ uint32_t pack_h2(float x, float y) {
    uint32_t h;
    asm("cvt.rn.f16x2.f32 %0, %1, %2;" : "=r"(h) : "f"(y), "f"(x));
    return h;
}

// ---------------------------------------------------------------------------
// Split kernels. Launch order matters for ncu capture (launch #3 = attn).
// ---------------------------------------------------------------------------
__global__ __launch_bounds__(256) void split_w(
    const float* __restrict__ W0, const float* __restrict__ W1,
    const float* __restrict__ W2, const float* __restrict__ W3,
    __half* __restrict__ out)
{
    int mat = blockIdx.x >> 10;
    int i = (blockIdx.x & 1023) * 256 + threadIdx.x;
    const float* src = (mat == 0) ? W0 : (mat == 1) ? W1 : (mat == 2) ? W2 : W3;
    float4 v = reinterpret_cast<const float4*>(src)[i];
    uint32_t* dst = reinterpret_cast<uint32_t*>(out + (size_t)mat * DD * DD);
    dst[2 * i]     = pack_h2(v.x, v.y);
    dst[2 * i + 1] = pack_h2(v.z, v.w);
}

__global__ __launch_bounds__(256) void split_x(
    const float* __restrict__ src,
    __half* __restrict__ hi, __half* __restrict__ lo)
{
    int i = blockIdx.x * 256 + threadIdx.x;
    float4 v = reinterpret_cast<const float4*>(src)[i];
    uint32_t h0, l0, h1, l1;
    split2h(v.x, v.y, h0, l0);
    split2h(v.z, v.w, h1, l1);
    reinterpret_cast<uint32_t*>(hi)[2 * i]     = h0;
    reinterpret_cast<uint32_t*>(hi)[2 * i + 1] = h1;
    reinterpret_cast<uint32_t*>(lo)[2 * i]     = l0;
    reinterpret_cast<uint32_t*>(lo)[2 * i + 1] = l1;
}

// ---------------------------------------------------------------------------
// fp16 2-chain GEMM (NT), fused over up to 3 weight matrices:
//   C[m,n] = ((Ah+Al)[m,:] . Wh[n,:] + bias[n]) * scale
// CTA 128x128, BK=64, 512 threads (16 warps, 4x4), warp tile 32x32,
// 2-stage cp.async pipeline, 2 CTAs/SM.
// ---------------------------------------------------------------------------
#define G_STAGE 49152   // Ah 16K | Al 16K | Wh 16K
#define G_SMEM  (2 * G_STAGE)

template<bool F32OUT>
__global__ __launch_bounds__(512, 2) void hgemm(
    const __half* __restrict__ Ah, const __half* __restrict__ Al,
    const __half* __restrict__ Wh,
    const float* __restrict__ B0, const float* __restrict__ B1,
    const float* __restrict__ B2,
    __half* __restrict__ O0h, __half* __restrict__ O1h,
    __half* __restrict__ O2h,
    float* __restrict__ Cf)
{
    extern __shared__ __align__(1024) char smem[];
    uint32_t sb = smem_u32(smem);
    const int tid = threadIdx.x;
    const int w = tid >> 5, lane = tid & 31;
    const int wr = w >> 2, wc = w & 3;          // 4x4 warp grid, 32x32 tiles
    const int mat = blockIdx.x >> 3;
    const int n0  = (blockIdx.x & 7) * 128;
    const int m0  = blockIdx.y * 128;
    const __half* Wmh = Wh + (size_t)mat * DD * DD;

    float acc[2][4][4];
    #pragma unroll
    for (int mt = 0; mt < 2; mt++)
        #pragma unroll
        for (int nt = 0; nt < 4; nt++)
            #pragma unroll
            for (int i = 0; i < 4; i++) acc[mt][nt][i] = 0.f;

    auto load_stage = [&](int t, int s) {
        uint32_t base = sb + s * G_STAGE;
        const char* srcs[3] = {
            (const char*)Ah  + (size_t)m0 * 2048 + t * 128,
            (const char*)Al  + (size_t)m0 * 2048 + t * 128,
            (const char*)Wmh + (size_t)n0 * 2048 + t * 128};
        #pragma unroll
        for (int mtx = 0; mtx < 3; mtx++) {
            #pragma unroll
            for (int i = 0; i < 2; i++) {
                int idx = tid + i * 512;       // 0..1023 (row*8 + chunk)
                int row = idx >> 3, c = idx & 7;
                cp16(base + mtx * 16384u + sw128((uint32_t)idx * 16),
                     srcs[mtx] + (size_t)row * 2048 + c * 16);
            }
        }
        asm volatile("cp.async.commit_group;" ::: "memory");
    };

    const int NT = DD / 64;  // 16
    load_stage(0, 0);

    for (int t = 0; t < NT; t++) {
        // wait for load(t); issue load(t+1) after the sync (its target stage
        // was consumed at t-1, which the sync orders before us)
        asm volatile("cp.async.wait_group 0;" ::: "memory");
        __syncthreads();
        if (t + 1 < NT) load_stage(t + 1, (t + 1) & 1);
        uint32_t base = sb + (t & 1) * G_STAGE;

        #pragma unroll
        for (int k16 = 0; k16 < 4; k16++) {
            uint32_t af_h[2][4], af_l[2][4];
            #pragma unroll
            for (int mt = 0; mt < 2; mt++) {
                int row = wr * 32 + mt * 16 + (lane & 15);
                uint32_t off = sw128((uint32_t)row * 128 +
                                     (k16 * 2 + (lane >> 4)) * 16);
                ldsm_x4(af_h[mt], base + off);
                ldsm_x4(af_l[mt], base + 16384u + off);
            }
            uint32_t bf[4][2];
            #pragma unroll
            for (int nh = 0; nh < 2; nh++) {
                int row = wc * 32 + nh * 16 + (lane & 15);
                uint32_t off = sw128((uint32_t)row * 128 +
                                     (k16 * 2 + (lane >> 4)) * 16);
                uint32_t r[4];
                ldsm_x4(r, base + 32768u + off);
                bf[nh * 2][0] = r[0]; bf[nh * 2 + 1][0] = r[1];
                bf[nh * 2][1] = r[2]; bf[nh * 2 + 1][1] = r[3];
            }
            #pragma unroll
            for (int mt = 0; mt < 2; mt++)
                #pragma unroll
                for (int nt = 0; nt < 4; nt++) {
                    mma16816(acc[mt][nt], af_h[mt], bf[nt]);
                    mma16816(acc[mt][nt], af_l[mt], bf[nt]);
                }
        }
    }

    // Epilogue
    const float* bias = (mat == 0) ? B0 : (mat == 1 ? B1 : B2);
    __half* Oh = (mat == 0) ? O0h : (mat == 1 ? O1h : O2h);
    const float scl = (!F32OUT && mat == 0) ? SCALE_Q : 1.0f;
    const int r = lane >> 2, cp2 = (lane & 3) * 2;
    #pragma unroll
    for (int mt = 0; mt < 2; mt++) {
        #pragma unroll
        for (int nt = 0; nt < 4; nt++) {
            int row = m0 + wr * 32 + mt * 16 + r;
            int col = n0 + wc * 32 + nt * 8 + cp2;
            float b0 = bias[col], b1 = bias[col + 1];
            float v00 = (acc[mt][nt][0] + b0) * scl;
            float v01 = (acc[mt][nt][1] + b1) * scl;
            float v10 = (acc[mt][nt][2] + b0) * scl;
            float v11 = (acc[mt][nt][3] + b1) * scl;
            if (F32OUT) {
                *reinterpret_cast<float2*>(Cf + (size_t)row * DD + col) =
                    make_float2(v00, v01);
                *reinterpret_cast<float2*>(Cf + (size_t)(row + 8) * DD + col) =
                    make_float2(v10, v11);
            } else {
                *reinterpret_cast<uint32_t*>(Oh + (size_t)row * DD + col) =
                    pack_h2(v00, v01);
                *reinterpret_cast<uint32_t*>(Oh + (size_t)(row + 8) * DD + col) =
                    pack_h2(v10, v11);
            }
        }
    }
}

// ---------------------------------------------------------------------------
// Flash attention, single-chain fp16 (S = Qh Kh^T, O += Ph Vh).
// 256 threads, BM=128, BN=64, 3-stage KV pipeline, 2 CTAs/SM (128 regs).
// P is packed to fp16 immediately after softmax to cut register pressure.
// ctx written as fp16 hi/lo (O-projection is K=1024 and needs the split).
// ---------------------------------------------------------------------------
#define A_STAGE 16384   // Kh 8K | Vh 8K
#define A_SMEM  (3 * A_STAGE)

__global__ __launch_bounds__(256, 2) void attn_mma(
    const __half* __restrict__ Qh,
    const __half* __restrict__ Kh,
    const __half* __restrict__ Vh,
    __half* __restrict__ Ch, __half* __restrict__ Cl)
{
    extern __shared__ __align__(1024) char smem[];
    uint32_t sb = smem_u32(smem);
    const int tid = threadIdx.x;
    const int w = tid >> 5, lane = tid & 31;
    const int q0 = blockIdx.x * 128;
    const int hd = blockIdx.y;
    const int b  = blockIdx.z;

    const size_t qbase = ((size_t)b * SS + q0) * DD + hd * 64;
    const size_t kbase = (size_t)b * SS * DD + hd * 64;

    auto load_kv = [&](int it, int s) {
        uint32_t base = sb + s * A_STAGE;
        const char* gk = (const char*)Kh + (kbase + (size_t)it * 64 * DD) * 2;
        const char* gv = (const char*)Vh + (kbase + (size_t)it * 64 * DD) * 2;
        #pragma unroll
        for (int i = 0; i < 2; i++) {
            int idx = tid + i * 256;       // 0..511
            int row = idx >> 3, c = idx & 7;
            cp16(base + sw128((uint32_t)idx * 16),
                 gk + (size_t)row * 2048 + c * 16);
            cp16(base + 8192u + sw128((uint32_t)idx * 16),
                 gv + (size_t)row * 2048 + c * 16);
        }
        asm volatile("cp.async.commit_group;" ::: "memory");
    };

    // ---- Prologue: Q (hi only, 16K) into stage-2 area; KV 0,1 in flight ----
    {
        const char* gq = (const char*)Qh + qbase * 2;
        uint32_t qb = sb + 2 * A_STAGE;
        #pragma unroll
        for (int i = 0; i < 4; i++) {
            int idx = tid + i * 256;       // 0..1023
            int row = idx >> 3, c = idx & 7;
            cp16(qb + sw128((uint32_t)idx * 16),
                 gq + (size_t)row * 2048 + c * 16);
        }
        asm volatile("cp.async.commit_group;" ::: "memory");
    }
    load_kv(0, 0);
    load_kv(1, 1);
    asm volatile("cp.async.wait_group 2;" ::: "memory");  // Q landed
    __syncthreads();

    uint32_t qf[4][4];
    {
        uint32_t qb = sb + 2 * A_STAGE;
        #pragma unroll
        for (int k16 = 0; k16 < 4; k16++) {
            int row = w * 16 + (lane & 15);
            uint32_t off = sw128((uint32_t)row * 128 +
                                 (k16 * 2 + (lane >> 4)) * 16);
            ldsm_x4(qf[k16], qb + off);
        }
    }
    __syncthreads();   // Q area may now be reused as KV stage 2

    float o[8][4];
    #pragma unroll
    for (int dt = 0; dt < 8; dt++)
        #pragma unroll
        for (int i = 0; i < 4; i++) o[dt][i] = 0.f;
    const float NEG_INF = __int_as_float(0xff800000);
    float mrow[2] = {NEG_INF, NEG_INF};
    float lrow[2] = {0.f, 0.f};

    const int NT = SS / 64;  // 32
    for (int it = 0; it < NT; it++) {
        if (it < NT - 1)
            asm volatile("cp.async.wait_group 1;" ::: "memory");
        else
            asm volatile("cp.async.wait_group 0;" ::: "memory");
        __syncthreads();
        if (it + 2 < NT) load_kv(it + 2, (it + 2) % 3);
        uint32_t base = sb + (it % 3) * A_STAGE;

        // ---- S = Q K^T (single chain; log2 units via folded Q scale) ----
        float s[8][4];
        #pragma unroll
        for (int nt = 0; nt < 8; nt++)
            #pragma unroll
            for (int i = 0; i < 4; i++) s[nt][i] = 0.f;

        #pragma unroll
        for (int k16 = 0; k16 < 4; k16++) {
            uint32_t kf[8][2];
            #pragma unroll
            for (int nh = 0; nh < 4; nh++) {
                int row = nh * 16 + (lane & 15);
                uint32_t off = sw128((uint32_t)row * 128 +
                                     (k16 * 2 + (lane >> 4)) * 16);
                uint32_t r[4];
                ldsm_x4(r, base + off);
                kf[nh * 2][0] = r[0]; kf[nh * 2 + 1][0] = r[1];
                kf[nh * 2][1] = r[2]; kf[nh * 2 + 1][1] = r[3];
            }
            #pragma unroll
            for (int nt = 0; nt < 8; nt++)
                mma16816(s[nt], qf[k16], kf[nt]);
        }

        // ---- online softmax in log2 domain ----
        #pragma unroll
        for (int hf = 0; hf < 2; hf++) {
            float mx = NEG_INF;
            #pragma unroll
            for (int nt = 0; nt < 8; nt++)
                mx = fmaxf(mx, fmaxf(s[nt][2 * hf], s[nt][2 * hf + 1]));
            mx = fmaxf(mx, __shfl_xor_sync(0xffffffffu, mx, 1));
            mx = fmaxf(mx, __shfl_xor_sync(0xffffffffu, mx, 2));
            float mn = fmaxf(mrow[hf], mx);
            uint32_t keep = __all_sync(0xffffffffu, mn == mrow[hf]);
            float rs = 0.f;
            #pragma unroll
            for (int nt = 0; nt < 8; nt++) {
                float p0 = ex2f(s[nt][2 * hf] - mn);
                float p1 = ex2f(s[nt][2 * hf + 1] - mn);
                s[nt][2 * hf] = p0; s[nt][2 * hf + 1] = p1;
                rs += p0 + p1;
            }
            rs += __shfl_xor_sync(0xffffffffu, rs, 1);
            rs += __shfl_xor_sync(0xffffffffu, rs, 2);
            if (keep) {
                lrow[hf] += rs;
            } else {
                float scale = ex2f(mrow[hf] - mn);
                lrow[hf] = lrow[hf] * scale + rs;
                mrow[hf] = mn;
                #pragma unroll
                for (int dt = 0; dt < 8; dt++) {
                    o[dt][2 * hf]     *= scale;
                    o[dt][2 * hf + 1] *= scale;
                }
            }
        }

        // ---- pack P to fp16 A-fragments (frees the fp32 S registers) ----
        uint32_t pp[16];
        #pragma unroll
        for (int t = 0; t < 4; t++) {
            pp[4 * t + 0] = pack_h2(s[2 * t][0],     s[2 * t][1]);
            pp[4 * t + 1] = pack_h2(s[2 * t][2],     s[2 * t][3]);
            pp[4 * t + 2] = pack_h2(s[2 * t + 1][0], s[2 * t + 1][1]);
            pp[4 * t + 3] = pack_h2(s[2 * t + 1][2], s[2 * t + 1][3]);
        }

        // ---- O += P V (single chain) ----
        #pragma unroll
        for (int t = 0; t < 4; t++) {
            uint32_t vf[8][2];
            #pragma unroll
            for (int dp = 0; dp < 4; dp++) {
                int row = t * 16 + (lane & 15);
                uint32_t off = sw128((uint32_t)row * 128 +
                                     (dp * 2 + (lane >> 4)) * 16);
                uint32_t r[4];
                ldsm_x4t(r, base + 8192u + off);
                vf[dp * 2][0] = r[0]; vf[dp * 2][1] = r[1];
                vf[dp * 2 + 1][0] = r[2]; vf[dp * 2 + 1][1] = r[3];
            }
            #pragma unroll
            for (int dt = 0; dt < 8; dt++)
                mma16816(o[dt], &pp[4 * t], vf[dt]);
        }
    }

    // ---- epilogue: ctx = O / l, written as fp16 hi/lo ----
    const int r = lane >> 2, cp2 = (lane & 3) * 2;
    #pragma unroll
    for (int hf = 0; hf < 2; hf++) {
        float inv = 1.f / lrow[hf];
        int row = q0 + w * 16 + r + hf * 8;
        size_t ob = ((size_t)b * SS + row) * DD + hd * 64;
        #pragma unroll
        for (int dt = 0; dt < 8; dt++) {
            float v0 = o[dt][2 * hf] * inv;
            float v1 = o[dt][2 * hf + 1] * inv;
            uint32_t h, l;
            split2h(v0, v1, h, l);
            *reinterpret_cast<uint32_t*>(Ch + ob + dt * 8 + cp2) = h;
            *reinterpret_cast<uint32_t*>(Cl + ob + dt * 8 + cp2) = l;
        }
    }
}

// ---------------------------------------------------------------------------
// Launch (order chosen so ncu's captured launch #3 = attn_mma)
// ---------------------------------------------------------------------------
extern "C" void kernel_launch(void* const* d_in, const int* in_sizes, int n_in,
                              void* d_out, int out_size)
{
    const float* x  = (const float*)d_in[0];
    const float* Wq = (const float*)d_in[1];
    const float* bq = (const float*)d_in[2];
    const float* Wk = (const float*)d_in[3];
    const float* bk = (const float*)d_in[4];
    const float* Wv = (const float*)d_in[5];
    const float* bv = (const float*)d_in[6];
    const float* Wo = (const float*)d_in[7];
    const float* bo = (const float*)d_in[8];
    float* out = (float*)d_out;

    __half *xh, *xl, *qh, *kh, *vh, *ch, *cl, *wh;
    cudaGetSymbolAddress((void**)&xh, g_xh);
    cudaGetSymbolAddress((void**)&xl, g_xl);
    cudaGetSymbolAddress((void**)&qh, g_qh);
    cudaGetSymbolAddress((void**)&kh, g_kh);
    cudaGetSymbolAddress((void**)&vh, g_vh);
    cudaGetSymbolAddress((void**)&ch, g_ch);
    cudaGetSymbolAddress((void**)&cl, g_cl);
    cudaGetSymbolAddress((void**)&wh, g_wh);

    cudaFuncSetAttribute(hgemm<false>,
                         cudaFuncAttributeMaxDynamicSharedMemorySize, G_SMEM);
    cudaFuncSetAttribute(hgemm<true>,
                         cudaFuncAttributeMaxDynamicSharedMemorySize, G_SMEM);
    cudaFuncSetAttribute(attn_mma,
                         cudaFuncAttributeMaxDynamicSharedMemorySize, A_SMEM);

    // launch 0: all weights -> fp16 hi
    split_w<<<4096, 256>>>(Wq, Wk, Wv, Wo, wh);
    // launch 1: x -> fp16 hi/lo
    split_x<<<MM * DD / 1024, 256>>>(x, xh, xl);

    // launch 2: fused QKV projection (mat 0 = Q gets softmax scale folded in)
    dim3 gqkv(24, 64);
    hgemm<false><<<gqkv, 512, G_SMEM>>>(
        xh, xl, wh, bq, bk, bv,
        qh, kh, vh, nullptr);

    // launch 3: attention  (ncu capture slot)
    dim3 ag(SS / 128, HH, BB);    // (16, 16, 4)
    attn_mma<<<ag, 256, A_SMEM>>>(qh, kh, vh, ch, cl);

    // launch 4: output projection (fp32 out)
    dim3 go(8, 64);
    hgemm<true><<<go, 512, G_SMEM>>>(
        ch, cl, wh + 3 * (size_t)DD * DD, bo, nullptr, nullptr,
        nullptr, nullptr, nullptr, out);
}

// round 8
// speedup vs baseline: 7.5279x; 1.3432x over previous
#include <cuda_runtime.h>
#include <cuda_fp16.h>
#include <math.h>
#include <stdint.h>

// Problem constants
#define BB 4
#define SS 2048
#define DD 1024
#define HH 16
#define DK 64
#define MM (BB * SS)   // 8192 rows

// 0.125 (1/sqrt(DK)) * log2(e): folded into Q so softmax runs in log2 domain
#define SCALE_Q 0.1803368801111204f

// ---------------------------------------------------------------------------
// Scratch (static device globals: allocation-free per harness rules)
// ---------------------------------------------------------------------------
__device__ __align__(16) __half g_xh[MM * DD];
__device__ __align__(16) __half g_qh[MM * DD];
__device__ __align__(16) __half g_kh[MM * DD];
__device__ __align__(16) __half g_vh[MM * DD];
__device__ __align__(16) __half g_ch[MM * DD];
__device__ __align__(16) __half g_cl[MM * DD];
__device__ __align__(16) __half g_wh[4 * DD * DD];   // weights: fp16 hi only

// ---------------------------------------------------------------------------
// Low-level helpers (base ISA only: ldmatrix + mma.sync + cp.async)
// ---------------------------------------------------------------------------
__device__ __forceinline__ uint32_t smem_u32(const void* p) {
    uint32_t a;
    asm("{ .reg .u64 t; cvta.to.shared.u64 t, %1; cvt.u32.u64 %0, t; }"
        : "=r"(a) : "l"(p));
    return a;
}

__device__ __forceinline__ uint32_t sw128(uint32_t off) {
    return off ^ ((off >> 3) & 0x70);
}

__device__ __forceinline__ void cp16(uint32_t dst, const void* src) {
    asm volatile("cp.async.cg.shared.global [%0], [%1], 16;"
                 :: "r"(dst), "l"(src) : "memory");
}

__device__ __forceinline__ void ldsm_x4(uint32_t* r, uint32_t addr) {
    asm volatile("ldmatrix.sync.aligned.m8n8.x4.shared.b16 {%0,%1,%2,%3}, [%4];"
                 : "=r"(r[0]), "=r"(r[1]), "=r"(r[2]), "=r"(r[3]) : "r"(addr));
}

__device__ __forceinline__ void ldsm_x4t(uint32_t* r, uint32_t addr) {
    asm volatile("ldmatrix.sync.aligned.m8n8.x4.trans.shared.b16 {%0,%1,%2,%3}, [%4];"
                 : "=r"(r[0]), "=r"(r[1]), "=r"(r[2]), "=r"(r[3]) : "r"(addr));
}

// fp16 inputs, fp32 accumulate
__device__ __forceinline__ void mma16816(float* c, const uint32_t* a,
                                         const uint32_t* b) {
    asm volatile(
        "mma.sync.aligned.m16n8k16.row.col.f32.f16.f16.f32 "
        "{%0,%1,%2,%3}, {%4,%5,%6,%7}, {%8,%9}, {%0,%1,%2,%3};"
        : "+f"(c[0]), "+f"(c[1]), "+f"(c[2]), "+f"(c[3])
        : "r"(a[0]), "r"(a[1]), "r"(a[2]), "r"(a[3]), "r"(b[0]), "r"(b[1]));
}

__device__ __forceinline__ float ex2f(float x) {
    float r;
    asm("ex2.approx.ftz.f32 %0, %1;" : "=f"(r) : "f"(x));
    return r;
}

// fp16 hi/lo split: hi = rn_fp16(x) (error 2^-12), lo = rn_fp16(x - hi)
__device__ __forceinline__ void split2h(float x, float y,
                                        uint32_t& hi, uint32_t& lo) {
    asm("cvt.rn.f16x2.f32 %0, %1, %2;" : "=r"(hi) : "f"(y), "f"(x));
    __half2 h2 = *reinterpret_cast<__half2*>(&hi);
    float rx = x - __half2float(__low2half(h2));
    float ry = y - __half2float(__high2half(h2));
    asm("cvt.rn.f16x2.f32 %0, %1, %2;" : "=r"(lo) : "f"(ry), "f"(rx));
}

__device__ __forceinline__ uint32_t pack_h2(float x, float y) {
    uint32_t h;
    asm("cvt.rn.f16x2.f32 %0, %1, %2;" : "=r"(h) : "f"(y), "f"(x));
    return h;
}

// ---------------------------------------------------------------------------
// Pack kernels. Launch order matters for ncu capture (launch #3 = attn).
// ---------------------------------------------------------------------------
__global__ __launch_bounds__(256) void split_w(
    const float* __restrict__ W0, const float* __restrict__ W1,
    const float* __restrict__ W2, const float* __restrict__ W3,
    __half* __restrict__ out)
{
    int mat = blockIdx.x >> 10;
    int i = (blockIdx.x & 1023) * 256 + threadIdx.x;
    const float* src = (mat == 0) ? W0 : (mat == 1) ? W1 : (mat == 2) ? W2 : W3;
    float4 v = reinterpret_cast<const float4*>(src)[i];
    uint32_t* dst = reinterpret_cast<uint32_t*>(out + (size_t)mat * DD * DD);
    dst[2 * i]     = pack_h2(v.x, v.y);
    dst[2 * i + 1] = pack_h2(v.z, v.w);
}

__global__ __launch_bounds__(256) void pack_x(
    const float* __restrict__ src, __half* __restrict__ dst)
{
    int i = blockIdx.x * 256 + threadIdx.x;
    float4 v = reinterpret_cast<const float4*>(src)[i];
    reinterpret_cast<uint32_t*>(dst)[2 * i]     = pack_h2(v.x, v.y);
    reinterpret_cast<uint32_t*>(dst)[2 * i + 1] = pack_h2(v.z, v.w);
}

// ---------------------------------------------------------------------------
// fp16 GEMM (NT), fused over up to 3 weight matrices (mat = blockIdx.x>>3):
//   C[m,n] = ((Ah[+Al])[m,:] . Wh[n,:] + bias[n]) * scale
// CTA 128x128, BK=64, 256 threads (8 warps, 4x2), warp tile 32x64.
// HAS_AL: 2-chain A split (O-projection). NSTAGES-deep cp.async pipeline.
// 2 CTAs/SM (96K smem, ~115 regs).
// ---------------------------------------------------------------------------
#define G_SMEM 98304    // QKV: 3 x 32K (Ah|Wh). Oproj: 2 x 48K (Ah|Al|Wh)

template<bool F32OUT, bool HAS_AL, int NSTAGES>
__global__ __launch_bounds__(256, 2) void hgemm(
    const __half* __restrict__ Ah, const __half* __restrict__ Al,
    const __half* __restrict__ Wh,
    const float* __restrict__ B0, const float* __restrict__ B1,
    const float* __restrict__ B2,
    __half* __restrict__ O0h, __half* __restrict__ O1h,
    __half* __restrict__ O2h,
    float* __restrict__ Cf)
{
    constexpr uint32_t SSZ  = HAS_AL ? 49152u : 32768u;  // stage bytes
    constexpr uint32_t WOFF = HAS_AL ? 32768u : 16384u;  // W tile offset

    extern __shared__ __align__(1024) char smem[];
    uint32_t sb = smem_u32(smem);
    const int tid = threadIdx.x;
    const int w = tid >> 5, lane = tid & 31;
    const int wr = w >> 1, wc = w & 1;          // 4x2 warp grid, 32x64 tiles
    const int mat = blockIdx.x >> 3;
    const int n0  = (blockIdx.x & 7) * 128;
    const int m0  = blockIdx.y * 128;
    const __half* Wmh = Wh + (size_t)mat * DD * DD;

    float acc[2][8][4];
    #pragma unroll
    for (int mt = 0; mt < 2; mt++)
        #pragma unroll
        for (int nt = 0; nt < 8; nt++)
            #pragma unroll
            for (int i = 0; i < 4; i++) acc[mt][nt][i] = 0.f;

    auto load_stage = [&](int t, int s) {
        uint32_t base = sb + s * SSZ;
        // A tile
        #pragma unroll
        for (int i = 0; i < 4; i++) {
            int idx = tid + i * 256;           // 0..1023
            int row = idx >> 3, c = idx & 7;
            cp16(base + sw128((uint32_t)idx * 16),
                 (const char*)Ah + (size_t)(m0 + row) * 2048 + t * 128 + c * 16);
        }
        if (HAS_AL) {
            #pragma unroll
            for (int i = 0; i < 4; i++) {
                int idx = tid + i * 256;
                int row = idx >> 3, c = idx & 7;
                cp16(base + 16384u + sw128((uint32_t)idx * 16),
                     (const char*)Al + (size_t)(m0 + row) * 2048 + t * 128 + c * 16);
            }
        }
        // W tile
        #pragma unroll
        for (int i = 0; i < 4; i++) {
            int idx = tid + i * 256;
            int row = idx >> 3, c = idx & 7;
            cp16(base + WOFF + sw128((uint32_t)idx * 16),
                 (const char*)Wmh + (size_t)(n0 + row) * 2048 + t * 128 + c * 16);
        }
        asm volatile("cp.async.commit_group;" ::: "memory");
    };

    const int NT = DD / 64;  // 16
    load_stage(0, 0);
    if (NSTAGES == 3) load_stage(1, 1);

    for (int t = 0; t < NT; t++) {
        if (NSTAGES == 3 && t < NT - 1)
            asm volatile("cp.async.wait_group 1;" ::: "memory");
        else
            asm volatile("cp.async.wait_group 0;" ::: "memory");
        __syncthreads();
        if (NSTAGES == 3) {
            if (t + 2 < NT) load_stage(t + 2, (t + 2) % 3);
        } else {
            if (t + 1 < NT) load_stage(t + 1, (t + 1) & 1);
        }
        uint32_t base = sb + (t % NSTAGES) * SSZ;

        #pragma unroll
        for (int k16 = 0; k16 < 4; k16++) {
            uint32_t af_h[2][4], af_l[2][4];
            #pragma unroll
            for (int mt = 0; mt < 2; mt++) {
                int row = wr * 32 + mt * 16 + (lane & 15);
                uint32_t off = sw128((uint32_t)row * 128 +
                                     (k16 * 2 + (lane >> 4)) * 16);
                ldsm_x4(af_h[mt], base + off);
                if (HAS_AL) ldsm_x4(af_l[mt], base + 16384u + off);
            }
            uint32_t bf[8][2];
            #pragma unroll
            for (int nh = 0; nh < 4; nh++) {
                int row = wc * 64 + nh * 16 + (lane & 15);
                uint32_t off = sw128((uint32_t)row * 128 +
                                     (k16 * 2 + (lane >> 4)) * 16);
                uint32_t r[4];
                ldsm_x4(r, base + WOFF + off);
                bf[nh * 2][0] = r[0]; bf[nh * 2 + 1][0] = r[1];
                bf[nh * 2][1] = r[2]; bf[nh * 2 + 1][1] = r[3];
            }
            #pragma unroll
            for (int mt = 0; mt < 2; mt++)
                #pragma unroll
                for (int nt = 0; nt < 8; nt++) {
                    mma16816(acc[mt][nt], af_h[mt], bf[nt]);
                    if (HAS_AL) mma16816(acc[mt][nt], af_l[mt], bf[nt]);
                }
        }
    }

    // Epilogue
    const float* bias = (mat == 0) ? B0 : (mat == 1 ? B1 : B2);
    __half* Oh = (mat == 0) ? O0h : (mat == 1 ? O1h : O2h);
    const float scl = (!F32OUT && mat == 0) ? SCALE_Q : 1.0f;
    const int r = lane >> 2, cp2 = (lane & 3) * 2;
    #pragma unroll
    for (int mt = 0; mt < 2; mt++) {
        #pragma unroll
        for (int nt = 0; nt < 8; nt++) {
            int row = m0 + wr * 32 + mt * 16 + r;
            int col = n0 + wc * 64 + nt * 8 + cp2;
            float b0 = bias[col], b1 = bias[col + 1];
            float v00 = (acc[mt][nt][0] + b0) * scl;
            float v01 = (acc[mt][nt][1] + b1) * scl;
            float v10 = (acc[mt][nt][2] + b0) * scl;
            float v11 = (acc[mt][nt][3] + b1) * scl;
            if (F32OUT) {
                *reinterpret_cast<float2*>(Cf + (size_t)row * DD + col) =
                    make_float2(v00, v01);
                *reinterpret_cast<float2*>(Cf + (size_t)(row + 8) * DD + col) =
                    make_float2(v10, v11);
            } else {
                *reinterpret_cast<uint32_t*>(Oh + (size_t)row * DD + col) =
                    pack_h2(v00, v01);
                *reinterpret_cast<uint32_t*>(Oh + (size_t)(row + 8) * DD + col) =
                    pack_h2(v10, v11);
            }
        }
    }
}

// ---------------------------------------------------------------------------
// Flash attention, single-chain fp16 (S = Qh Kh^T, O += Ph Vh).
// 256 threads, BM=128, BN=64, 3-stage KV pipeline, 2 CTAs/SM (128 regs).
// ctx written as fp16 hi/lo (O-projection is K=1024 and needs the split).
// ---------------------------------------------------------------------------
#define A_STAGE 16384   // Kh 8K | Vh 8K
#define A_SMEM  (3 * A_STAGE)

__global__ __launch_bounds__(256, 2) void attn_mma(
    const __half* __restrict__ Qh,
    const __half* __restrict__ Kh,
    const __half* __restrict__ Vh,
    __half* __restrict__ Ch, __half* __restrict__ Cl)
{
    extern __shared__ __align__(1024) char smem[];
    uint32_t sb = smem_u32(smem);
    const int tid = threadIdx.x;
    const int w = tid >> 5, lane = tid & 31;
    const int q0 = blockIdx.x * 128;
    const int hd = blockIdx.y;
    const int b  = blockIdx.z;

    const size_t qbase = ((size_t)b * SS + q0) * DD + hd * 64;
    const size_t kbase = (size_t)b * SS * DD + hd * 64;

    auto load_kv = [&](int it, int s) {
        uint32_t base = sb + s * A_STAGE;
        const char* gk = (const char*)Kh + (kbase + (size_t)it * 64 * DD) * 2;
        const char* gv = (const char*)Vh + (kbase + (size_t)it * 64 * DD) * 2;
        #pragma unroll
        for (int i = 0; i < 2; i++) {
            int idx = tid + i * 256;       // 0..511
            int row = idx >> 3, c = idx & 7;
            cp16(base + sw128((uint32_t)idx * 16),
                 gk + (size_t)row * 2048 + c * 16);
            cp16(base + 8192u + sw128((uint32_t)idx * 16),
                 gv + (size_t)row * 2048 + c * 16);
        }
        asm volatile("cp.async.commit_group;" ::: "memory");
    };

    // ---- Prologue: Q (hi only, 16K) into stage-2 area; KV 0,1 in flight ----
    {
        const char* gq = (const char*)Qh + qbase * 2;
        uint32_t qb = sb + 2 * A_STAGE;
        #pragma unroll
        for (int i = 0; i < 4; i++) {
            int idx = tid + i * 256;       // 0..1023
            int row = idx >> 3, c = idx & 7;
            cp16(qb + sw128((uint32_t)idx * 16),
                 gq + (size_t)row * 2048 + c * 16);
        }
        asm volatile("cp.async.commit_group;" ::: "memory");
    }
    load_kv(0, 0);
    load_kv(1, 1);
    asm volatile("cp.async.wait_group 2;" ::: "memory");  // Q landed
    __syncthreads();

    uint32_t qf[4][4];
    {
        uint32_t qb = sb + 2 * A_STAGE;
        #pragma unroll
        for (int k16 = 0; k16 < 4; k16++) {
            int row = w * 16 + (lane & 15);
            uint32_t off = sw128((uint32_t)row * 128 +
                                 (k16 * 2 + (lane >> 4)) * 16);
            ldsm_x4(qf[k16], qb + off);
        }
    }
    __syncthreads();   // Q area may now be reused as KV stage 2

    float o[8][4];
    #pragma unroll
    for (int dt = 0; dt < 8; dt++)
        #pragma unroll
        for (int i = 0; i < 4; i++) o[dt][i] = 0.f;
    const float NEG_INF = __int_as_float(0xff800000);
    float mrow[2] = {NEG_INF, NEG_INF};
    float lrow[2] = {0.f, 0.f};

    const int NT = SS / 64;  // 32
    for (int it = 0; it < NT; it++) {
        if (it < NT - 1)
            asm volatile("cp.async.wait_group 1;" ::: "memory");
        else
            asm volatile("cp.async.wait_group 0;" ::: "memory");
        __syncthreads();
        if (it + 2 < NT) load_kv(it + 2, (it + 2) % 3);
        uint32_t base = sb + (it % 3) * A_STAGE;

        // ---- S = Q K^T (single chain; log2 units via folded Q scale) ----
        float s[8][4];
        #pragma unroll
        for (int nt = 0; nt < 8; nt++)
            #pragma unroll
            for (int i = 0; i < 4; i++) s[nt][i] = 0.f;

        #pragma unroll
        for (int k16 = 0; k16 < 4; k16++) {
            uint32_t kf[8][2];
            #pragma unroll
            for (int nh = 0; nh < 4; nh++) {
                int row = nh * 16 + (lane & 15);
                uint32_t off = sw128((uint32_t)row * 128 +
                                     (k16 * 2 + (lane >> 4)) * 16);
                uint32_t r[4];
                ldsm_x4(r, base + off);
                kf[nh * 2][0] = r[0]; kf[nh * 2 + 1][0] = r[1];
                kf[nh * 2][1] = r[2]; kf[nh * 2 + 1][1] = r[3];
            }
            #pragma unroll
            for (int nt = 0; nt < 8; nt++)
                mma16816(s[nt], qf[k16], kf[nt]);
        }

        // ---- online softmax in log2 domain ----
        #pragma unroll
        for (int hf = 0; hf < 2; hf++) {
            float mx = NEG_INF;
            #pragma unroll
            for (int nt = 0; nt < 8; nt++)
                mx = fmaxf(mx, fmaxf(s[nt][2 * hf], s[nt][2 * hf + 1]));
            mx = fmaxf(mx, __shfl_xor_sync(0xffffffffu, mx, 1));
            mx = fmaxf(mx, __shfl_xor_sync(0xffffffffu, mx, 2));
            float mn = fmaxf(mrow[hf], mx);
            uint32_t keep = __all_sync(0xffffffffu, mn == mrow[hf]);
            float rs = 0.f;
            #pragma unroll
            for (int nt = 0; nt < 8; nt++) {
                float p0 = ex2f(s[nt][2 * hf] - mn);
                float p1 = ex2f(s[nt][2 * hf + 1] - mn);
                s[nt][2 * hf] = p0; s[nt][2 * hf + 1] = p1;
                rs += p0 + p1;
            }
            rs += __shfl_xor_sync(0xffffffffu, rs, 1);
            rs += __shfl_xor_sync(0xffffffffu, rs, 2);
            if (keep) {
                lrow[hf] += rs;
            } else {
                float scale = ex2f(mrow[hf] - mn);
                lrow[hf] = lrow[hf] * scale + rs;
                mrow[hf] = mn;
                #pragma unroll
                for (int dt = 0; dt < 8; dt++) {
                    o[dt][2 * hf]     *= scale;
                    o[dt][2 * hf + 1] *= scale;
                }
            }
        }

        // ---- pack P to fp16 A-fragments (frees the fp32 S registers) ----
        uint32_t pp[16];
        #pragma unroll
        for (int t = 0; t < 4; t++) {
            pp[4 * t + 0] = pack_h2(s[2 * t][0],     s[2 * t][1]);
            pp[4 * t + 1] = pack_h2(s[2 * t][2],     s[2 * t][3]);
            pp[4 * t + 2] = pack_h2(s[2 * t + 1][0], s[2 * t + 1][1]);
            pp[4 * t + 3] = pack_h2(s[2 * t + 1][2], s[2 * t + 1][3]);
        }

        // ---- O += P V (single chain) ----
        #pragma unroll
        for (int t = 0; t < 4; t++) {
            uint32_t vf[8][2];
            #pragma unroll
            for (int dp = 0; dp < 4; dp++) {
                int row = t * 16 + (lane & 15);
                uint32_t off = sw128((uint32_t)row * 128 +
                                     (dp * 2 + (lane >> 4)) * 16);
                uint32_t r[4];
                ldsm_x4t(r, base + 8192u + off);
                vf[dp * 2][0] = r[0]; vf[dp * 2][1] = r[1];
                vf[dp * 2 + 1][0] = r[2]; vf[dp * 2 + 1][1] = r[3];
            }
            #pragma unroll
            for (int dt = 0; dt < 8; dt++)
                mma16816(o[dt], &pp[4 * t], vf[dt]);
        }
    }

    // ---- epilogue: ctx = O / l, written as fp16 hi/lo ----
    const int r = lane >> 2, cp2 = (lane & 3) * 2;
    #pragma unroll
    for (int hf = 0; hf < 2; hf++) {
        float inv = 1.f / lrow[hf];
        int row = q0 + w * 16 + r + hf * 8;
        size_t ob = ((size_t)b * SS + row) * DD + hd * 64;
        #pragma unroll
        for (int dt = 0; dt < 8; dt++) {
            float v0 = o[dt][2 * hf] * inv;
            float v1 = o[dt][2 * hf + 1] * inv;
            uint32_t h, l;
            split2h(v0, v1, h, l);
            *reinterpret_cast<uint32_t*>(Ch + ob + dt * 8 + cp2) = h;
            *reinterpret_cast<uint32_t*>(Cl + ob + dt * 8 + cp2) = l;
        }
    }
}

// ---------------------------------------------------------------------------
// Launch (order chosen so ncu's captured launch #3 = attn_mma)
// ---------------------------------------------------------------------------
extern "C" void kernel_launch(void* const* d_in, const int* in_sizes, int n_in,
                              void* d_out, int out_size)
{
    const float* x  = (const float*)d_in[0];
    const float* Wq = (const float*)d_in[1];
    const float* bq = (const float*)d_in[2];
    const float* Wk = (const float*)d_in[3];
    const float* bk = (const float*)d_in[4];
    const float* Wv = (const float*)d_in[5];
    const float* bv = (const float*)d_in[6];
    const float* Wo = (const float*)d_in[7];
    const float* bo = (const float*)d_in[8];
    float* out = (float*)d_out;

    __half *xh, *qh, *kh, *vh, *ch, *cl, *wh;
    cudaGetSymbolAddress((void**)&xh, g_xh);
    cudaGetSymbolAddress((void**)&qh, g_qh);
    cudaGetSymbolAddress((void**)&kh, g_kh);
    cudaGetSymbolAddress((void**)&vh, g_vh);
    cudaGetSymbolAddress((void**)&ch, g_ch);
    cudaGetSymbolAddress((void**)&cl, g_cl);
    cudaGetSymbolAddress((void**)&wh, g_wh);

    cudaFuncSetAttribute((const void*)hgemm<false, false, 3>,
                         cudaFuncAttributeMaxDynamicSharedMemorySize, G_SMEM);
    cudaFuncSetAttribute((const void*)hgemm<true, true, 2>,
                         cudaFuncAttributeMaxDynamicSharedMemorySize, G_SMEM);
    cudaFuncSetAttribute((const void*)attn_mma,
                         cudaFuncAttributeMaxDynamicSharedMemorySize, A_SMEM);

    // launch 0: all weights -> fp16
    split_w<<<4096, 256>>>(Wq, Wk, Wv, Wo, wh);
    // launch 1: x -> fp16 (single precision chain for QKV)
    pack_x<<<MM * DD / 1024, 256>>>(x, xh);

    // launch 2: fused QKV projection (mat 0 = Q gets softmax scale folded in)
    dim3 gqkv(24, 64);
    hgemm<false, false, 3><<<gqkv, 256, G_SMEM>>>(
        xh, nullptr, wh, bq, bk, bv,
        qh, kh, vh, nullptr);

    // launch 3: attention  (ncu capture slot)
    dim3 ag(SS / 128, HH, BB);    // (16, 16, 4)
    attn_mma<<<ag, 256, A_SMEM>>>(qh, kh, vh, ch, cl);

    // launch 4: output projection (fp32 out, ctx hi/lo 2-chain)
    dim3 go(8, 64);
    hgemm<true, true, 2><<<go, 256, G_SMEM>>>(
        ch, cl, wh + 3 * (size_t)DD * DD, bo, nullptr, nullptr,
        nullptr, nullptr, nullptr, out);
}

// round 9
// speedup vs baseline: 8.2433x; 1.0950x over previous
#include <cuda_runtime.h>
#include <cuda_fp16.h>
#include <math.h>
#include <stdint.h>

// Problem constants
#define BB 4
#define SS 2048
#define DD 1024
#define HH 16
#define DK 64
#define MM (BB * SS)   // 8192 rows

// 0.125 (1/sqrt(DK)) * log2(e): folded into Q so softmax runs in log2 domain
#define SCALE_Q 0.1803368801111204f

// ---------------------------------------------------------------------------
// Scratch (static device globals: allocation-free per harness rules)
// ---------------------------------------------------------------------------
__device__ __align__(16) __half g_xh[MM * DD];
__device__ __align__(16) __half g_qh[MM * DD];
__device__ __align__(16) __half g_kh[MM * DD];
__device__ __align__(16) __half g_vh[MM * DD];
__device__ __align__(16) __half g_ch[MM * DD];
__device__ __align__(16) __half g_wh[4 * DD * DD];   // weights: fp16

// ---------------------------------------------------------------------------
// Low-level helpers (base ISA only: ldmatrix + mma.sync + cp.async)
// ---------------------------------------------------------------------------
__device__ __forceinline__ uint32_t smem_u32(const void* p) {
    uint32_t a;
    asm("{ .reg .u64 t; cvta.to.shared.u64 t, %1; cvt.u32.u64 %0, t; }"
        : "=r"(a) : "l"(p));
    return a;
}

__device__ __forceinline__ uint32_t sw128(uint32_t off) {
    return off ^ ((off >> 3) & 0x70);
}

__device__ __forceinline__ void cp16(uint32_t dst, const void* src) {
    asm volatile("cp.async.cg.shared.global [%0], [%1], 16;"
                 :: "r"(dst), "l"(src) : "memory");
}

__device__ __forceinline__ void ldsm_x4(uint32_t* r, uint32_t addr) {
    asm volatile("ldmatrix.sync.aligned.m8n8.x4.shared.b16 {%0,%1,%2,%3}, [%4];"
                 : "=r"(r[0]), "=r"(r[1]), "=r"(r[2]), "=r"(r[3]) : "r"(addr));
}

__device__ __forceinline__ void ldsm_x4t(uint32_t* r, uint32_t addr) {
    asm volatile("ldmatrix.sync.aligned.m8n8.x4.trans.shared.b16 {%0,%1,%2,%3}, [%4];"
                 : "=r"(r[0]), "=r"(r[1]), "=r"(r[2]), "=r"(r[3]) : "r"(addr));
}

// fp16 inputs, fp32 accumulate
__device__ __forceinline__ void mma16816(float* c, const uint32_t* a,
                                         const uint32_t* b) {
    asm volatile(
        "mma.sync.aligned.m16n8k16.row.col.f32.f16.f16.f32 "
        "{%0,%1,%2,%3}, {%4,%5,%6,%7}, {%8,%9}, {%0,%1,%2,%3};"
        : "+f"(c[0]), "+f"(c[1]), "+f"(c[2]), "+f"(c[3])
        : "r"(a[0]), "r"(a[1]), "r"(a[2]), "r"(a[3]), "r"(b[0]), "r"(b[1]));
}

__device__ __forceinline__ float ex2f(float x) {
    float r;
    asm("ex2.approx.ftz.f32 %0, %1;" : "=f"(r) : "f"(x));
    return r;
}

__device__ __forceinline__ uint32_t ex2_h2(uint32_t a) {
    uint32_t r;
    asm("ex2.approx.f16x2 %0, %1;" : "=r"(r) : "r"(a));
    return r;
}

__device__ __forceinline__ uint32_t pack_h2(float x, float y) {
    uint32_t h;
    asm("cvt.rn.f16x2.f32 %0, %1, %2;" : "=r"(h) : "f"(y), "f"(x));
    return h;
}

// ---------------------------------------------------------------------------
// Pack kernels. Launch order matters for ncu capture (launch #3 = attn).
// ---------------------------------------------------------------------------
__global__ __launch_bounds__(256) void split_w(
    const float* __restrict__ W0, const float* __restrict__ W1,
    const float* __restrict__ W2, const float* __restrict__ W3,
    __half* __restrict__ out)
{
    int mat = blockIdx.x >> 10;
    int i = (blockIdx.x & 1023) * 256 + threadIdx.x;
    const float* src = (mat == 0) ? W0 : (mat == 1) ? W1 : (mat == 2) ? W2 : W3;
    float4 v = reinterpret_cast<const float4*>(src)[i];
    uint32_t* dst = reinterpret_cast<uint32_t*>(out + (size_t)mat * DD * DD);
    dst[2 * i]     = pack_h2(v.x, v.y);
    dst[2 * i + 1] = pack_h2(v.z, v.w);
}

__global__ __launch_bounds__(256) void pack_x(
    const float* __restrict__ src, __half* __restrict__ dst)
{
    int i = blockIdx.x * 256 + threadIdx.x;
    float4 v = reinterpret_cast<const float4*>(src)[i];
    reinterpret_cast<uint32_t*>(dst)[2 * i]     = pack_h2(v.x, v.y);
    reinterpret_cast<uint32_t*>(dst)[2 * i + 1] = pack_h2(v.z, v.w);
}

// ---------------------------------------------------------------------------
// fp16 GEMM (NT), fused over up to 3 weight matrices (mat = blockIdx.x>>3):
//   C[m,n] = (Ah[m,:] . Wh[n,:] + bias[n]) * scale
// CTA 128x128, BK=64, 256 threads (8 warps, 4x2), warp tile 32x64,
// 3-stage cp.async pipeline, 2 CTAs/SM.
// ---------------------------------------------------------------------------
#define G_STAGE 32768   // Ah 16K | Wh 16K
#define G_SMEM  (3 * G_STAGE)

template<bool F32OUT>
__global__ __launch_bounds__(256, 2) void hgemm(
    const __half* __restrict__ Ah,
    const __half* __restrict__ Wh,
    const float* __restrict__ B0, const float* __restrict__ B1,
    const float* __restrict__ B2,
    __half* __restrict__ O0h, __half* __restrict__ O1h,
    __half* __restrict__ O2h,
    float* __restrict__ Cf)
{
    extern __shared__ __align__(1024) char smem[];
    uint32_t sb = smem_u32(smem);
    const int tid = threadIdx.x;
    const int w = tid >> 5, lane = tid & 31;
    const int wr = w >> 1, wc = w & 1;          // 4x2 warp grid, 32x64 tiles
    const int mat = blockIdx.x >> 3;
    const int n0  = (blockIdx.x & 7) * 128;
    const int m0  = blockIdx.y * 128;
    const __half* Wmh = Wh + (size_t)mat * DD * DD;

    float acc[2][8][4];
    #pragma unroll
    for (int mt = 0; mt < 2; mt++)
        #pragma unroll
        for (int nt = 0; nt < 8; nt++)
            #pragma unroll
            for (int i = 0; i < 4; i++) acc[mt][nt][i] = 0.f;

    auto load_stage = [&](int t, int s) {
        uint32_t base = sb + s * G_STAGE;
        #pragma unroll
        for (int i = 0; i < 4; i++) {
            int idx = tid + i * 256;           // 0..1023
            int row = idx >> 3, c = idx & 7;
            cp16(base + sw128((uint32_t)idx * 16),
                 (const char*)Ah + (size_t)(m0 + row) * 2048 + t * 128 + c * 16);
            cp16(base + 16384u + sw128((uint32_t)idx * 16),
                 (const char*)Wmh + (size_t)(n0 + row) * 2048 + t * 128 + c * 16);
        }
        asm volatile("cp.async.commit_group;" ::: "memory");
    };

    const int NT = DD / 64;  // 16
    load_stage(0, 0);
    load_stage(1, 1);

    for (int t = 0; t < NT; t++) {
        if (t < NT - 1)
            asm volatile("cp.async.wait_group 1;" ::: "memory");
        else
            asm volatile("cp.async.wait_group 0;" ::: "memory");
        __syncthreads();
        if (t + 2 < NT) load_stage(t + 2, (t + 2) % 3);
        uint32_t base = sb + (t % 3) * G_STAGE;

        #pragma unroll
        for (int k16 = 0; k16 < 4; k16++) {
            uint32_t af[2][4];
            #pragma unroll
            for (int mt = 0; mt < 2; mt++) {
                int row = wr * 32 + mt * 16 + (lane & 15);
                uint32_t off = sw128((uint32_t)row * 128 +
                                     (k16 * 2 + (lane >> 4)) * 16);
                ldsm_x4(af[mt], base + off);
            }
            uint32_t bf[8][2];
            #pragma unroll
            for (int nh = 0; nh < 4; nh++) {
                int row = wc * 64 + nh * 16 + (lane & 15);
                uint32_t off = sw128((uint32_t)row * 128 +
                                     (k16 * 2 + (lane >> 4)) * 16);
                uint32_t r[4];
                ldsm_x4(r, base + 16384u + off);
                bf[nh * 2][0] = r[0]; bf[nh * 2 + 1][0] = r[1];
                bf[nh * 2][1] = r[2]; bf[nh * 2 + 1][1] = r[3];
            }
            #pragma unroll
            for (int mt = 0; mt < 2; mt++)
                #pragma unroll
                for (int nt = 0; nt < 8; nt++)
                    mma16816(acc[mt][nt], af[mt], bf[nt]);
        }
    }

    // Epilogue
    const float* bias = (mat == 0) ? B0 : (mat == 1 ? B1 : B2);
    __half* Oh = (mat == 0) ? O0h : (mat == 1 ? O1h : O2h);
    const float scl = (!F32OUT && mat == 0) ? SCALE_Q : 1.0f;
    const int r = lane >> 2, cp2 = (lane & 3) * 2;
    #pragma unroll
    for (int mt = 0; mt < 2; mt++) {
        #pragma unroll
        for (int nt = 0; nt < 8; nt++) {
            int row = m0 + wr * 32 + mt * 16 + r;
            int col = n0 + wc * 64 + nt * 8 + cp2;
            float b0 = bias[col], b1 = bias[col + 1];
            float v00 = (acc[mt][nt][0] + b0) * scl;
            float v01 = (acc[mt][nt][1] + b1) * scl;
            float v10 = (acc[mt][nt][2] + b0) * scl;
            float v11 = (acc[mt][nt][3] + b1) * scl;
            if (F32OUT) {
                *reinterpret_cast<float2*>(Cf + (size_t)row * DD + col) =
                    make_float2(v00, v01);
                *reinterpret_cast<float2*>(Cf + (size_t)(row + 8) * DD + col) =
                    make_float2(v10, v11);
            } else {
                *reinterpret_cast<uint32_t*>(Oh + (size_t)row * DD + col) =
                    pack_h2(v00, v01);
                *reinterpret_cast<uint32_t*>(Oh + (size_t)(row + 8) * DD + col) =
                    pack_h2(v10, v11);
            }
        }
    }
}

// ---------------------------------------------------------------------------
// Flash attention, single-chain fp16 (S = Qh Kh^T, O += Ph Vh).
// exp via ex2.approx.f16x2 (produces PV A-fragments directly); the softmax
// denominator l is accumulated by an extra ones-column MMA so it is exactly
// consistent with the fp16 P used in PV.
// 256 threads, BM=128, BN=64, 3-stage KV pipeline, 2 CTAs/SM.
// ---------------------------------------------------------------------------
#define A_STAGE 16384   // Kh 8K | Vh 8K
#define A_SMEM  (3 * A_STAGE)

__global__ __launch_bounds__(256, 2) void attn_mma(
    const __half* __restrict__ Qh,
    const __half* __restrict__ Kh,
    const __half* __restrict__ Vh,
    __half* __restrict__ Ch)
{
    extern __shared__ __align__(1024) char smem[];
    uint32_t sb = smem_u32(smem);
    const int tid = threadIdx.x;
    const int w = tid >> 5, lane = tid & 31;
    const int q0 = blockIdx.x * 128;
    const int hd = blockIdx.y;
    const int b  = blockIdx.z;

    const size_t qbase = ((size_t)b * SS + q0) * DD + hd * 64;
    const size_t kbase = (size_t)b * SS * DD + hd * 64;

    auto load_kv = [&](int it, int s) {
        uint32_t base = sb + s * A_STAGE;
        const char* gk = (const char*)Kh + (kbase + (size_t)it * 64 * DD) * 2;
        const char* gv = (const char*)Vh + (kbase + (size_t)it * 64 * DD) * 2;
        #pragma unroll
        for (int i = 0; i < 2; i++) {
            int idx = tid + i * 256;       // 0..511
            int row = idx >> 3, c = idx & 7;
            cp16(base + sw128((uint32_t)idx * 16),
                 gk + (size_t)row * 2048 + c * 16);
            cp16(base + 8192u + sw128((uint32_t)idx * 16),
                 gv + (size_t)row * 2048 + c * 16);
        }
        asm volatile("cp.async.commit_group;" ::: "memory");
    };

    // ---- Prologue: Q (16K) into stage-2 area; KV stages 0,1 in flight ----
    {
        const char* gq = (const char*)Qh + qbase * 2;
        uint32_t qb = sb + 2 * A_STAGE;
        #pragma unroll
        for (int i = 0; i < 4; i++) {
            int idx = tid + i * 256;       // 0..1023
            int row = idx >> 3, c = idx & 7;
            cp16(qb + sw128((uint32_t)idx * 16),
                 gq + (size_t)row * 2048 + c * 16);
        }
        asm volatile("cp.async.commit_group;" ::: "memory");
    }
    load_kv(0, 0);
    load_kv(1, 1);
    asm volatile("cp.async.wait_group 2;" ::: "memory");  // Q landed
    __syncthreads();

    uint32_t qf[4][4];
    {
        uint32_t qb = sb + 2 * A_STAGE;
        #pragma unroll
        for (int k16 = 0; k16 < 4; k16++) {
            int row = w * 16 + (lane & 15);
            uint32_t off = sw128((uint32_t)row * 128 +
                                 (k16 * 2 + (lane >> 4)) * 16);
            ldsm_x4(qf[k16], qb + off);
        }
    }
    __syncthreads();   // Q area may now be reused as KV stage 2

    float o[8][4];
    #pragma unroll
    for (int dt = 0; dt < 8; dt++)
        #pragma unroll
        for (int i = 0; i < 4; i++) o[dt][i] = 0.f;
    float lacc[4] = {0.f, 0.f, 0.f, 0.f};
    const float NEG_INF = __int_as_float(0xff800000);
    float mrow[2] = {NEG_INF, NEG_INF};
    const uint32_t ONE_H2 = 0x3C003C00u;
    const uint32_t onef[2] = {ONE_H2, ONE_H2};

    const int NT = SS / 64;  // 32
    for (int it = 0; it < NT; it++) {
        if (it < NT - 1)
            asm volatile("cp.async.wait_group 1;" ::: "memory");
        else
            asm volatile("cp.async.wait_group 0;" ::: "memory");
        __syncthreads();
        if (it + 2 < NT) load_kv(it + 2, (it + 2) % 3);
        uint32_t base = sb + (it % 3) * A_STAGE;

        // ---- S = Q K^T (single chain; log2 units via folded Q scale) ----
        float s[8][4];
        #pragma unroll
        for (int nt = 0; nt < 8; nt++)
            #pragma unroll
            for (int i = 0; i < 4; i++) s[nt][i] = 0.f;

        #pragma unroll
        for (int k16 = 0; k16 < 4; k16++) {
            uint32_t kf[8][2];
            #pragma unroll
            for (int nh = 0; nh < 4; nh++) {
                int row = nh * 16 + (lane & 15);
                uint32_t off = sw128((uint32_t)row * 128 +
                                     (k16 * 2 + (lane >> 4)) * 16);
                uint32_t r[4];
                ldsm_x4(r, base + off);
                kf[nh * 2][0] = r[0]; kf[nh * 2 + 1][0] = r[1];
                kf[nh * 2][1] = r[2]; kf[nh * 2 + 1][1] = r[3];
            }
            #pragma unroll
            for (int nt = 0; nt < 8; nt++)
                mma16816(s[nt], qf[k16], kf[nt]);
        }

        // ---- online softmax in log2 domain; exp in f16x2 -> P frags ----
        uint32_t pp[16];
        #pragma unroll
        for (int hf = 0; hf < 2; hf++) {
            float mx = NEG_INF;
            #pragma unroll
            for (int nt = 0; nt < 8; nt++)
                mx = fmaxf(mx, fmaxf(s[nt][2 * hf], s[nt][2 * hf + 1]));
            mx = fmaxf(mx, __shfl_xor_sync(0xffffffffu, mx, 1));
            mx = fmaxf(mx, __shfl_xor_sync(0xffffffffu, mx, 2));
            float mn = fmaxf(mrow[hf], mx);
            uint32_t keep = __all_sync(0xffffffffu, mn == mrow[hf]);
            if (!keep) {
                float scale = ex2f(mrow[hf] - mn);
                mrow[hf] = mn;
                #pragma unroll
                for (int dt = 0; dt < 8; dt++) {
                    o[dt][2 * hf]     *= scale;
                    o[dt][2 * hf + 1] *= scale;
                }
                lacc[2 * hf]     *= scale;
                lacc[2 * hf + 1] *= scale;
            }
            #pragma unroll
            for (int nt = 0; nt < 8; nt++) {
                uint32_t u = pack_h2(s[nt][2 * hf] - mn,
                                     s[nt][2 * hf + 1] - mn);
                pp[4 * (nt >> 1) + (nt & 1) * 2 + hf] = ex2_h2(u);
            }
        }

        // ---- O += P V, and l += P . 1 (extra ones-column MMA) ----
        #pragma unroll
        for (int t = 0; t < 4; t++) {
            uint32_t vf[8][2];
            #pragma unroll
            for (int dp = 0; dp < 4; dp++) {
                int row = t * 16 + (lane & 15);
                uint32_t off = sw128((uint32_t)row * 128 +
                                     (dp * 2 + (lane >> 4)) * 16);
                uint32_t r[4];
                ldsm_x4t(r, base + 8192u + off);
                vf[dp * 2][0] = r[0]; vf[dp * 2][1] = r[1];
                vf[dp * 2 + 1][0] = r[2]; vf[dp * 2 + 1][1] = r[3];
            }
            #pragma unroll
            for (int dt = 0; dt < 8; dt++)
                mma16816(o[dt], &pp[4 * t], vf[dt]);
            mma16816(lacc, &pp[4 * t], onef);
        }
    }

    // ---- epilogue: ctx = O / l, written as fp16 ----
    const int r = lane >> 2, cp2 = (lane & 3) * 2;
    #pragma unroll
    for (int hf = 0; hf < 2; hf++) {
        float inv = 1.f / lacc[2 * hf];
        int row = q0 + w * 16 + r + hf * 8;
        size_t ob = ((size_t)b * SS + row) * DD + hd * 64;
        #pragma unroll
        for (int dt = 0; dt < 8; dt++) {
            float v0 = o[dt][2 * hf] * inv;
            float v1 = o[dt][2 * hf + 1] * inv;
            *reinterpret_cast<uint32_t*>(Ch + ob + dt * 8 + cp2) =
                pack_h2(v0, v1);
        }
    }
}

// ---------------------------------------------------------------------------
// Launch (order chosen so ncu's captured launch #3 = attn_mma)
// ---------------------------------------------------------------------------
extern "C" void kernel_launch(void* const* d_in, const int* in_sizes, int n_in,
                              void* d_out, int out_size)
{
    const float* x  = (const float*)d_in[0];
    const float* Wq = (const float*)d_in[1];
    const float* bq = (const float*)d_in[2];
    const float* Wk = (const float*)d_in[3];
    const float* bk = (const float*)d_in[4];
    const float* Wv = (const float*)d_in[5];
    const float* bv = (const float*)d_in[6];
    const float* Wo = (const float*)d_in[7];
    const float* bo = (const float*)d_in[8];
    float* out = (float*)d_out;

    __half *xh, *qh, *kh, *vh, *ch, *wh;
    cudaGetSymbolAddress((void**)&xh, g_xh);
    cudaGetSymbolAddress((void**)&qh, g_qh);
    cudaGetSymbolAddress((void**)&kh, g_kh);
    cudaGetSymbolAddress((void**)&vh, g_vh);
    cudaGetSymbolAddress((void**)&ch, g_ch);
    cudaGetSymbolAddress((void**)&wh, g_wh);

    cudaFuncSetAttribute((const void*)hgemm<false>,
                         cudaFuncAttributeMaxDynamicSharedMemorySize, G_SMEM);
    cudaFuncSetAttribute((const void*)hgemm<true>,
                         cudaFuncAttributeMaxDynamicSharedMemorySize, G_SMEM);
    cudaFuncSetAttribute((const void*)attn_mma,
                         cudaFuncAttributeMaxDynamicSharedMemorySize, A_SMEM);

    // launch 0: all weights -> fp16
    split_w<<<4096, 256>>>(Wq, Wk, Wv, Wo, wh);
    // launch 1: x -> fp16
    pack_x<<<MM * DD / 1024, 256>>>(x, xh);

    // launch 2: fused QKV projection (mat 0 = Q gets softmax scale folded in)
    dim3 gqkv(24, 64);
    hgemm<false><<<gqkv, 256, G_SMEM>>>(
        xh, wh, bq, bk, bv, qh, kh, vh, nullptr);

    // launch 3: attention  (ncu capture slot)
    dim3 ag(SS / 128, HH, BB);    // (16, 16, 4)
    attn_mma<<<ag, 256, A_SMEM>>>(qh, kh, vh, ch);

    // launch 4: output projection (fp32 out, single fp16 chain)
    dim3 go(8, 64);
    hgemm<true><<<go, 256, G_SMEM>>>(
        ch, wh + 3 * (size_t)DD * DD, bo, nullptr, nullptr,
        nullptr, nullptr, nullptr, out);
}

// round 10
// speedup vs baseline: 8.4265x; 1.0222x over previous
#include <cuda_runtime.h>
#include <cuda_fp16.h>
#include <math.h>
#include <stdint.h>

// Problem constants
#define BB 4
#define SS 2048
#define DD 1024
#define HH 16
#define DK 64
#define MM (BB * SS)   // 8192 rows

// 0.125 (1/sqrt(DK)) * log2(e): folded into Q so softmax runs in log2 domain
#define SCALE_Q 0.1803368801111204f

// ---------------------------------------------------------------------------
// Scratch (static device globals: allocation-free per harness rules)
// ---------------------------------------------------------------------------
__device__ __align__(16) __half g_xh[MM * DD];
__device__ __align__(16) __half g_qh[MM * DD];
__device__ __align__(16) __half g_kh[MM * DD];
__device__ __align__(16) __half g_vh[MM * DD];
__device__ __align__(16) __half g_ch[MM * DD];
__device__ __align__(16) __half g_wh[4 * DD * DD];   // weights: fp16

// ---------------------------------------------------------------------------
// Low-level helpers (base ISA only: ldmatrix + mma.sync + cp.async)
// ---------------------------------------------------------------------------
__device__ __forceinline__ uint32_t smem_u32(const void* p) {
    uint32_t a;
    asm("{ .reg .u64 t; cvta.to.shared.u64 t, %1; cvt.u32.u64 %0, t; }"
        : "=r"(a) : "l"(p));
    return a;
}

__device__ __forceinline__ uint32_t sw128(uint32_t off) {
    return off ^ ((off >> 3) & 0x70);
}

__device__ __forceinline__ void cp16(uint32_t dst, const void* src) {
    asm volatile("cp.async.cg.shared.global [%0], [%1], 16;"
                 :: "r"(dst), "l"(src) : "memory");
}

__device__ __forceinline__ void ldsm_x4(uint32_t* r, uint32_t addr) {
    asm volatile("ldmatrix.sync.aligned.m8n8.x4.shared.b16 {%0,%1,%2,%3}, [%4];"
                 : "=r"(r[0]), "=r"(r[1]), "=r"(r[2]), "=r"(r[3]) : "r"(addr));
}

__device__ __forceinline__ void ldsm_x4t(uint32_t* r, uint32_t addr) {
    asm volatile("ldmatrix.sync.aligned.m8n8.x4.trans.shared.b16 {%0,%1,%2,%3}, [%4];"
                 : "=r"(r[0]), "=r"(r[1]), "=r"(r[2]), "=r"(r[3]) : "r"(addr));
}

// fp16 inputs, fp32 accumulate
__device__ __forceinline__ void mma16816(float* c, const uint32_t* a,
                                         const uint32_t* b) {
    asm volatile(
        "mma.sync.aligned.m16n8k16.row.col.f32.f16.f16.f32 "
        "{%0,%1,%2,%3}, {%4,%5,%6,%7}, {%8,%9}, {%0,%1,%2,%3};"
        : "+f"(c[0]), "+f"(c[1]), "+f"(c[2]), "+f"(c[3])
        : "r"(a[0]), "r"(a[1]), "r"(a[2]), "r"(a[3]), "r"(b[0]), "r"(b[1]));
}

__device__ __forceinline__ float ex2f(float x) {
    float r;
    asm("ex2.approx.ftz.f32 %0, %1;" : "=f"(r) : "f"(x));
    return r;
}

__device__ __forceinline__ uint32_t ex2_h2(uint32_t a) {
    uint32_t r;
    asm("ex2.approx.f16x2 %0, %1;" : "=r"(r) : "r"(a));
    return r;
}

__device__ __forceinline__ uint32_t pack_h2(float x, float y) {
    uint32_t h;
    asm("cvt.rn.f16x2.f32 %0, %1, %2;" : "=r"(h) : "f"(y), "f"(x));
    return h;
}

// ---------------------------------------------------------------------------
// Pack kernels. Launch order matters for ncu capture (launch #3 = attn).
// ---------------------------------------------------------------------------
__global__ __launch_bounds__(256) void split_w(
    const float* __restrict__ W0, const float* __restrict__ W1,
    const float* __restrict__ W2, const float* __restrict__ W3,
    __half* __restrict__ out)
{
    int mat = blockIdx.x >> 10;
    int i = (blockIdx.x & 1023) * 256 + threadIdx.x;
    const float* src = (mat == 0) ? W0 : (mat == 1) ? W1 : (mat == 2) ? W2 : W3;
    float4 v = reinterpret_cast<const float4*>(src)[i];
    uint32_t* dst = reinterpret_cast<uint32_t*>(out + (size_t)mat * DD * DD);
    dst[2 * i]     = pack_h2(v.x, v.y);
    dst[2 * i + 1] = pack_h2(v.z, v.w);
}

__global__ __launch_bounds__(256) void pack_x(
    const float* __restrict__ src, __half* __restrict__ dst)
{
    int i = blockIdx.x * 256 + threadIdx.x;
    float4 v = reinterpret_cast<const float4*>(src)[i];
    reinterpret_cast<uint32_t*>(dst)[2 * i]     = pack_h2(v.x, v.y);
    reinterpret_cast<uint32_t*>(dst)[2 * i + 1] = pack_h2(v.z, v.w);
}

// ---------------------------------------------------------------------------
// fp16 GEMM (NT), fused over up to 3 weight matrices (mat = blockIdx.x>>3):
//   C[m,n] = (Ah[m,:] . Wh[n,:] + bias[n]) * scale
// CTA 128x128, BK=64, 256 threads (8 warps, 4x2), warp tile 32x64,
// 3-stage cp.async pipeline, 2 CTAs/SM.
// ---------------------------------------------------------------------------
#define G_STAGE 32768   // Ah 16K | Wh 16K
#define G_SMEM  (3 * G_STAGE)

template<bool F32OUT>
__global__ __launch_bounds__(256, 2) void hgemm(
    const __half* __restrict__ Ah,
    const __half* __restrict__ Wh,
    const float* __restrict__ B0, const float* __restrict__ B1,
    const float* __restrict__ B2,
    __half* __restrict__ O0h, __half* __restrict__ O1h,
    __half* __restrict__ O2h,
    float* __restrict__ Cf)
{
    extern __shared__ __align__(1024) char smem[];
    uint32_t sb = smem_u32(smem);
    const int tid = threadIdx.x;
    const int w = tid >> 5, lane = tid & 31;
    const int wr = w >> 1, wc = w & 1;          // 4x2 warp grid, 32x64 tiles
    const int mat = blockIdx.x >> 3;
    const int n0  = (blockIdx.x & 7) * 128;
    const int m0  = blockIdx.y * 128;
    const __half* Wmh = Wh + (size_t)mat * DD * DD;

    float acc[2][8][4];
    #pragma unroll
    for (int mt = 0; mt < 2; mt++)
        #pragma unroll
        for (int nt = 0; nt < 8; nt++)
            #pragma unroll
            for (int i = 0; i < 4; i++) acc[mt][nt][i] = 0.f;

    auto load_stage = [&](int t, int s) {
        uint32_t base = sb + s * G_STAGE;
        #pragma unroll
        for (int i = 0; i < 4; i++) {
            int idx = tid + i * 256;           // 0..1023
            int row = idx >> 3, c = idx & 7;
            cp16(base + sw128((uint32_t)idx * 16),
                 (const char*)Ah + (size_t)(m0 + row) * 2048 + t * 128 + c * 16);
            cp16(base + 16384u + sw128((uint32_t)idx * 16),
                 (const char*)Wmh + (size_t)(n0 + row) * 2048 + t * 128 + c * 16);
        }
        asm volatile("cp.async.commit_group;" ::: "memory");
    };

    const int NT = DD / 64;  // 16
    load_stage(0, 0);
    load_stage(1, 1);

    for (int t = 0; t < NT; t++) {
        if (t < NT - 1)
            asm volatile("cp.async.wait_group 1;" ::: "memory");
        else
            asm volatile("cp.async.wait_group 0;" ::: "memory");
        __syncthreads();
        if (t + 2 < NT) load_stage(t + 2, (t + 2) % 3);
        uint32_t base = sb + (t % 3) * G_STAGE;

        #pragma unroll
        for (int k16 = 0; k16 < 4; k16++) {
            uint32_t af[2][4];
            #pragma unroll
            for (int mt = 0; mt < 2; mt++) {
                int row = wr * 32 + mt * 16 + (lane & 15);
                uint32_t off = sw128((uint32_t)row * 128 +
                                     (k16 * 2 + (lane >> 4)) * 16);
                ldsm_x4(af[mt], base + off);
            }
            uint32_t bf[8][2];
            #pragma unroll
            for (int nh = 0; nh < 4; nh++) {
                int row = wc * 64 + nh * 16 + (lane & 15);
                uint32_t off = sw128((uint32_t)row * 128 +
                                     (k16 * 2 + (lane >> 4)) * 16);
                uint32_t r[4];
                ldsm_x4(r, base + 16384u + off);
                bf[nh * 2][0] = r[0]; bf[nh * 2 + 1][0] = r[1];
                bf[nh * 2][1] = r[2]; bf[nh * 2 + 1][1] = r[3];
            }
            #pragma unroll
            for (int mt = 0; mt < 2; mt++)
                #pragma unroll
                for (int nt = 0; nt < 8; nt++)
                    mma16816(acc[mt][nt], af[mt], bf[nt]);
        }
    }

    // Epilogue
    const float* bias = (mat == 0) ? B0 : (mat == 1 ? B1 : B2);
    __half* Oh = (mat == 0) ? O0h : (mat == 1 ? O1h : O2h);
    const float scl = (!F32OUT && mat == 0) ? SCALE_Q : 1.0f;
    const int r = lane >> 2, cp2 = (lane & 3) * 2;
    #pragma unroll
    for (int mt = 0; mt < 2; mt++) {
        #pragma unroll
        for (int nt = 0; nt < 8; nt++) {
            int row = m0 + wr * 32 + mt * 16 + r;
            int col = n0 + wc * 64 + nt * 8 + cp2;
            float b0 = bias[col], b1 = bias[col + 1];
            float v00 = (acc[mt][nt][0] + b0) * scl;
            float v01 = (acc[mt][nt][1] + b1) * scl;
            float v10 = (acc[mt][nt][2] + b0) * scl;
            float v11 = (acc[mt][nt][3] + b1) * scl;
            if (F32OUT) {
                *reinterpret_cast<float2*>(Cf + (size_t)row * DD + col) =
                    make_float2(v00, v01);
                *reinterpret_cast<float2*>(Cf + (size_t)(row + 8) * DD + col) =
                    make_float2(v10, v11);
            } else {
                *reinterpret_cast<uint32_t*>(Oh + (size_t)row * DD + col) =
                    pack_h2(v00, v01);
                *reinterpret_cast<uint32_t*>(Oh + (size_t)(row + 8) * DD + col) =
                    pack_h2(v10, v11);
            }
        }
    }
}

// ---------------------------------------------------------------------------
// Flash attention, single-chain fp16, ONE-TILE SOFTWARE PIPELINE:
// iter t issues S(t) MMAs then PV(t-1) MMAs (independent of softmax(t)),
// so softmax's MUFU/shuffle latency overlaps a deep tensor queue.
// 4-stage KV ring (stage t-2 free at iter-t top), Q persistent in smem,
// Q-fragments reloaded per k16 to keep regs <= 128. 2 CTAs/SM.
// ---------------------------------------------------------------------------
#define A_STAGE 16384   // Kh 8K | Vh 8K
#define A_SMEM  (4 * A_STAGE + 16384)   // 4 KV stages + Q region (80 KB)

__global__ __launch_bounds__(256, 2) void attn_mma(
    const __half* __restrict__ Qh,
    const __half* __restrict__ Kh,
    const __half* __restrict__ Vh,
    __half* __restrict__ Ch)
{
    extern __shared__ __align__(1024) char smem[];
    uint32_t sb = smem_u32(smem);
    const uint32_t qreg = sb + 4 * A_STAGE;
    const int tid = threadIdx.x;
    const int w = tid >> 5, lane = tid & 31;
    const int q0 = blockIdx.x * 128;
    const int hd = blockIdx.y;
    const int b  = blockIdx.z;

    const size_t qbase = ((size_t)b * SS + q0) * DD + hd * 64;
    const size_t kbase = (size_t)b * SS * DD + hd * 64;

    auto load_kv = [&](int it, int s) {
        uint32_t base = sb + s * A_STAGE;
        const char* gk = (const char*)Kh + (kbase + (size_t)it * 64 * DD) * 2;
        const char* gv = (const char*)Vh + (kbase + (size_t)it * 64 * DD) * 2;
        #pragma unroll
        for (int i = 0; i < 2; i++) {
            int idx = tid + i * 256;       // 0..511
            int row = idx >> 3, c = idx & 7;
            cp16(base + sw128((uint32_t)idx * 16),
                 gk + (size_t)row * 2048 + c * 16);
            cp16(base + 8192u + sw128((uint32_t)idx * 16),
                 gv + (size_t)row * 2048 + c * 16);
        }
        asm volatile("cp.async.commit_group;" ::: "memory");
    };

    // ---- Prologue: Q -> qreg (group 0); KV stages 0,1 in flight ----
    {
        const char* gq = (const char*)Qh + qbase * 2;
        #pragma unroll
        for (int i = 0; i < 4; i++) {
            int idx = tid + i * 256;       // 0..1023
            int row = idx >> 3, c = idx & 7;
            cp16(qreg + sw128((uint32_t)idx * 16),
                 gq + (size_t)row * 2048 + c * 16);
        }
        asm volatile("cp.async.commit_group;" ::: "memory");
    }
    load_kv(0, 0);
    load_kv(1, 1);

    float o[8][4];
    #pragma unroll
    for (int dt = 0; dt < 8; dt++)
        #pragma unroll
        for (int i = 0; i < 4; i++) o[dt][i] = 0.f;
    float lacc[4] = {0.f, 0.f, 0.f, 0.f};
    const float NEG_INF = __int_as_float(0xff800000);
    float mrow[2] = {NEG_INF, NEG_INF};
    const uint32_t ONE_H2 = 0x3C003C00u;
    const uint32_t onef[2] = {ONE_H2, ONE_H2};
    uint32_t pp_prev[16];

    const int NT = SS / 64;  // 32
    uint32_t base_prev = 0;

    for (int it = 0; it < NT; it++) {
        // kv(it) must be landed; only kv(it+1) may stay pending
        if (it < NT - 1)
            asm volatile("cp.async.wait_group 1;" ::: "memory");
        else
            asm volatile("cp.async.wait_group 0;" ::: "memory");
        __syncthreads();   // all warps done with iter it-1 => stage it-2 free
        if (it + 2 < NT) load_kv(it + 2, (it + 2) & 3);
        uint32_t base = sb + (it & 3) * A_STAGE;

        // ---- S(t) = Q K^T (Q frags reloaded from persistent smem) ----
        float s[8][4];
        #pragma unroll
        for (int nt = 0; nt < 8; nt++)
            #pragma unroll
            for (int i = 0; i < 4; i++) s[nt][i] = 0.f;

        #pragma unroll
        for (int k16 = 0; k16 < 4; k16++) {
            uint32_t qk[4];
            {
                int row = w * 16 + (lane & 15);
                uint32_t off = sw128((uint32_t)row * 128 +
                                     (k16 * 2 + (lane >> 4)) * 16);
                ldsm_x4(qk, qreg + off);
            }
            uint32_t kf[8][2];
            #pragma unroll
            for (int nh = 0; nh < 4; nh++) {
                int row = nh * 16 + (lane & 15);
                uint32_t off = sw128((uint32_t)row * 128 +
                                     (k16 * 2 + (lane >> 4)) * 16);
                uint32_t r[4];
                ldsm_x4(r, base + off);
                kf[nh * 2][0] = r[0]; kf[nh * 2 + 1][0] = r[1];
                kf[nh * 2][1] = r[2]; kf[nh * 2 + 1][1] = r[3];
            }
            #pragma unroll
            for (int nt = 0; nt < 8; nt++)
                mma16816(s[nt], qk, kf[nt]);
        }

        // ---- PV(t-1): independent of softmax(t); overlaps its latency ----
        if (it > 0) {
            #pragma unroll
            for (int t = 0; t < 4; t++) {
                uint32_t vf[8][2];
                #pragma unroll
                for (int dp = 0; dp < 4; dp++) {
                    int row = t * 16 + (lane & 15);
                    uint32_t off = sw128((uint32_t)row * 128 +
                                         (dp * 2 + (lane >> 4)) * 16);
                    uint32_t r[4];
                    ldsm_x4t(r, base_prev + 8192u + off);
                    vf[dp * 2][0] = r[0]; vf[dp * 2][1] = r[1];
                    vf[dp * 2 + 1][0] = r[2]; vf[dp * 2 + 1][1] = r[3];
                }
                #pragma unroll
                for (int dt = 0; dt < 8; dt++)
                    mma16816(o[dt], &pp_prev[4 * t], vf[dt]);
                mma16816(lacc, &pp_prev[4 * t], onef);
            }
        }

        // ---- softmax(t) in log2 domain; exp in f16x2 -> pp_prev ----
        #pragma unroll
        for (int hf = 0; hf < 2; hf++) {
            float mx = NEG_INF;
            #pragma unroll
            for (int nt = 0; nt < 8; nt++)
                mx = fmaxf(mx, fmaxf(s[nt][2 * hf], s[nt][2 * hf + 1]));
            mx = fmaxf(mx, __shfl_xor_sync(0xffffffffu, mx, 1));
            mx = fmaxf(mx, __shfl_xor_sync(0xffffffffu, mx, 2));
            float mn = fmaxf(mrow[hf], mx);
            uint32_t keep = __all_sync(0xffffffffu, mn == mrow[hf]);
            if (!keep) {
                float scale = ex2f(mrow[hf] - mn);
                mrow[hf] = mn;
                #pragma unroll
                for (int dt = 0; dt < 8; dt++) {
                    o[dt][2 * hf]     *= scale;
                    o[dt][2 * hf + 1] *= scale;
                }
                lacc[2 * hf]     *= scale;
                lacc[2 * hf + 1] *= scale;
            }
            #pragma unroll
            for (int nt = 0; nt < 8; nt++) {
                uint32_t u = pack_h2(s[nt][2 * hf] - mn,
                                     s[nt][2 * hf + 1] - mn);
                pp_prev[4 * (nt >> 1) + (nt & 1) * 2 + hf] = ex2_h2(u);
            }
        }
        base_prev = base;
    }

    // ---- drain: PV(NT-1) ----
    #pragma unroll
    for (int t = 0; t < 4; t++) {
        uint32_t vf[8][2];
        #pragma unroll
        for (int dp = 0; dp < 4; dp++) {
            int row = t * 16 + (lane & 15);
            uint32_t off = sw128((uint32_t)row * 128 +
                                 (dp * 2 + (lane >> 4)) * 16);
            uint32_t r[4];
            ldsm_x4t(r, base_prev + 8192u + off);
            vf[dp * 2][0] = r[0]; vf[dp * 2][1] = r[1];
            vf[dp * 2 + 1][0] = r[2]; vf[dp * 2 + 1][1] = r[3];
        }
        #pragma unroll
        for (int dt = 0; dt < 8; dt++)
            mma16816(o[dt], &pp_prev[4 * t], vf[dt]);
        mma16816(lacc, &pp_prev[4 * t], onef);
    }

    // ---- epilogue: ctx = O / l, written as fp16 ----
    const int r = lane >> 2, cp2 = (lane & 3) * 2;
    #pragma unroll
    for (int hf = 0; hf < 2; hf++) {
        float inv = 1.f / lacc[2 * hf];
        int row = q0 + w * 16 + r + hf * 8;
        size_t ob = ((size_t)b * SS + row) * DD + hd * 64;
        #pragma unroll
        for (int dt = 0; dt < 8; dt++) {
            float v0 = o[dt][2 * hf] * inv;
            float v1 = o[dt][2 * hf + 1] * inv;
            *reinterpret_cast<uint32_t*>(Ch + ob + dt * 8 + cp2) =
                pack_h2(v0, v1);
        }
    }
}

// ---------------------------------------------------------------------------
// Launch (order chosen so ncu's captured launch #3 = attn_mma)
// ---------------------------------------------------------------------------
extern "C" void kernel_launch(void* const* d_in, const int* in_sizes, int n_in,
                              void* d_out, int out_size)
{
    const float* x  = (const float*)d_in[0];
    const float* Wq = (const float*)d_in[1];
    const float* bq = (const float*)d_in[2];
    const float* Wk = (const float*)d_in[3];
    const float* bk = (const float*)d_in[4];
    const float* Wv = (const float*)d_in[5];
    const float* bv = (const float*)d_in[6];
    const float* Wo = (const float*)d_in[7];
    const float* bo = (const float*)d_in[8];
    float* out = (float*)d_out;

    __half *xh, *qh, *kh, *vh, *ch, *wh;
    cudaGetSymbolAddress((void**)&xh, g_xh);
    cudaGetSymbolAddress((void**)&qh, g_qh);
    cudaGetSymbolAddress((void**)&kh, g_kh);
    cudaGetSymbolAddress((void**)&vh, g_vh);
    cudaGetSymbolAddress((void**)&ch, g_ch);
    cudaGetSymbolAddress((void**)&wh, g_wh);

    cudaFuncSetAttribute((const void*)hgemm<false>,
                         cudaFuncAttributeMaxDynamicSharedMemorySize, G_SMEM);
    cudaFuncSetAttribute((const void*)hgemm<true>,
                         cudaFuncAttributeMaxDynamicSharedMemorySize, G_SMEM);
    cudaFuncSetAttribute((const void*)attn_mma,
                         cudaFuncAttributeMaxDynamicSharedMemorySize, A_SMEM);

    // launch 0: all weights -> fp16
    split_w<<<4096, 256>>>(Wq, Wk, Wv, Wo, wh);
    // launch 1: x -> fp16
    pack_x<<<MM * DD / 1024, 256>>>(x, xh);

    // launch 2: fused QKV projection (mat 0 = Q gets softmax scale folded in)
    dim3 gqkv(24, 64);
    hgemm<false><<<gqkv, 256, G_SMEM>>>(
        xh, wh, bq, bk, bv, qh, kh, vh, nullptr);

    // launch 3: attention  (ncu capture slot)
    dim3 ag(SS / 128, HH, BB);    // (16, 16, 4)
    attn_mma<<<ag, 256, A_SMEM>>>(qh, kh, vh, ch);

    // launch 4: output projection (fp32 out, single fp16 chain)
    dim3 go(8, 64);
    hgemm<true><<<go, 256, G_SMEM>>>(
        ch, wh + 3 * (size_t)DD * DD, bo, nullptr, nullptr,
        nullptr, nullptr, nullptr, out);
}